// round 1
// baseline (speedup 1.0000x reference)
#include <cuda_runtime.h>
#include <math.h>

#define BSZ   8
#define NSEQ  1024
#define DIMM  512
#define NH    8
#define HD    64
#define COLS3 1536

// Scratch (device globals: allowed; no runtime allocation)
__device__ float g_q[BSZ*NH*NSEQ*HD];
__device__ float g_k[BSZ*NH*NSEQ*HD];
__device__ float g_v[BSZ*NH*NSEQ*HD];
__device__ float g_ao[BSZ*NSEQ*DIMM];

// XOR swizzle for [k][i] smem arrays with stride 64 floats.
// Keeps groups of 4 consecutive i contiguous (float4-able), permutes the 16
// float4 slots per row by k>>2 so transposed scalar stores are ~2-way max.
__device__ __forceinline__ int swz(int k, int i) {
    return k * 64 + ((((i >> 2) ^ (k >> 2)) & 15) << 2) + (i & 3);
}

// ---------------------------------------------------------------------------
// Kernel 1: QKV = x @ w_qkv, epilogue: q-scale + interleaved RoPE, scatter to
// g_q/g_k/g_v in [B,H,N,D] layout.
// Grid (24, 128), 256 threads, 64x64 tile, 4x4 per thread, k-chunk 32.
// ---------------------------------------------------------------------------
__global__ __launch_bounds__(256) void k_qkv(const float* __restrict__ x,
                                             const float* __restrict__ w) {
    __shared__ __align__(16) float As[32 * 64];
    __shared__ __align__(16) float Bs[32 * 64];

    const int tid = threadIdx.x;
    const int tx = tid & 15, ty = tid >> 4;
    const int row0 = blockIdx.y * 64;
    const int col0 = blockIdx.x * 64;

    float acc[4][4] = {};

    for (int kk = 0; kk < DIMM; kk += 32) {
        __syncthreads();
        // A tile: 64 rows x 32 k, transposed+swizzled store
#pragma unroll
        for (int it = 0; it < 2; it++) {
            int idx = it * 256 + tid;
            int r = idx >> 3, k4 = idx & 7;
            float4 v = *(const float4*)&x[(row0 + r) * DIMM + kk + 4 * k4];
            As[swz(4 * k4 + 0, r)] = v.x;
            As[swz(4 * k4 + 1, r)] = v.y;
            As[swz(4 * k4 + 2, r)] = v.z;
            As[swz(4 * k4 + 3, r)] = v.w;
        }
        // B tile: 32 k x 64 cols, natural
#pragma unroll
        for (int it = 0; it < 2; it++) {
            int idx = it * 256 + tid;
            int r = idx >> 4, c4 = idx & 15;
            *(float4*)&Bs[r * 64 + 4 * c4] =
                *(const float4*)&w[(kk + r) * COLS3 + col0 + 4 * c4];
        }
        __syncthreads();
#pragma unroll 8
        for (int k = 0; k < 32; k++) {
            float4 av = *(const float4*)&As[swz(k, 4 * ty)];
            float4 bv = *(const float4*)&Bs[k * 64 + 4 * tx];
            float a_[4] = {av.x, av.y, av.z, av.w};
            float b_[4] = {bv.x, bv.y, bv.z, bv.w};
#pragma unroll
            for (int ir = 0; ir < 4; ir++)
#pragma unroll
                for (int jc = 0; jc < 4; jc++)
                    acc[ir][jc] = fmaf(a_[ir], b_[jc], acc[ir][jc]);
        }
    }

    // Epilogue: section (q/k/v), head, dim; RoPE on q,k; scatter.
    const int col = col0 + 4 * tx;
    const int sec = col >> 9;          // 0=q 1=k 2=v
    const int rem = col & 511;
    const int h = rem >> 6;
    const int dbase = rem & 63;        // multiple of 4

    // inv_freq for the two pairs this thread owns (dbase, dbase+2)
    const float LOG2B = 13.287712379549449f; // log2(10000)
    float inv0 = exp2f(-(float)dbase * (LOG2B / 64.f));
    float inv1 = exp2f(-(float)(dbase + 2) * (LOG2B / 64.f));

#pragma unroll
    for (int ir = 0; ir < 4; ir++) {
        int R = row0 + 4 * ty + ir;
        int b = R >> 10, n = R & 1023;
        float v0 = acc[ir][0], v1 = acc[ir][1], v2 = acc[ir][2], v3 = acc[ir][3];
        if (sec == 0) { v0 *= 0.125f; v1 *= 0.125f; v2 *= 0.125f; v3 *= 0.125f; }
        if (sec < 2) {
            float fn = (float)n;
            float s0, c0, s1, c1;
            sincosf(fn * inv0, &s0, &c0);
            sincosf(fn * inv1, &s1, &c1);
            float t0 = v0 * c0 - v1 * s0;
            float t1 = v1 * c0 + v0 * s0;
            float t2 = v2 * c1 - v3 * s1;
            float t3 = v3 * c1 + v2 * s1;
            v0 = t0; v1 = t1; v2 = t2; v3 = t3;
        }
        float* dst = (sec == 0) ? g_q : (sec == 1 ? g_k : g_v);
        float4 o = make_float4(v0, v1, v2, v3);
        *(float4*)&dst[((b * NH + h) * NSEQ + n) * HD + dbase] = o;
    }
}

// ---------------------------------------------------------------------------
// Kernel 2: flash attention per (b,h,64-row Q tile) with additive pos_bias.
// 256 threads (16x16), BM=BN=64, D=64. Smem: Qs[k][i], KP[k][j] (reused for
// P[j][i]), Vs[j][d]. Exactly 48KB static smem.
// ---------------------------------------------------------------------------
__global__ __launch_bounds__(256) void k_attn(const float* __restrict__ bias) {
    __shared__ __align__(16) float Qs[64 * 64];
    __shared__ __align__(16) float KP[64 * 64];
    __shared__ __align__(16) float Vs[64 * 64];

    const int tid = threadIdx.x;
    const int tx = tid & 15, ty = tid >> 4;
    const int i0 = blockIdx.x * 64;
    const int h = blockIdx.y, b = blockIdx.z;
    const int bh = b * NH + h;
    const float* Qg = g_q + bh * NSEQ * HD;
    const float* Kg = g_k + bh * NSEQ * HD;
    const float* Vg = g_v + bh * NSEQ * HD;
    const float* bg = bias + (size_t)h * NSEQ * NSEQ;

    // Load Q tile transposed+swizzled (once)
#pragma unroll
    for (int it = 0; it < 4; it++) {
        int idx = it * 256 + tid;
        int r = idx >> 4, d4 = idx & 15;
        float4 v = *(const float4*)&Qg[(i0 + r) * HD + 4 * d4];
        Qs[swz(4 * d4 + 0, r)] = v.x;
        Qs[swz(4 * d4 + 1, r)] = v.y;
        Qs[swz(4 * d4 + 2, r)] = v.z;
        Qs[swz(4 * d4 + 3, r)] = v.w;
    }

    float o[4][4] = {};
    float m[4], l[4];
#pragma unroll
    for (int ir = 0; ir < 4; ir++) { m[ir] = -INFINITY; l[ir] = 0.f; }

    for (int jt = 0; jt < 16; jt++) {
        const int j0 = jt * 64;
        __syncthreads();
        // K tile transposed+swizzled into KP; V tile natural into Vs
#pragma unroll
        for (int it = 0; it < 4; it++) {
            int idx = it * 256 + tid;
            int r = idx >> 4, d4 = idx & 15;
            float4 kv = *(const float4*)&Kg[(j0 + r) * HD + 4 * d4];
            KP[swz(4 * d4 + 0, r)] = kv.x;
            KP[swz(4 * d4 + 1, r)] = kv.y;
            KP[swz(4 * d4 + 2, r)] = kv.z;
            KP[swz(4 * d4 + 3, r)] = kv.w;
            float4 vv = *(const float4*)&Vg[(j0 + r) * HD + 4 * d4];
            *(float4*)&Vs[r * 64 + 4 * d4] = vv;
        }
        __syncthreads();

        // S = Q K^T (4x4 per thread)
        float s[4][4] = {};
#pragma unroll 8
        for (int k = 0; k < 64; k++) {
            float4 av = *(const float4*)&Qs[swz(k, 4 * ty)];
            float4 bv = *(const float4*)&KP[swz(k, 4 * tx)];
            float a_[4] = {av.x, av.y, av.z, av.w};
            float b_[4] = {bv.x, bv.y, bv.z, bv.w};
#pragma unroll
            for (int ir = 0; ir < 4; ir++)
#pragma unroll
                for (int jc = 0; jc < 4; jc++)
                    s[ir][jc] = fmaf(a_[ir], b_[jc], s[ir][jc]);
        }
        // + pos_bias
#pragma unroll
        for (int ir = 0; ir < 4; ir++) {
            float4 bz = *(const float4*)&bg[(size_t)(i0 + 4 * ty + ir) * NSEQ + j0 + 4 * tx];
            s[ir][0] += bz.x; s[ir][1] += bz.y; s[ir][2] += bz.z; s[ir][3] += bz.w;
        }
        // Online softmax (row groups = 16 lanes sharing ty)
#pragma unroll
        for (int ir = 0; ir < 4; ir++) {
            float tm = fmaxf(fmaxf(s[ir][0], s[ir][1]), fmaxf(s[ir][2], s[ir][3]));
            tm = fmaxf(tm, __shfl_xor_sync(0xffffffffu, tm, 1));
            tm = fmaxf(tm, __shfl_xor_sync(0xffffffffu, tm, 2));
            tm = fmaxf(tm, __shfl_xor_sync(0xffffffffu, tm, 4));
            tm = fmaxf(tm, __shfl_xor_sync(0xffffffffu, tm, 8));
            float mn = fmaxf(m[ir], tm);
            float resc = __expf(m[ir] - mn);
            m[ir] = mn;
            float ps = 0.f;
#pragma unroll
            for (int jc = 0; jc < 4; jc++) {
                s[ir][jc] = __expf(s[ir][jc] - mn);
                ps += s[ir][jc];
            }
            ps += __shfl_xor_sync(0xffffffffu, ps, 1);
            ps += __shfl_xor_sync(0xffffffffu, ps, 2);
            ps += __shfl_xor_sync(0xffffffffu, ps, 4);
            ps += __shfl_xor_sync(0xffffffffu, ps, 8);
            l[ir] = l[ir] * resc + ps;
            o[ir][0] *= resc; o[ir][1] *= resc; o[ir][2] *= resc; o[ir][3] *= resc;
        }
        __syncthreads();   // everyone done reading K from KP
        // P -> KP as [j][i] swizzled (float4 over i)
#pragma unroll
        for (int jc = 0; jc < 4; jc++) {
            float4 pv = make_float4(s[0][jc], s[1][jc], s[2][jc], s[3][jc]);
            *(float4*)&KP[swz(4 * tx + jc, 4 * ty)] = pv;
        }
        __syncthreads();
        // O += P V
#pragma unroll 8
        for (int j = 0; j < 64; j++) {
            float4 av = *(const float4*)&KP[swz(j, 4 * ty)];
            float4 bv = *(const float4*)&Vs[j * 64 + 4 * tx];
            float a_[4] = {av.x, av.y, av.z, av.w};
            float b_[4] = {bv.x, bv.y, bv.z, bv.w};
#pragma unroll
            for (int ir = 0; ir < 4; ir++)
#pragma unroll
                for (int dc = 0; dc < 4; dc++)
                    o[ir][dc] = fmaf(a_[ir], b_[dc], o[ir][dc]);
        }
    }

    // Normalize + store to g_ao in [B,N,H*D] (ready for final GEMM)
#pragma unroll
    for (int ir = 0; ir < 4; ir++) {
        float inv = 1.f / l[ir];
        int i = i0 + 4 * ty + ir;
        float4 ov = make_float4(o[ir][0] * inv, o[ir][1] * inv,
                                o[ir][2] * inv, o[ir][3] * inv);
        *(float4*)&g_ao[((size_t)b * NSEQ + i) * DIMM + h * HD + 4 * tx] = ov;
    }
}

// ---------------------------------------------------------------------------
// Kernel 3: out = g_ao @ w_out  -> d_out.  Grid (8, 128).
// ---------------------------------------------------------------------------
__global__ __launch_bounds__(256) void k_out(const float* __restrict__ w,
                                             float* __restrict__ out) {
    __shared__ __align__(16) float As[32 * 64];
    __shared__ __align__(16) float Bs[32 * 64];

    const int tid = threadIdx.x;
    const int tx = tid & 15, ty = tid >> 4;
    const int row0 = blockIdx.y * 64;
    const int col0 = blockIdx.x * 64;

    float acc[4][4] = {};

    for (int kk = 0; kk < DIMM; kk += 32) {
        __syncthreads();
#pragma unroll
        for (int it = 0; it < 2; it++) {
            int idx = it * 256 + tid;
            int r = idx >> 3, k4 = idx & 7;
            float4 v = *(const float4*)&g_ao[(size_t)(row0 + r) * DIMM + kk + 4 * k4];
            As[swz(4 * k4 + 0, r)] = v.x;
            As[swz(4 * k4 + 1, r)] = v.y;
            As[swz(4 * k4 + 2, r)] = v.z;
            As[swz(4 * k4 + 3, r)] = v.w;
        }
#pragma unroll
        for (int it = 0; it < 2; it++) {
            int idx = it * 256 + tid;
            int r = idx >> 4, c4 = idx & 15;
            *(float4*)&Bs[r * 64 + 4 * c4] =
                *(const float4*)&w[(kk + r) * DIMM + col0 + 4 * c4];
        }
        __syncthreads();
#pragma unroll 8
        for (int k = 0; k < 32; k++) {
            float4 av = *(const float4*)&As[swz(k, 4 * ty)];
            float4 bv = *(const float4*)&Bs[k * 64 + 4 * tx];
            float a_[4] = {av.x, av.y, av.z, av.w};
            float b_[4] = {bv.x, bv.y, bv.z, bv.w};
#pragma unroll
            for (int ir = 0; ir < 4; ir++)
#pragma unroll
                for (int jc = 0; jc < 4; jc++)
                    acc[ir][jc] = fmaf(a_[ir], b_[jc], acc[ir][jc]);
        }
    }
#pragma unroll
    for (int ir = 0; ir < 4; ir++) {
        float4 ov = make_float4(acc[ir][0], acc[ir][1], acc[ir][2], acc[ir][3]);
        *(float4*)&out[(size_t)(row0 + 4 * ty + ir) * DIMM + col0 + 4 * tx] = ov;
    }
}

// ---------------------------------------------------------------------------
extern "C" void kernel_launch(void* const* d_in, const int* in_sizes, int n_in,
                              void* d_out, int out_size) {
    const float *x = nullptr, *pb = nullptr, *wq = nullptr, *wo = nullptr;
    for (int i = 0; i < n_in; i++) {
        switch (in_sizes[i]) {
            case 4194304: x  = (const float*)d_in[i]; break;  // x [8,1024,512]
            case 8388608: pb = (const float*)d_in[i]; break;  // pos_bias [8,1024,1024]
            case 786432:  wq = (const float*)d_in[i]; break;  // w_qkv [512,1536]
            case 262144:  wo = (const float*)d_in[i]; break;  // w_out [512,512]
        }
    }
    // Fallback to metadata order if size-matching failed
    if (!x)  x  = (const float*)d_in[0];
    if (!pb) pb = (const float*)d_in[1];
    if (!wq) wq = (const float*)d_in[2];
    if (!wo) wo = (const float*)d_in[3];

    k_qkv<<<dim3(24, 128), 256>>>(x, wq);
    k_attn<<<dim3(16, NH, BSZ), 256>>>(pb);
    k_out<<<dim3(8, 128), 256>>>(wo, (float*)d_out);
}

// round 2
// speedup vs baseline: 1.3497x; 1.3497x over previous
#include <cuda_runtime.h>
#include <cuda_fp16.h>
#include <math.h>
#include <stdint.h>

#define BSZ   8
#define NSEQ  1024
#define DIMM  512
#define NH    8
#define HD    64
#define COLS3 1536

// Scratch (device globals: allowed; no runtime allocation)
__device__ float g_q[BSZ*NH*NSEQ*HD];
__device__ float g_k[BSZ*NH*NSEQ*HD];
__device__ float g_v[BSZ*NH*NSEQ*HD];
__device__ float g_ao[BSZ*NSEQ*DIMM];

// ---------------------------------------------------------------------------
// mma.sync helpers (m16n8k16 f16 -> f32)
// ---------------------------------------------------------------------------
__device__ __forceinline__ uint32_t smem_u32(const void* p) {
    return (uint32_t)__cvta_generic_to_shared(p);
}
__device__ __forceinline__ void ldsm_x4(uint32_t& r0, uint32_t& r1,
                                        uint32_t& r2, uint32_t& r3, uint32_t a) {
    asm volatile("ldmatrix.sync.aligned.m8n8.x4.shared.b16 {%0,%1,%2,%3}, [%4];\n"
                 : "=r"(r0), "=r"(r1), "=r"(r2), "=r"(r3) : "r"(a));
}
__device__ __forceinline__ void ldsm_x4_t(uint32_t& r0, uint32_t& r1,
                                          uint32_t& r2, uint32_t& r3, uint32_t a) {
    asm volatile("ldmatrix.sync.aligned.m8n8.x4.trans.shared.b16 {%0,%1,%2,%3}, [%4];\n"
                 : "=r"(r0), "=r"(r1), "=r"(r2), "=r"(r3) : "r"(a));
}
__device__ __forceinline__ void mma16816(float c[4], const uint32_t a[4],
                                         const uint32_t b[2]) {
    asm volatile(
        "mma.sync.aligned.m16n8k16.row.col.f32.f16.f16.f32 "
        "{%0,%1,%2,%3}, {%4,%5,%6,%7}, {%8,%9}, {%0,%1,%2,%3};\n"
        : "+f"(c[0]), "+f"(c[1]), "+f"(c[2]), "+f"(c[3])
        : "r"(a[0]), "r"(a[1]), "r"(a[2]), "r"(a[3]), "r"(b[0]), "r"(b[1]));
}

// XOR swizzle for [k][i] smem arrays with stride 64 floats (attention kernel).
__device__ __forceinline__ int swz(int k, int i) {
    return k * 64 + ((((i >> 2) ^ (k >> 2)) & 15) << 2) + (i & 3);
}

// ---------------------------------------------------------------------------
// Tensor-core GEMM with fp16 2-term split (3 MMA passes ~= fp32 accuracy).
// C[8192 x NC] = A[8192 x 512] * B[512 x NC]
// Block 128x128, 8 warps (2x4), warp tile 64x32, K-chunk 32.
// QKV=true: A = x (arg), epilogue = q-scale + interleaved RoPE, scatter q/k/v.
// QKV=false: A = g_ao, plain store to Og.
// ---------------------------------------------------------------------------
template<int NC, bool QKV>
__global__ __launch_bounds__(256) void gemm_mma(const float* __restrict__ Ag,
                                                const float* __restrict__ Bg,
                                                float* __restrict__ Og) {
    constexpr int KD  = 512;
    constexpr int AST = 40;    // half-stride for A tiles (conflict-free ldmatrix)
    constexpr int BST = 136;   // half-stride for B tiles
    __shared__ __align__(16) __half Ah[128 * AST];
    __shared__ __align__(16) __half Al[128 * AST];
    __shared__ __align__(16) __half Bh[32 * BST];
    __shared__ __align__(16) __half Bl[32 * BST];

    const int tid  = threadIdx.x;
    const int lane = tid & 31;
    const int wid  = tid >> 5;
    const int wm   = wid >> 2;   // 0..1  (64-row slab)
    const int wn   = wid & 3;    // 0..3  (32-col slab)
    const int row0 = blockIdx.y * 128;
    const int col0 = blockIdx.x * 128;

    const float* Asrc = QKV ? Ag : g_ao;

    float C[4][4][4];
#pragma unroll
    for (int i = 0; i < 4; i++)
#pragma unroll
        for (int j = 0; j < 4; j++)
#pragma unroll
            for (int e = 0; e < 4; e++) C[i][j][e] = 0.f;

    // gmem->smem mappings (256 threads)
    const int ar = tid >> 1,  ac = (tid & 1) * 16;   // A: 2 thr/row, 16 floats each
    const int br = tid >> 3,  bc = (tid & 7) * 16;   // B: 8 thr/row, 16 floats each

    // ldmatrix lane addressing
    const int lrow = lane & 15;
    const int lko  = (lane >> 4) * 8;

    for (int kk = 0; kk < KD; kk += 32) {
        __syncthreads();
        { // A tile: 128x32 fp32 -> hi/lo halves
            const float* src = Asrc + (size_t)(row0 + ar) * KD + kk + ac;
            __half hb[16], lb[16];
#pragma unroll
            for (int q = 0; q < 4; q++) {
                float4 v = *(const float4*)(src + 4 * q);
                float f[4] = {v.x, v.y, v.z, v.w};
#pragma unroll
                for (int e = 0; e < 4; e++) {
                    __half h = __float2half_rn(f[e]);
                    hb[4*q+e] = h;
                    lb[4*q+e] = __float2half_rn(f[e] - __half2float(h));
                }
            }
            *(uint4*)&Ah[ar*AST + ac]     = *(const uint4*)&hb[0];
            *(uint4*)&Ah[ar*AST + ac + 8] = *(const uint4*)&hb[8];
            *(uint4*)&Al[ar*AST + ac]     = *(const uint4*)&lb[0];
            *(uint4*)&Al[ar*AST + ac + 8] = *(const uint4*)&lb[8];
        }
        { // B tile: 32x128 fp32 -> hi/lo halves
            const float* src = Bg + (size_t)(kk + br) * NC + col0 + bc;
            __half hb[16], lb[16];
#pragma unroll
            for (int q = 0; q < 4; q++) {
                float4 v = *(const float4*)(src + 4 * q);
                float f[4] = {v.x, v.y, v.z, v.w};
#pragma unroll
                for (int e = 0; e < 4; e++) {
                    __half h = __float2half_rn(f[e]);
                    hb[4*q+e] = h;
                    lb[4*q+e] = __float2half_rn(f[e] - __half2float(h));
                }
            }
            *(uint4*)&Bh[br*BST + bc]     = *(const uint4*)&hb[0];
            *(uint4*)&Bh[br*BST + bc + 8] = *(const uint4*)&hb[8];
            *(uint4*)&Bl[br*BST + bc]     = *(const uint4*)&lb[0];
            *(uint4*)&Bl[br*BST + bc + 8] = *(const uint4*)&lb[8];
        }
        __syncthreads();

#pragma unroll
        for (int kq = 0; kq < 32; kq += 16) {
            uint32_t aH[4][4], aL[4][4];
#pragma unroll
            for (int mt = 0; mt < 4; mt++) {
                int r = wm * 64 + mt * 16 + lrow;
                ldsm_x4(aH[mt][0], aH[mt][1], aH[mt][2], aH[mt][3],
                        smem_u32(&Ah[r * AST + kq + lko]));
                ldsm_x4(aL[mt][0], aL[mt][1], aL[mt][2], aL[mt][3],
                        smem_u32(&Al[r * AST + kq + lko]));
            }
#pragma unroll
            for (int ng = 0; ng < 2; ng++) {
                uint32_t bH[4], bL[4];
                int rr = kq + lrow;
                int cb = wn * 32 + ng * 16 + lko;
                ldsm_x4_t(bH[0], bH[1], bH[2], bH[3], smem_u32(&Bh[rr * BST + cb]));
                ldsm_x4_t(bL[0], bL[1], bL[2], bL[3], smem_u32(&Bl[rr * BST + cb]));
#pragma unroll
                for (int mt = 0; mt < 4; mt++) {
                    mma16816(C[mt][ng*2],     aH[mt], &bH[0]);
                    mma16816(C[mt][ng*2],     aH[mt], &bL[0]);
                    mma16816(C[mt][ng*2],     aL[mt], &bH[0]);
                    mma16816(C[mt][ng*2 + 1], aH[mt], &bH[2]);
                    mma16816(C[mt][ng*2 + 1], aH[mt], &bL[2]);
                    mma16816(C[mt][ng*2 + 1], aL[mt], &bH[2]);
                }
            }
        }
    }

    // Epilogue. C fragment: e0,e1 = (row g, cols 2c,2c+1); e2,e3 = (row g+8).
    const int g  = lane >> 2;
    const int cc = (lane & 3) * 2;
    if (QKV) {
        const int sec     = col0 >> 9;                 // uniform per block
        const int rembase = (col0 & 511) + wn * 32;
        float* dst = (sec == 0) ? g_q : (sec == 1 ? g_k : g_v);
        const float LOG2B = 13.287712379549449f;       // log2(10000)
#pragma unroll
        for (int nt = 0; nt < 4; nt++) {
            int rem   = rembase + nt * 8 + cc;
            int h     = rem >> 6;
            int dbase = rem & 63;
            float ifr = exp2f(-(float)dbase * (LOG2B / 64.f));
#pragma unroll
            for (int mt = 0; mt < 4; mt++) {
#pragma unroll
                for (int hf = 0; hf < 2; hf++) {
                    int R = row0 + wm * 64 + mt * 16 + g + hf * 8;
                    int b = R >> 10, n = R & 1023;
                    float v0 = C[mt][nt][hf*2 + 0];
                    float v1 = C[mt][nt][hf*2 + 1];
                    if (sec == 0) { v0 *= 0.125f; v1 *= 0.125f; }
                    if (sec < 2) {
                        float s, co;
                        sincosf((float)n * ifr, &s, &co);
                        float t0 = v0 * co - v1 * s;
                        float t1 = v1 * co + v0 * s;
                        v0 = t0; v1 = t1;
                    }
                    *(float2*)&dst[(((size_t)b * NH + h) * NSEQ + n) * HD + dbase] =
                        make_float2(v0, v1);
                }
            }
        }
    } else {
#pragma unroll
        for (int nt = 0; nt < 4; nt++) {
            int colg = col0 + wn * 32 + nt * 8 + cc;
#pragma unroll
            for (int mt = 0; mt < 4; mt++) {
#pragma unroll
                for (int hf = 0; hf < 2; hf++) {
                    int R = row0 + wm * 64 + mt * 16 + g + hf * 8;
                    *(float2*)&Og[(size_t)R * NC + colg] =
                        make_float2(C[mt][nt][hf*2], C[mt][nt][hf*2 + 1]);
                }
            }
        }
    }
}

// ---------------------------------------------------------------------------
// Kernel 2: flash attention per (b,h,64-row Q tile) with additive pos_bias.
// (unchanged from R1 — target of the next round)
// ---------------------------------------------------------------------------
__global__ __launch_bounds__(256) void k_attn(const float* __restrict__ bias) {
    __shared__ __align__(16) float Qs[64 * 64];
    __shared__ __align__(16) float KP[64 * 64];
    __shared__ __align__(16) float Vs[64 * 64];

    const int tid = threadIdx.x;
    const int tx = tid & 15, ty = tid >> 4;
    const int i0 = blockIdx.x * 64;
    const int h = blockIdx.y, b = blockIdx.z;
    const int bh = b * NH + h;
    const float* Qg = g_q + bh * NSEQ * HD;
    const float* Kg = g_k + bh * NSEQ * HD;
    const float* Vg = g_v + bh * NSEQ * HD;
    const float* bg = bias + (size_t)h * NSEQ * NSEQ;

#pragma unroll
    for (int it = 0; it < 4; it++) {
        int idx = it * 256 + tid;
        int r = idx >> 4, d4 = idx & 15;
        float4 v = *(const float4*)&Qg[(i0 + r) * HD + 4 * d4];
        Qs[swz(4 * d4 + 0, r)] = v.x;
        Qs[swz(4 * d4 + 1, r)] = v.y;
        Qs[swz(4 * d4 + 2, r)] = v.z;
        Qs[swz(4 * d4 + 3, r)] = v.w;
    }

    float o[4][4] = {};
    float m[4], l[4];
#pragma unroll
    for (int ir = 0; ir < 4; ir++) { m[ir] = -INFINITY; l[ir] = 0.f; }

    for (int jt = 0; jt < 16; jt++) {
        const int j0 = jt * 64;
        __syncthreads();
#pragma unroll
        for (int it = 0; it < 4; it++) {
            int idx = it * 256 + tid;
            int r = idx >> 4, d4 = idx & 15;
            float4 kv = *(const float4*)&Kg[(j0 + r) * HD + 4 * d4];
            KP[swz(4 * d4 + 0, r)] = kv.x;
            KP[swz(4 * d4 + 1, r)] = kv.y;
            KP[swz(4 * d4 + 2, r)] = kv.z;
            KP[swz(4 * d4 + 3, r)] = kv.w;
            float4 vv = *(const float4*)&Vg[(j0 + r) * HD + 4 * d4];
            *(float4*)&Vs[r * 64 + 4 * d4] = vv;
        }
        __syncthreads();

        float s[4][4] = {};
#pragma unroll 8
        for (int k = 0; k < 64; k++) {
            float4 av = *(const float4*)&Qs[swz(k, 4 * ty)];
            float4 bv = *(const float4*)&KP[swz(k, 4 * tx)];
            float a_[4] = {av.x, av.y, av.z, av.w};
            float b_[4] = {bv.x, bv.y, bv.z, bv.w};
#pragma unroll
            for (int ir = 0; ir < 4; ir++)
#pragma unroll
                for (int jc = 0; jc < 4; jc++)
                    s[ir][jc] = fmaf(a_[ir], b_[jc], s[ir][jc]);
        }
#pragma unroll
        for (int ir = 0; ir < 4; ir++) {
            float4 bz = *(const float4*)&bg[(size_t)(i0 + 4 * ty + ir) * NSEQ + j0 + 4 * tx];
            s[ir][0] += bz.x; s[ir][1] += bz.y; s[ir][2] += bz.z; s[ir][3] += bz.w;
        }
#pragma unroll
        for (int ir = 0; ir < 4; ir++) {
            float tm = fmaxf(fmaxf(s[ir][0], s[ir][1]), fmaxf(s[ir][2], s[ir][3]));
            tm = fmaxf(tm, __shfl_xor_sync(0xffffffffu, tm, 1));
            tm = fmaxf(tm, __shfl_xor_sync(0xffffffffu, tm, 2));
            tm = fmaxf(tm, __shfl_xor_sync(0xffffffffu, tm, 4));
            tm = fmaxf(tm, __shfl_xor_sync(0xffffffffu, tm, 8));
            float mn = fmaxf(m[ir], tm);
            float resc = __expf(m[ir] - mn);
            m[ir] = mn;
            float ps = 0.f;
#pragma unroll
            for (int jc = 0; jc < 4; jc++) {
                s[ir][jc] = __expf(s[ir][jc] - mn);
                ps += s[ir][jc];
            }
            ps += __shfl_xor_sync(0xffffffffu, ps, 1);
            ps += __shfl_xor_sync(0xffffffffu, ps, 2);
            ps += __shfl_xor_sync(0xffffffffu, ps, 4);
            ps += __shfl_xor_sync(0xffffffffu, ps, 8);
            l[ir] = l[ir] * resc + ps;
            o[ir][0] *= resc; o[ir][1] *= resc; o[ir][2] *= resc; o[ir][3] *= resc;
        }
        __syncthreads();
#pragma unroll
        for (int jc = 0; jc < 4; jc++) {
            float4 pv = make_float4(s[0][jc], s[1][jc], s[2][jc], s[3][jc]);
            *(float4*)&KP[swz(4 * tx + jc, 4 * ty)] = pv;
        }
        __syncthreads();
#pragma unroll 8
        for (int j = 0; j < 64; j++) {
            float4 av = *(const float4*)&KP[swz(j, 4 * ty)];
            float4 bv = *(const float4*)&Vs[j * 64 + 4 * tx];
            float a_[4] = {av.x, av.y, av.z, av.w};
            float b_[4] = {bv.x, bv.y, bv.z, bv.w};
#pragma unroll
            for (int ir = 0; ir < 4; ir++)
#pragma unroll
                for (int dc = 0; dc < 4; dc++)
                    o[ir][dc] = fmaf(a_[ir], b_[dc], o[ir][dc]);
        }
    }

#pragma unroll
    for (int ir = 0; ir < 4; ir++) {
        float inv = 1.f / l[ir];
        int i = i0 + 4 * ty + ir;
        float4 ov = make_float4(o[ir][0] * inv, o[ir][1] * inv,
                                o[ir][2] * inv, o[ir][3] * inv);
        *(float4*)&g_ao[((size_t)b * NSEQ + i) * DIMM + h * HD + 4 * tx] = ov;
    }
}

// ---------------------------------------------------------------------------
extern "C" void kernel_launch(void* const* d_in, const int* in_sizes, int n_in,
                              void* d_out, int out_size) {
    const float *x = nullptr, *pb = nullptr, *wq = nullptr, *wo = nullptr;
    for (int i = 0; i < n_in; i++) {
        switch (in_sizes[i]) {
            case 4194304: x  = (const float*)d_in[i]; break;  // x [8,1024,512]
            case 8388608: pb = (const float*)d_in[i]; break;  // pos_bias [8,1024,1024]
            case 786432:  wq = (const float*)d_in[i]; break;  // w_qkv [512,1536]
            case 262144:  wo = (const float*)d_in[i]; break;  // w_out [512,512]
        }
    }
    if (!x)  x  = (const float*)d_in[0];
    if (!pb) pb = (const float*)d_in[1];
    if (!wq) wq = (const float*)d_in[2];
    if (!wo) wo = (const float*)d_in[3];

    gemm_mma<COLS3, true><<<dim3(12, 64), 256>>>(x, wq, nullptr);
    k_attn<<<dim3(16, NH, BSZ), 256>>>(pb);
    gemm_mma<DIMM, false><<<dim3(4, 64), 256>>>(nullptr, wo, (float*)d_out);
}

// round 3
// speedup vs baseline: 2.1149x; 1.5670x over previous
#include <cuda_runtime.h>
#include <cuda_fp16.h>
#include <math.h>
#include <stdint.h>

#define BSZ   8
#define NSEQ  1024
#define DIMM  512
#define NH    8
#define HD    64
#define COLS3 1536

// Scratch (device globals: allowed; no runtime allocation)
__device__ float g_q[BSZ*NH*NSEQ*HD];
__device__ float g_k[BSZ*NH*NSEQ*HD];
__device__ float g_v[BSZ*NH*NSEQ*HD];
__device__ float g_ao[BSZ*NSEQ*DIMM];

// ---------------------------------------------------------------------------
// mma.sync helpers (m16n8k16 f16 -> f32)
// ---------------------------------------------------------------------------
__device__ __forceinline__ uint32_t smem_u32(const void* p) {
    return (uint32_t)__cvta_generic_to_shared(p);
}
__device__ __forceinline__ void ldsm_x4(uint32_t& r0, uint32_t& r1,
                                        uint32_t& r2, uint32_t& r3, uint32_t a) {
    asm volatile("ldmatrix.sync.aligned.m8n8.x4.shared.b16 {%0,%1,%2,%3}, [%4];\n"
                 : "=r"(r0), "=r"(r1), "=r"(r2), "=r"(r3) : "r"(a));
}
__device__ __forceinline__ void ldsm_x4_t(uint32_t& r0, uint32_t& r1,
                                          uint32_t& r2, uint32_t& r3, uint32_t a) {
    asm volatile("ldmatrix.sync.aligned.m8n8.x4.trans.shared.b16 {%0,%1,%2,%3}, [%4];\n"
                 : "=r"(r0), "=r"(r1), "=r"(r2), "=r"(r3) : "r"(a));
}
__device__ __forceinline__ void mma16816(float c[4], const uint32_t a[4],
                                         const uint32_t b[2]) {
    asm volatile(
        "mma.sync.aligned.m16n8k16.row.col.f32.f16.f16.f32 "
        "{%0,%1,%2,%3}, {%4,%5,%6,%7}, {%8,%9}, {%0,%1,%2,%3};\n"
        : "+f"(c[0]), "+f"(c[1]), "+f"(c[2]), "+f"(c[3])
        : "r"(a[0]), "r"(a[1]), "r"(a[2]), "r"(a[3]), "r"(b[0]), "r"(b[1]));
}
__device__ __forceinline__ void mma2(float c[4], const uint32_t a[4],
                                     uint32_t b0, uint32_t b1) {
    asm volatile(
        "mma.sync.aligned.m16n8k16.row.col.f32.f16.f16.f32 "
        "{%0,%1,%2,%3}, {%4,%5,%6,%7}, {%8,%9}, {%0,%1,%2,%3};\n"
        : "+f"(c[0]), "+f"(c[1]), "+f"(c[2]), "+f"(c[3])
        : "r"(a[0]), "r"(a[1]), "r"(a[2]), "r"(a[3]), "r"(b0), "r"(b1));
}
__device__ __forceinline__ uint32_t pkh2(__half a, __half b) {
    __half2 t = __halves2half2(a, b);
    return *reinterpret_cast<uint32_t*>(&t);
}

// ---------------------------------------------------------------------------
// Tensor-core GEMM with fp16 2-term split (3 MMA passes ~= fp32 accuracy).
// (unchanged from R2 — known good)
// ---------------------------------------------------------------------------
template<int NC, bool QKV>
__global__ __launch_bounds__(256) void gemm_mma(const float* __restrict__ Ag,
                                                const float* __restrict__ Bg,
                                                float* __restrict__ Og) {
    constexpr int KD  = 512;
    constexpr int AST = 40;
    constexpr int BST = 136;
    __shared__ __align__(16) __half Ah[128 * AST];
    __shared__ __align__(16) __half Al[128 * AST];
    __shared__ __align__(16) __half Bh[32 * BST];
    __shared__ __align__(16) __half Bl[32 * BST];

    const int tid  = threadIdx.x;
    const int lane = tid & 31;
    const int wid  = tid >> 5;
    const int wm   = wid >> 2;
    const int wn   = wid & 3;
    const int row0 = blockIdx.y * 128;
    const int col0 = blockIdx.x * 128;

    const float* Asrc = QKV ? Ag : g_ao;

    float C[4][4][4];
#pragma unroll
    for (int i = 0; i < 4; i++)
#pragma unroll
        for (int j = 0; j < 4; j++)
#pragma unroll
            for (int e = 0; e < 4; e++) C[i][j][e] = 0.f;

    const int ar = tid >> 1,  ac = (tid & 1) * 16;
    const int br = tid >> 3,  bc = (tid & 7) * 16;
    const int lrow = lane & 15;
    const int lko  = (lane >> 4) * 8;

    for (int kk = 0; kk < KD; kk += 32) {
        __syncthreads();
        {
            const float* src = Asrc + (size_t)(row0 + ar) * KD + kk + ac;
            __half hb[16], lb[16];
#pragma unroll
            for (int q = 0; q < 4; q++) {
                float4 v = *(const float4*)(src + 4 * q);
                float f[4] = {v.x, v.y, v.z, v.w};
#pragma unroll
                for (int e = 0; e < 4; e++) {
                    __half h = __float2half_rn(f[e]);
                    hb[4*q+e] = h;
                    lb[4*q+e] = __float2half_rn(f[e] - __half2float(h));
                }
            }
            *(uint4*)&Ah[ar*AST + ac]     = *(const uint4*)&hb[0];
            *(uint4*)&Ah[ar*AST + ac + 8] = *(const uint4*)&hb[8];
            *(uint4*)&Al[ar*AST + ac]     = *(const uint4*)&lb[0];
            *(uint4*)&Al[ar*AST + ac + 8] = *(const uint4*)&lb[8];
        }
        {
            const float* src = Bg + (size_t)(kk + br) * NC + col0 + bc;
            __half hb[16], lb[16];
#pragma unroll
            for (int q = 0; q < 4; q++) {
                float4 v = *(const float4*)(src + 4 * q);
                float f[4] = {v.x, v.y, v.z, v.w};
#pragma unroll
                for (int e = 0; e < 4; e++) {
                    __half h = __float2half_rn(f[e]);
                    hb[4*q+e] = h;
                    lb[4*q+e] = __float2half_rn(f[e] - __half2float(h));
                }
            }
            *(uint4*)&Bh[br*BST + bc]     = *(const uint4*)&hb[0];
            *(uint4*)&Bh[br*BST + bc + 8] = *(const uint4*)&hb[8];
            *(uint4*)&Bl[br*BST + bc]     = *(const uint4*)&lb[0];
            *(uint4*)&Bl[br*BST + bc + 8] = *(const uint4*)&lb[8];
        }
        __syncthreads();

#pragma unroll
        for (int kq = 0; kq < 32; kq += 16) {
            uint32_t aH[4][4], aL[4][4];
#pragma unroll
            for (int mt = 0; mt < 4; mt++) {
                int r = wm * 64 + mt * 16 + lrow;
                ldsm_x4(aH[mt][0], aH[mt][1], aH[mt][2], aH[mt][3],
                        smem_u32(&Ah[r * AST + kq + lko]));
                ldsm_x4(aL[mt][0], aL[mt][1], aL[mt][2], aL[mt][3],
                        smem_u32(&Al[r * AST + kq + lko]));
            }
#pragma unroll
            for (int ng = 0; ng < 2; ng++) {
                uint32_t bH[4], bL[4];
                int rr = kq + lrow;
                int cb = wn * 32 + ng * 16 + lko;
                ldsm_x4_t(bH[0], bH[1], bH[2], bH[3], smem_u32(&Bh[rr * BST + cb]));
                ldsm_x4_t(bL[0], bL[1], bL[2], bL[3], smem_u32(&Bl[rr * BST + cb]));
#pragma unroll
                for (int mt = 0; mt < 4; mt++) {
                    mma16816(C[mt][ng*2],     aH[mt], &bH[0]);
                    mma16816(C[mt][ng*2],     aH[mt], &bL[0]);
                    mma16816(C[mt][ng*2],     aL[mt], &bH[0]);
                    mma16816(C[mt][ng*2 + 1], aH[mt], &bH[2]);
                    mma16816(C[mt][ng*2 + 1], aH[mt], &bL[2]);
                    mma16816(C[mt][ng*2 + 1], aL[mt], &bH[2]);
                }
            }
        }
    }

    const int g  = lane >> 2;
    const int cc = (lane & 3) * 2;
    if (QKV) {
        const int sec     = col0 >> 9;
        const int rembase = (col0 & 511) + wn * 32;
        float* dst = (sec == 0) ? g_q : (sec == 1 ? g_k : g_v);
        const float LOG2B = 13.287712379549449f;
#pragma unroll
        for (int nt = 0; nt < 4; nt++) {
            int rem   = rembase + nt * 8 + cc;
            int h     = rem >> 6;
            int dbase = rem & 63;
            float ifr = exp2f(-(float)dbase * (LOG2B / 64.f));
#pragma unroll
            for (int mt = 0; mt < 4; mt++) {
#pragma unroll
                for (int hf = 0; hf < 2; hf++) {
                    int R = row0 + wm * 64 + mt * 16 + g + hf * 8;
                    int b = R >> 10, n = R & 1023;
                    float v0 = C[mt][nt][hf*2 + 0];
                    float v1 = C[mt][nt][hf*2 + 1];
                    if (sec == 0) { v0 *= 0.125f; v1 *= 0.125f; }
                    if (sec < 2) {
                        float s, co;
                        sincosf((float)n * ifr, &s, &co);
                        float t0 = v0 * co - v1 * s;
                        float t1 = v1 * co + v0 * s;
                        v0 = t0; v1 = t1;
                    }
                    *(float2*)&dst[(((size_t)b * NH + h) * NSEQ + n) * HD + dbase] =
                        make_float2(v0, v1);
                }
            }
        }
    } else {
#pragma unroll
        for (int nt = 0; nt < 4; nt++) {
            int colg = col0 + wn * 32 + nt * 8 + cc;
#pragma unroll
            for (int mt = 0; mt < 4; mt++) {
#pragma unroll
                for (int hf = 0; hf < 2; hf++) {
                    int R = row0 + wm * 64 + mt * 16 + g + hf * 8;
                    *(float2*)&Og[(size_t)R * NC + colg] =
                        make_float2(C[mt][nt][hf*2], C[mt][nt][hf*2 + 1]);
                }
            }
        }
    }
}

// ---------------------------------------------------------------------------
// Flash attention on tensor cores, fp16 2-term split everywhere.
// Block: 128 Q-rows x one (b,h). 8 warps, each owns 16 Q rows.
// Smem (dynamic, 72KB): Qh/Ql [128x72], Kh/Kl [64x72], Vh/Vl [64x72].
// K stored natural [j][d] -> non-trans ldsm gives B-frags for S=Q*K^T.
// V stored natural [j][d] -> trans ldsm gives B-frags for O=P*V.
// P fragments built in registers from S fragments (no smem round trip).
// ---------------------------------------------------------------------------
#define QST 72
#define ATTN_SMEM ((2*128*QST + 4*64*QST) * 2)   // 73728 bytes

__global__ __launch_bounds__(256, 1) void k_attn_mma(const float* __restrict__ bias) {
    extern __shared__ __half sm[];
    __half* Qh = sm;
    __half* Ql = Qh + 128*QST;
    __half* Kh = Ql + 128*QST;
    __half* Kl = Kh + 64*QST;
    __half* Vh = Kl + 64*QST;
    __half* Vl = Vh + 64*QST;

    const int b  = blockIdx.x;      // fastest: batches share bias slice in L2
    const int h  = blockIdx.y;
    const int i0 = blockIdx.z * 128;
    const int tid = threadIdx.x, lane = tid & 31, w = tid >> 5;
    const int lrow = lane & 15, lko = (lane >> 4) * 8;
    const int g = lane >> 2, c2 = (lane & 3) * 2;

    const size_t bh = (size_t)(b * NH + h) * NSEQ * HD;
    const float* Qg = g_q + bh;
    const float* Kg = g_k + bh;
    const float* Vg = g_v + bh;
    const float* bg = bias + (size_t)h * NSEQ * NSEQ;

    // ---- load Q tile 128x64 once, split hi/lo ----
    {
        int r = tid >> 1, c0 = (tid & 1) * 32;
        const float* src = Qg + (size_t)(i0 + r) * HD + c0;
        __half hb[32], lb[32];
#pragma unroll
        for (int q = 0; q < 8; q++) {
            float4 v = *(const float4*)(src + 4 * q);
            float f[4] = {v.x, v.y, v.z, v.w};
#pragma unroll
            for (int e = 0; e < 4; e++) {
                __half hh = __float2half_rn(f[e]);
                hb[4*q+e] = hh;
                lb[4*q+e] = __float2half_rn(f[e] - __half2float(hh));
            }
        }
#pragma unroll
        for (int q = 0; q < 4; q++) {
            *(uint4*)&Qh[r*QST + c0 + 8*q] = *(const uint4*)&hb[8*q];
            *(uint4*)&Ql[r*QST + c0 + 8*q] = *(const uint4*)&lb[8*q];
        }
    }

    float Of[8][4];
#pragma unroll
    for (int nt = 0; nt < 8; nt++)
#pragma unroll
        for (int e = 0; e < 4; e++) Of[nt][e] = 0.f;
    float m0 = -INFINITY, m1 = -INFINITY, l0 = 0.f, l1 = 0.f;

    const int r0g = i0 + w * 16 + g;       // this thread's first global Q row

    for (int jt = 0; jt < 16; jt++) {
        const int j0 = jt * 64;
        __syncthreads();
        // ---- load K/V tile 64x64 each, split hi/lo ----
        {
            int jr = tid >> 2, c0 = (tid & 3) * 16;
            const float* ks = Kg + (size_t)(j0 + jr) * HD + c0;
            const float* vs = Vg + (size_t)(j0 + jr) * HD + c0;
            __half khb[16], klb[16], vhb[16], vlb[16];
#pragma unroll
            for (int q = 0; q < 4; q++) {
                float4 kv = *(const float4*)(ks + 4 * q);
                float4 vv = *(const float4*)(vs + 4 * q);
                float kf[4] = {kv.x, kv.y, kv.z, kv.w};
                float vf[4] = {vv.x, vv.y, vv.z, vv.w};
#pragma unroll
                for (int e = 0; e < 4; e++) {
                    __half hk = __float2half_rn(kf[e]);
                    khb[4*q+e] = hk;
                    klb[4*q+e] = __float2half_rn(kf[e] - __half2float(hk));
                    __half hv = __float2half_rn(vf[e]);
                    vhb[4*q+e] = hv;
                    vlb[4*q+e] = __float2half_rn(vf[e] - __half2float(hv));
                }
            }
            *(uint4*)&Kh[jr*QST + c0]     = *(const uint4*)&khb[0];
            *(uint4*)&Kh[jr*QST + c0 + 8] = *(const uint4*)&khb[8];
            *(uint4*)&Kl[jr*QST + c0]     = *(const uint4*)&klb[0];
            *(uint4*)&Kl[jr*QST + c0 + 8] = *(const uint4*)&klb[8];
            *(uint4*)&Vh[jr*QST + c0]     = *(const uint4*)&vhb[0];
            *(uint4*)&Vh[jr*QST + c0 + 8] = *(const uint4*)&vhb[8];
            *(uint4*)&Vl[jr*QST + c0]     = *(const uint4*)&vlb[0];
            *(uint4*)&Vl[jr*QST + c0 + 8] = *(const uint4*)&vlb[8];
        }
        __syncthreads();

        // ---- S = Q K^T (128 x 64 per block; 16 x 64 per warp) ----
        float Sf[8][4];
#pragma unroll
        for (int nt = 0; nt < 8; nt++)
#pragma unroll
            for (int e = 0; e < 4; e++) Sf[nt][e] = 0.f;

#pragma unroll
        for (int ks = 0; ks < 4; ks++) {
            uint32_t aH[4], aL[4];
            ldsm_x4(aH[0], aH[1], aH[2], aH[3],
                    smem_u32(&Qh[(w*16 + lrow)*QST + ks*16 + lko]));
            ldsm_x4(aL[0], aL[1], aL[2], aL[3],
                    smem_u32(&Ql[(w*16 + lrow)*QST + ks*16 + lko]));
#pragma unroll
            for (int ng = 0; ng < 4; ng++) {
                uint32_t bh_[4], bl_[4];
                ldsm_x4(bh_[0], bh_[1], bh_[2], bh_[3],
                        smem_u32(&Kh[(ng*16 + lrow)*QST + ks*16 + lko]));
                ldsm_x4(bl_[0], bl_[1], bl_[2], bl_[3],
                        smem_u32(&Kl[(ng*16 + lrow)*QST + ks*16 + lko]));
                // non-trans pairing: tile(2ng)->(r0,r2), tile(2ng+1)->(r1,r3)
                mma2(Sf[2*ng],   aH, bh_[0], bh_[2]);
                mma2(Sf[2*ng],   aH, bl_[0], bl_[2]);
                mma2(Sf[2*ng],   aL, bh_[0], bh_[2]);
                mma2(Sf[2*ng+1], aH, bh_[1], bh_[3]);
                mma2(Sf[2*ng+1], aH, bl_[1], bl_[3]);
                mma2(Sf[2*ng+1], aL, bh_[1], bh_[3]);
            }
        }

        // ---- + pos_bias ----
        {
            const float* bp0 = bg + (size_t)r0g * NSEQ + j0 + c2;
            const float* bp1 = bp0 + 8 * NSEQ;
#pragma unroll
            for (int nt = 0; nt < 8; nt++) {
                float2 u = *(const float2*)(bp0 + nt * 8);
                float2 v = *(const float2*)(bp1 + nt * 8);
                Sf[nt][0] += u.x; Sf[nt][1] += u.y;
                Sf[nt][2] += v.x; Sf[nt][3] += v.y;
            }
        }

        // ---- online softmax (rows r0g, r0g+8; spread over lane&3) ----
        float mx0 = -INFINITY, mx1 = -INFINITY;
#pragma unroll
        for (int nt = 0; nt < 8; nt++) {
            mx0 = fmaxf(mx0, fmaxf(Sf[nt][0], Sf[nt][1]));
            mx1 = fmaxf(mx1, fmaxf(Sf[nt][2], Sf[nt][3]));
        }
        mx0 = fmaxf(mx0, __shfl_xor_sync(0xffffffffu, mx0, 1));
        mx0 = fmaxf(mx0, __shfl_xor_sync(0xffffffffu, mx0, 2));
        mx1 = fmaxf(mx1, __shfl_xor_sync(0xffffffffu, mx1, 1));
        mx1 = fmaxf(mx1, __shfl_xor_sync(0xffffffffu, mx1, 2));
        float mn0 = fmaxf(m0, mx0), mn1 = fmaxf(m1, mx1);
        float rs0 = __expf(m0 - mn0), rs1 = __expf(m1 - mn1);
        m0 = mn0; m1 = mn1;

        uint32_t pH0[8], pH1[8], pL0[8], pL1[8];
        float s0 = 0.f, s1 = 0.f;
#pragma unroll
        for (int nt = 0; nt < 8; nt++) {
            float p0 = __expf(Sf[nt][0] - mn0);
            float p1 = __expf(Sf[nt][1] - mn0);
            float p2 = __expf(Sf[nt][2] - mn1);
            float p3 = __expf(Sf[nt][3] - mn1);
            s0 += p0 + p1; s1 += p2 + p3;
            __half h0 = __float2half_rn(p0), h1 = __float2half_rn(p1);
            __half h2 = __float2half_rn(p2), h3 = __float2half_rn(p3);
            pH0[nt] = pkh2(h0, h1);
            pH1[nt] = pkh2(h2, h3);
            pL0[nt] = pkh2(__float2half_rn(p0 - __half2float(h0)),
                           __float2half_rn(p1 - __half2float(h1)));
            pL1[nt] = pkh2(__float2half_rn(p2 - __half2float(h2)),
                           __float2half_rn(p3 - __half2float(h3)));
        }
        s0 += __shfl_xor_sync(0xffffffffu, s0, 1);
        s0 += __shfl_xor_sync(0xffffffffu, s0, 2);
        s1 += __shfl_xor_sync(0xffffffffu, s1, 1);
        s1 += __shfl_xor_sync(0xffffffffu, s1, 2);
        l0 = l0 * rs0 + s0;
        l1 = l1 * rs1 + s1;
#pragma unroll
        for (int nt = 0; nt < 8; nt++) {
            Of[nt][0] *= rs0; Of[nt][1] *= rs0;
            Of[nt][2] *= rs1; Of[nt][3] *= rs1;
        }

        // ---- O += P V (P a-frags from registers; V b-frags via trans ldsm) ----
#pragma unroll
        for (int ks = 0; ks < 4; ks++) {
            uint32_t aH[4] = {pH0[2*ks], pH1[2*ks], pH0[2*ks+1], pH1[2*ks+1]};
            uint32_t aL[4] = {pL0[2*ks], pL1[2*ks], pL0[2*ks+1], pL1[2*ks+1]};
#pragma unroll
            for (int dg = 0; dg < 4; dg++) {
                uint32_t bh_[4], bl_[4];
                ldsm_x4_t(bh_[0], bh_[1], bh_[2], bh_[3],
                          smem_u32(&Vh[(ks*16 + lrow)*QST + dg*16 + lko]));
                ldsm_x4_t(bl_[0], bl_[1], bl_[2], bl_[3],
                          smem_u32(&Vl[(ks*16 + lrow)*QST + dg*16 + lko]));
                // trans pairing: tile(2dg)->(r0,r1), tile(2dg+1)->(r2,r3)
                mma2(Of[2*dg],   aH, bh_[0], bh_[1]);
                mma2(Of[2*dg],   aH, bl_[0], bl_[1]);
                mma2(Of[2*dg],   aL, bh_[0], bh_[1]);
                mma2(Of[2*dg+1], aH, bh_[2], bh_[3]);
                mma2(Of[2*dg+1], aH, bl_[2], bl_[3]);
                mma2(Of[2*dg+1], aL, bh_[2], bh_[3]);
            }
        }
    }

    // ---- normalize + store to g_ao [B,N,H*D] ----
    {
        float inv0 = 1.f / l0, inv1 = 1.f / l1;
        float* o0 = g_ao + ((size_t)b * NSEQ + r0g) * DIMM + h * HD + c2;
        float* o1 = o0 + 8 * DIMM;
#pragma unroll
        for (int nt = 0; nt < 8; nt++) {
            *(float2*)(o0 + nt * 8) = make_float2(Of[nt][0] * inv0, Of[nt][1] * inv0);
            *(float2*)(o1 + nt * 8) = make_float2(Of[nt][2] * inv1, Of[nt][3] * inv1);
        }
    }
}

// ---------------------------------------------------------------------------
extern "C" void kernel_launch(void* const* d_in, const int* in_sizes, int n_in,
                              void* d_out, int out_size) {
    const float *x = nullptr, *pb = nullptr, *wq = nullptr, *wo = nullptr;
    for (int i = 0; i < n_in; i++) {
        switch (in_sizes[i]) {
            case 4194304: x  = (const float*)d_in[i]; break;  // x [8,1024,512]
            case 8388608: pb = (const float*)d_in[i]; break;  // pos_bias [8,1024,1024]
            case 786432:  wq = (const float*)d_in[i]; break;  // w_qkv [512,1536]
            case 262144:  wo = (const float*)d_in[i]; break;  // w_out [512,512]
        }
    }
    if (!x)  x  = (const float*)d_in[0];
    if (!pb) pb = (const float*)d_in[1];
    if (!wq) wq = (const float*)d_in[2];
    if (!wo) wo = (const float*)d_in[3];

    cudaFuncSetAttribute(k_attn_mma, cudaFuncAttributeMaxDynamicSharedMemorySize,
                         ATTN_SMEM);

    gemm_mma<COLS3, true><<<dim3(12, 64), 256>>>(x, wq, nullptr);
    k_attn_mma<<<dim3(BSZ, NH, 8), 256, ATTN_SMEM>>>(pb);
    gemm_mma<DIMM, false><<<dim3(4, 64), 256>>>(nullptr, wo, (float*)d_out);
}

// round 4
// speedup vs baseline: 2.4705x; 1.1682x over previous
#include <cuda_runtime.h>
#include <cuda_fp16.h>
#include <math.h>
#include <stdint.h>

#define BSZ   8
#define NSEQ  1024
#define DIMM  512
#define NH    8
#define HD    64
#define COLS3 1536

// Scratch: Q/K/V stored pre-split into fp16 hi/lo (split done in QKV epilogue).
__device__ __align__(16) __half g_qh[BSZ*NH*NSEQ*HD];
__device__ __align__(16) __half g_ql[BSZ*NH*NSEQ*HD];
__device__ __align__(16) __half g_kh[BSZ*NH*NSEQ*HD];
__device__ __align__(16) __half g_kl[BSZ*NH*NSEQ*HD];
__device__ __align__(16) __half g_vh[BSZ*NH*NSEQ*HD];
__device__ __align__(16) __half g_vl[BSZ*NH*NSEQ*HD];
__device__ float g_ao[BSZ*NSEQ*DIMM];

// ---------------------------------------------------------------------------
// helpers
// ---------------------------------------------------------------------------
__device__ __forceinline__ uint32_t smem_u32(const void* p) {
    return (uint32_t)__cvta_generic_to_shared(p);
}
__device__ __forceinline__ void ldsm_x4(uint32_t& r0, uint32_t& r1,
                                        uint32_t& r2, uint32_t& r3, uint32_t a) {
    asm volatile("ldmatrix.sync.aligned.m8n8.x4.shared.b16 {%0,%1,%2,%3}, [%4];\n"
                 : "=r"(r0), "=r"(r1), "=r"(r2), "=r"(r3) : "r"(a));
}
__device__ __forceinline__ void ldsm_x4_t(uint32_t& r0, uint32_t& r1,
                                          uint32_t& r2, uint32_t& r3, uint32_t a) {
    asm volatile("ldmatrix.sync.aligned.m8n8.x4.trans.shared.b16 {%0,%1,%2,%3}, [%4];\n"
                 : "=r"(r0), "=r"(r1), "=r"(r2), "=r"(r3) : "r"(a));
}
__device__ __forceinline__ void mma16816(float c[4], const uint32_t a[4],
                                         const uint32_t b[2]) {
    asm volatile(
        "mma.sync.aligned.m16n8k16.row.col.f32.f16.f16.f32 "
        "{%0,%1,%2,%3}, {%4,%5,%6,%7}, {%8,%9}, {%0,%1,%2,%3};\n"
        : "+f"(c[0]), "+f"(c[1]), "+f"(c[2]), "+f"(c[3])
        : "r"(a[0]), "r"(a[1]), "r"(a[2]), "r"(a[3]), "r"(b[0]), "r"(b[1]));
}
__device__ __forceinline__ void mma2(float c[4], const uint32_t a[4],
                                     uint32_t b0, uint32_t b1) {
    asm volatile(
        "mma.sync.aligned.m16n8k16.row.col.f32.f16.f16.f32 "
        "{%0,%1,%2,%3}, {%4,%5,%6,%7}, {%8,%9}, {%0,%1,%2,%3};\n"
        : "+f"(c[0]), "+f"(c[1]), "+f"(c[2]), "+f"(c[3])
        : "r"(a[0]), "r"(a[1]), "r"(a[2]), "r"(a[3]), "r"(b0), "r"(b1));
}
__device__ __forceinline__ uint32_t pkh2(__half a, __half b) {
    __half2 t = __halves2half2(a, b);
    return *reinterpret_cast<uint32_t*>(&t);
}
#define CP16(dst, src) \
    asm volatile("cp.async.cg.shared.global [%0], [%1], 16;\n" :: "r"(dst), "l"(src))
#define CPCOMMIT() asm volatile("cp.async.commit_group;\n")
#define CPWAIT0()  asm volatile("cp.async.wait_group 0;\n")

// ---------------------------------------------------------------------------
// Tensor-core GEMM with fp16 2-term split (3 MMA passes ~= fp32 accuracy).
// QKV=true epilogue: q-scale + interleaved RoPE, write hi/lo halves to
// g_{q,k,v}{h,l} (pre-split for the attention kernel).
// ---------------------------------------------------------------------------
template<int NC, bool QKV>
__global__ __launch_bounds__(256) void gemm_mma(const float* __restrict__ Ag,
                                                const float* __restrict__ Bg,
                                                float* __restrict__ Og) {
    constexpr int KD  = 512;
    constexpr int AST = 40;
    constexpr int BST = 136;
    __shared__ __align__(16) __half Ah[128 * AST];
    __shared__ __align__(16) __half Al[128 * AST];
    __shared__ __align__(16) __half Bh[32 * BST];
    __shared__ __align__(16) __half Bl[32 * BST];

    const int tid  = threadIdx.x;
    const int lane = tid & 31;
    const int wid  = tid >> 5;
    const int wm   = wid >> 2;
    const int wn   = wid & 3;
    const int row0 = blockIdx.y * 128;
    const int col0 = blockIdx.x * 128;

    const float* Asrc = QKV ? Ag : g_ao;

    float C[4][4][4];
#pragma unroll
    for (int i = 0; i < 4; i++)
#pragma unroll
        for (int j = 0; j < 4; j++)
#pragma unroll
            for (int e = 0; e < 4; e++) C[i][j][e] = 0.f;

    const int ar = tid >> 1,  ac = (tid & 1) * 16;
    const int br = tid >> 3,  bc = (tid & 7) * 16;
    const int lrow = lane & 15;
    const int lko  = (lane >> 4) * 8;

    for (int kk = 0; kk < KD; kk += 32) {
        __syncthreads();
        {
            const float* src = Asrc + (size_t)(row0 + ar) * KD + kk + ac;
            __half hb[16], lb[16];
#pragma unroll
            for (int q = 0; q < 4; q++) {
                float4 v = *(const float4*)(src + 4 * q);
                float f[4] = {v.x, v.y, v.z, v.w};
#pragma unroll
                for (int e = 0; e < 4; e++) {
                    __half h = __float2half_rn(f[e]);
                    hb[4*q+e] = h;
                    lb[4*q+e] = __float2half_rn(f[e] - __half2float(h));
                }
            }
            *(uint4*)&Ah[ar*AST + ac]     = *(const uint4*)&hb[0];
            *(uint4*)&Ah[ar*AST + ac + 8] = *(const uint4*)&hb[8];
            *(uint4*)&Al[ar*AST + ac]     = *(const uint4*)&lb[0];
            *(uint4*)&Al[ar*AST + ac + 8] = *(const uint4*)&lb[8];
        }
        {
            const float* src = Bg + (size_t)(kk + br) * NC + col0 + bc;
            __half hb[16], lb[16];
#pragma unroll
            for (int q = 0; q < 4; q++) {
                float4 v = *(const float4*)(src + 4 * q);
                float f[4] = {v.x, v.y, v.z, v.w};
#pragma unroll
                for (int e = 0; e < 4; e++) {
                    __half h = __float2half_rn(f[e]);
                    hb[4*q+e] = h;
                    lb[4*q+e] = __float2half_rn(f[e] - __half2float(h));
                }
            }
            *(uint4*)&Bh[br*BST + bc]     = *(const uint4*)&hb[0];
            *(uint4*)&Bh[br*BST + bc + 8] = *(const uint4*)&hb[8];
            *(uint4*)&Bl[br*BST + bc]     = *(const uint4*)&lb[0];
            *(uint4*)&Bl[br*BST + bc + 8] = *(const uint4*)&lb[8];
        }
        __syncthreads();

#pragma unroll
        for (int kq = 0; kq < 32; kq += 16) {
            uint32_t aH[4][4], aL[4][4];
#pragma unroll
            for (int mt = 0; mt < 4; mt++) {
                int r = wm * 64 + mt * 16 + lrow;
                ldsm_x4(aH[mt][0], aH[mt][1], aH[mt][2], aH[mt][3],
                        smem_u32(&Ah[r * AST + kq + lko]));
                ldsm_x4(aL[mt][0], aL[mt][1], aL[mt][2], aL[mt][3],
                        smem_u32(&Al[r * AST + kq + lko]));
            }
#pragma unroll
            for (int ng = 0; ng < 2; ng++) {
                uint32_t bH[4], bL[4];
                int rr = kq + lrow;
                int cb = wn * 32 + ng * 16 + lko;
                ldsm_x4_t(bH[0], bH[1], bH[2], bH[3], smem_u32(&Bh[rr * BST + cb]));
                ldsm_x4_t(bL[0], bL[1], bL[2], bL[3], smem_u32(&Bl[rr * BST + cb]));
#pragma unroll
                for (int mt = 0; mt < 4; mt++) {
                    mma16816(C[mt][ng*2],     aH[mt], &bH[0]);
                    mma16816(C[mt][ng*2],     aH[mt], &bL[0]);
                    mma16816(C[mt][ng*2],     aL[mt], &bH[0]);
                    mma16816(C[mt][ng*2 + 1], aH[mt], &bH[2]);
                    mma16816(C[mt][ng*2 + 1], aH[mt], &bL[2]);
                    mma16816(C[mt][ng*2 + 1], aL[mt], &bH[2]);
                }
            }
        }
    }

    const int g  = lane >> 2;
    const int cc = (lane & 3) * 2;
    if (QKV) {
        const int sec     = col0 >> 9;
        const int rembase = (col0 & 511) + wn * 32;
        __half* dsth = (sec == 0) ? g_qh : (sec == 1 ? g_kh : g_vh);
        __half* dstl = (sec == 0) ? g_ql : (sec == 1 ? g_kl : g_vl);
        const float LOG2B = 13.287712379549449f;
#pragma unroll
        for (int nt = 0; nt < 4; nt++) {
            int rem   = rembase + nt * 8 + cc;
            int h     = rem >> 6;
            int dbase = rem & 63;
            float ifr = exp2f(-(float)dbase * (LOG2B / 64.f));
#pragma unroll
            for (int mt = 0; mt < 4; mt++) {
#pragma unroll
                for (int hf = 0; hf < 2; hf++) {
                    int R = row0 + wm * 64 + mt * 16 + g + hf * 8;
                    int b = R >> 10, n = R & 1023;
                    float v0 = C[mt][nt][hf*2 + 0];
                    float v1 = C[mt][nt][hf*2 + 1];
                    if (sec == 0) { v0 *= 0.125f; v1 *= 0.125f; }
                    if (sec < 2) {
                        float s, co;
                        sincosf((float)n * ifr, &s, &co);
                        float t0 = v0 * co - v1 * s;
                        float t1 = v1 * co + v0 * s;
                        v0 = t0; v1 = t1;
                    }
                    size_t idx = (((size_t)b * NH + h) * NSEQ + n) * HD + dbase;
                    __half h0 = __float2half_rn(v0), h1 = __float2half_rn(v1);
                    *(__half2*)&dsth[idx] = __halves2half2(h0, h1);
                    *(__half2*)&dstl[idx] = __halves2half2(
                        __float2half_rn(v0 - __half2float(h0)),
                        __float2half_rn(v1 - __half2float(h1)));
                }
            }
        }
    } else {
#pragma unroll
        for (int nt = 0; nt < 4; nt++) {
            int colg = col0 + wn * 32 + nt * 8 + cc;
#pragma unroll
            for (int mt = 0; mt < 4; mt++) {
#pragma unroll
                for (int hf = 0; hf < 2; hf++) {
                    int R = row0 + wm * 64 + mt * 16 + g + hf * 8;
                    *(float2*)&Og[(size_t)R * NC + colg] =
                        make_float2(C[mt][nt][hf*2], C[mt][nt][hf*2 + 1]);
                }
            }
        }
    }
}

// ---------------------------------------------------------------------------
// Flash attention, fp16-split operands pre-staged in gmem.
// Block: 128 Q-rows x one (b,h), 8 warps. Q frags resident in registers.
// K/V double-buffered via cp.async (2 stages x {Kh,Kl,Vh,Vl}[64x72]).
// PV uses Ph*Vh + Ph*Vl (Pl*Vh dropped: |Pl|<=2^-11*P -> ~5e-4 pre-projection).
// ---------------------------------------------------------------------------
#define QST 72
#define STAGE_H (4 * 64 * QST)          // halves per stage (Kh,Kl,Vh,Vl)
#define ATTN_SMEM (2 * STAGE_H * 2)     // 73728 bytes

__global__ __launch_bounds__(256, 1) void k_attn_mma(const float* __restrict__ bias) {
    extern __shared__ __half sm[];

    const int b  = blockIdx.x;      // fastest: batches share bias slice in L2
    const int h  = blockIdx.y;
    const int i0 = blockIdx.z * 128;
    const int tid = threadIdx.x, lane = tid & 31, w = tid >> 5;
    const int lrow = lane & 15, lko = (lane >> 4) * 8;
    const int g = lane >> 2, c2 = (lane & 3) * 2;

    const size_t bh = (size_t)(b * NH + h) * NSEQ * HD;
    const __half* kv_src[4] = {g_kh + bh, g_kl + bh, g_vh + bh, g_vl + bh};
    const float* bg = bias + (size_t)h * NSEQ * NSEQ;

    // ---- stage Q (hi -> stage0 area, lo -> stage1 area), extract frags ----
    {
        const __half* qh = g_qh + bh;
        const __half* ql = g_ql + bh;
#pragma unroll
        for (int i = 0; i < 8; i++) {
            int cid = tid + 256 * i;            // 2048 chunks: 2 arr x 128 r x 8 ch
            int arr = cid >> 10;
            int rem = cid & 1023;
            int row = rem >> 3, ch = rem & 7;
            const __half* src = (arr ? ql : qh) + (size_t)(i0 + row) * HD + ch * 8;
            CP16(smem_u32(&sm[arr * STAGE_H + row * QST + ch * 8]), src);
        }
        CPCOMMIT();
        CPWAIT0();
        __syncthreads();
    }
    uint32_t qH[4][4], qL[4][4];
#pragma unroll
    for (int ks = 0; ks < 4; ks++) {
        ldsm_x4(qH[ks][0], qH[ks][1], qH[ks][2], qH[ks][3],
                smem_u32(&sm[(w*16 + lrow)*QST + ks*16 + lko]));
        ldsm_x4(qL[ks][0], qL[ks][1], qL[ks][2], qL[ks][3],
                smem_u32(&sm[STAGE_H + (w*16 + lrow)*QST + ks*16 + lko]));
    }
    __syncthreads();

    // ---- prefetch K/V stage 0 (jt = 0) ----
#pragma unroll
    for (int i = 0; i < 8; i++) {
        int cid = tid + 256 * i;                // 2048 chunks: 4 arr x 64 r x 8 ch
        int arr = cid >> 9;
        int rem = cid & 511;
        int row = rem >> 3, ch = rem & 7;
        CP16(smem_u32(&sm[arr * 64 * QST + row * QST + ch * 8]),
             kv_src[arr] + (size_t)row * HD + ch * 8);
    }
    CPCOMMIT();

    float Of[8][4];
#pragma unroll
    for (int nt = 0; nt < 8; nt++)
#pragma unroll
        for (int e = 0; e < 4; e++) Of[nt][e] = 0.f;
    float m0 = -INFINITY, m1 = -INFINITY, l0 = 0.f, l1 = 0.f;
    const int r0g = i0 + w * 16 + g;

    for (int jt = 0; jt < 16; jt++) {
        CPWAIT0();
        __syncthreads();
        if (jt < 15) {   // prefetch next tile into the other stage
            int j0n = (jt + 1) * 64;
            const int sb = ((jt + 1) & 1) * STAGE_H;
#pragma unroll
            for (int i = 0; i < 8; i++) {
                int cid = tid + 256 * i;
                int arr = cid >> 9;
                int rem = cid & 511;
                int row = rem >> 3, ch = rem & 7;
                CP16(smem_u32(&sm[sb + arr * 64 * QST + row * QST + ch * 8]),
                     kv_src[arr] + (size_t)(j0n + row) * HD + ch * 8);
            }
            CPCOMMIT();
        }
        const __half* st = sm + (jt & 1) * STAGE_H;
        const int j0 = jt * 64;

        // bias prefetch (long-latency LDGs issued before the MMA burst)
        float2 bu[8], bw[8];
        {
            const float* bp0 = bg + (size_t)r0g * NSEQ + j0 + c2;
            const float* bp1 = bp0 + 8 * NSEQ;
#pragma unroll
            for (int nt = 0; nt < 8; nt++) {
                bu[nt] = *(const float2*)(bp0 + nt * 8);
                bw[nt] = *(const float2*)(bp1 + nt * 8);
            }
        }

        // ---- S = Q K^T ----
        float Sf[8][4];
#pragma unroll
        for (int nt = 0; nt < 8; nt++)
#pragma unroll
            for (int e = 0; e < 4; e++) Sf[nt][e] = 0.f;
#pragma unroll
        for (int ks = 0; ks < 4; ks++) {
#pragma unroll
            for (int ng = 0; ng < 4; ng++) {
                uint32_t kh_[4], kl_[4];
                ldsm_x4(kh_[0], kh_[1], kh_[2], kh_[3],
                        smem_u32(&st[(ng*16 + lrow)*QST + ks*16 + lko]));
                ldsm_x4(kl_[0], kl_[1], kl_[2], kl_[3],
                        smem_u32(&st[64*QST + (ng*16 + lrow)*QST + ks*16 + lko]));
                mma2(Sf[2*ng],   qH[ks], kh_[0], kh_[2]);
                mma2(Sf[2*ng],   qH[ks], kl_[0], kl_[2]);
                mma2(Sf[2*ng],   qL[ks], kh_[0], kh_[2]);
                mma2(Sf[2*ng+1], qH[ks], kh_[1], kh_[3]);
                mma2(Sf[2*ng+1], qH[ks], kl_[1], kl_[3]);
                mma2(Sf[2*ng+1], qL[ks], kh_[1], kh_[3]);
            }
        }
#pragma unroll
        for (int nt = 0; nt < 8; nt++) {
            Sf[nt][0] += bu[nt].x; Sf[nt][1] += bu[nt].y;
            Sf[nt][2] += bw[nt].x; Sf[nt][3] += bw[nt].y;
        }

        // ---- online softmax ----
        float mx0 = -INFINITY, mx1 = -INFINITY;
#pragma unroll
        for (int nt = 0; nt < 8; nt++) {
            mx0 = fmaxf(mx0, fmaxf(Sf[nt][0], Sf[nt][1]));
            mx1 = fmaxf(mx1, fmaxf(Sf[nt][2], Sf[nt][3]));
        }
        mx0 = fmaxf(mx0, __shfl_xor_sync(0xffffffffu, mx0, 1));
        mx0 = fmaxf(mx0, __shfl_xor_sync(0xffffffffu, mx0, 2));
        mx1 = fmaxf(mx1, __shfl_xor_sync(0xffffffffu, mx1, 1));
        mx1 = fmaxf(mx1, __shfl_xor_sync(0xffffffffu, mx1, 2));
        float mn0 = fmaxf(m0, mx0), mn1 = fmaxf(m1, mx1);
        float rs0 = __expf(m0 - mn0), rs1 = __expf(m1 - mn1);
        m0 = mn0; m1 = mn1;

        uint32_t pH0[8], pH1[8];
        float s0 = 0.f, s1 = 0.f;
#pragma unroll
        for (int nt = 0; nt < 8; nt++) {
            float p0 = __expf(Sf[nt][0] - mn0);
            float p1 = __expf(Sf[nt][1] - mn0);
            float p2 = __expf(Sf[nt][2] - mn1);
            float p3 = __expf(Sf[nt][3] - mn1);
            s0 += p0 + p1; s1 += p2 + p3;
            pH0[nt] = pkh2(__float2half_rn(p0), __float2half_rn(p1));
            pH1[nt] = pkh2(__float2half_rn(p2), __float2half_rn(p3));
        }
        s0 += __shfl_xor_sync(0xffffffffu, s0, 1);
        s0 += __shfl_xor_sync(0xffffffffu, s0, 2);
        s1 += __shfl_xor_sync(0xffffffffu, s1, 1);
        s1 += __shfl_xor_sync(0xffffffffu, s1, 2);
        l0 = l0 * rs0 + s0;
        l1 = l1 * rs1 + s1;
#pragma unroll
        for (int nt = 0; nt < 8; nt++) {
            Of[nt][0] *= rs0; Of[nt][1] *= rs0;
            Of[nt][2] *= rs1; Of[nt][3] *= rs1;
        }

        // ---- O += P V ----
#pragma unroll
        for (int ks = 0; ks < 4; ks++) {
            uint32_t aH[4] = {pH0[2*ks], pH1[2*ks], pH0[2*ks+1], pH1[2*ks+1]};
#pragma unroll
            for (int dg = 0; dg < 4; dg++) {
                uint32_t vh_[4], vl_[4];
                ldsm_x4_t(vh_[0], vh_[1], vh_[2], vh_[3],
                          smem_u32(&st[2*64*QST + (ks*16 + lrow)*QST + dg*16 + lko]));
                ldsm_x4_t(vl_[0], vl_[1], vl_[2], vl_[3],
                          smem_u32(&st[3*64*QST + (ks*16 + lrow)*QST + dg*16 + lko]));
                mma2(Of[2*dg],   aH, vh_[0], vh_[1]);
                mma2(Of[2*dg],   aH, vl_[0], vl_[1]);
                mma2(Of[2*dg+1], aH, vh_[2], vh_[3]);
                mma2(Of[2*dg+1], aH, vl_[2], vl_[3]);
            }
        }
    }

    // ---- normalize + store to g_ao [B,N,H*D] ----
    {
        float inv0 = 1.f / l0, inv1 = 1.f / l1;
        float* o0 = g_ao + ((size_t)b * NSEQ + r0g) * DIMM + h * HD + c2;
        float* o1 = o0 + 8 * DIMM;
#pragma unroll
        for (int nt = 0; nt < 8; nt++) {
            *(float2*)(o0 + nt * 8) = make_float2(Of[nt][0] * inv0, Of[nt][1] * inv0);
            *(float2*)(o1 + nt * 8) = make_float2(Of[nt][2] * inv1, Of[nt][3] * inv1);
        }
    }
}

// ---------------------------------------------------------------------------
extern "C" void kernel_launch(void* const* d_in, const int* in_sizes, int n_in,
                              void* d_out, int out_size) {
    const float *x = nullptr, *pb = nullptr, *wq = nullptr, *wo = nullptr;
    for (int i = 0; i < n_in; i++) {
        switch (in_sizes[i]) {
            case 4194304: x  = (const float*)d_in[i]; break;  // x [8,1024,512]
            case 8388608: pb = (const float*)d_in[i]; break;  // pos_bias [8,1024,1024]
            case 786432:  wq = (const float*)d_in[i]; break;  // w_qkv [512,1536]
            case 262144:  wo = (const float*)d_in[i]; break;  // w_out [512,512]
        }
    }
    if (!x)  x  = (const float*)d_in[0];
    if (!pb) pb = (const float*)d_in[1];
    if (!wq) wq = (const float*)d_in[2];
    if (!wo) wo = (const float*)d_in[3];

    cudaFuncSetAttribute(k_attn_mma, cudaFuncAttributeMaxDynamicSharedMemorySize,
                         ATTN_SMEM);

    gemm_mma<COLS3, true><<<dim3(12, 64), 256>>>(x, wq, nullptr);
    k_attn_mma<<<dim3(BSZ, NH, 8), 256, ATTN_SMEM>>>(pb);
    gemm_mma<DIMM, false><<<dim3(4, 64), 256>>>(nullptr, wo, (float*)d_out);
}

// round 6
// speedup vs baseline: 2.5619x; 1.0370x over previous
#include <cuda_runtime.h>
#include <cuda_fp16.h>
#include <math.h>
#include <stdint.h>

#define BSZ   8
#define NSEQ  1024
#define DIMM  512
#define NH    8
#define HD    64
#define COLS3 1536
#define MROWS (BSZ*NSEQ)

// Pre-split hi/lo half operands (device globals; no runtime allocation)
__device__ __align__(16) __half g_xh[MROWS*DIMM],  g_xl[MROWS*DIMM];
__device__ __align__(16) __half g_wqh[DIMM*COLS3], g_wql[DIMM*COLS3];
__device__ __align__(16) __half g_woh[DIMM*DIMM],  g_wol[DIMM*DIMM];
__device__ __align__(16) __half g_qh[MROWS*DIMM],  g_ql[MROWS*DIMM];
__device__ __align__(16) __half g_kh[MROWS*DIMM],  g_kl[MROWS*DIMM];
__device__ __align__(16) __half g_vh[MROWS*DIMM],  g_vl[MROWS*DIMM];
__device__ __align__(16) __half g_aoh[MROWS*DIMM], g_aol[MROWS*DIMM];

// ---------------------------------------------------------------------------
// helpers
// ---------------------------------------------------------------------------
__device__ __forceinline__ uint32_t smem_u32(const void* p) {
    return (uint32_t)__cvta_generic_to_shared(p);
}
__device__ __forceinline__ void ldsm_x4(uint32_t& r0, uint32_t& r1,
                                        uint32_t& r2, uint32_t& r3, uint32_t a) {
    asm volatile("ldmatrix.sync.aligned.m8n8.x4.shared.b16 {%0,%1,%2,%3}, [%4];\n"
                 : "=r"(r0), "=r"(r1), "=r"(r2), "=r"(r3) : "r"(a));
}
__device__ __forceinline__ void ldsm_x4_t(uint32_t& r0, uint32_t& r1,
                                          uint32_t& r2, uint32_t& r3, uint32_t a) {
    asm volatile("ldmatrix.sync.aligned.m8n8.x4.trans.shared.b16 {%0,%1,%2,%3}, [%4];\n"
                 : "=r"(r0), "=r"(r1), "=r"(r2), "=r"(r3) : "r"(a));
}
__device__ __forceinline__ void mma2(float c[4], const uint32_t a[4],
                                     uint32_t b0, uint32_t b1) {
    asm volatile(
        "mma.sync.aligned.m16n8k16.row.col.f32.f16.f16.f32 "
        "{%0,%1,%2,%3}, {%4,%5,%6,%7}, {%8,%9}, {%0,%1,%2,%3};\n"
        : "+f"(c[0]), "+f"(c[1]), "+f"(c[2]), "+f"(c[3])
        : "r"(a[0]), "r"(a[1]), "r"(a[2]), "r"(a[3]), "r"(b0), "r"(b1));
}
__device__ __forceinline__ uint32_t pkh2(__half a, __half b) {
    __half2 t = __halves2half2(a, b);
    return *reinterpret_cast<uint32_t*>(&t);
}
#define CP16(dst, src) \
    asm volatile("cp.async.cg.shared.global [%0], [%1], 16;\n" :: "r"(dst), "l"(src))
#define CPCOMMIT() asm volatile("cp.async.commit_group;\n")
#define CPWAIT0()  asm volatile("cp.async.wait_group 0;\n")

// ---------------------------------------------------------------------------
// Elementwise fp32 -> (hi, lo) fp16 split. SEL picks destination globals
// (0: x, 1: w_qkv, 2: w_out) so no host-resolved device pointers are needed.
// ---------------------------------------------------------------------------
template<int SEL>
__global__ __launch_bounds__(256) void k_split(const float* __restrict__ s, int n4) {
    __half* hi = (SEL == 0) ? g_xh : (SEL == 1 ? g_wqh : g_woh);
    __half* lo = (SEL == 0) ? g_xl : (SEL == 1 ? g_wql : g_wol);
    int i = blockIdx.x * blockDim.x + threadIdx.x;
    if (i >= n4) return;
    float4 v = ((const float4*)s)[i];
    float f[4] = {v.x, v.y, v.z, v.w};
    __half h[4], l[4];
#pragma unroll
    for (int e = 0; e < 4; e++) {
        h[e] = __float2half_rn(f[e]);
        l[e] = __float2half_rn(f[e] - __half2float(h[e]));
    }
    ((uint2*)hi)[i] = *(const uint2*)h;
    ((uint2*)lo)[i] = *(const uint2*)l;
}

// ---------------------------------------------------------------------------
// Pipelined tensor-core GEMM, pre-split hi/lo operands, 3-pass fp16 split.
// C[8192 x NC] = A[8192 x 512] * B[512 x NC]
// Block 128x128, 8 warps (2x4), warp tile 64x32, KC=32, cp.async double-buffer.
// QKV=true: A = g_x*, B = g_wq*; epilogue q-scale + RoPE -> split q/k/v.
// QKV=false: A = g_ao*, B = g_wo*; plain fp32 store to Og.
// ---------------------------------------------------------------------------
#define AST 40
#define BST 136
#define G_ASTAGE (128*AST)            // halves, one array
#define G_BSTAGE (32*BST)
#define G_STAGE  (2*G_ASTAGE + 2*G_BSTAGE)   // 18944 halves = 37888 B
#define GEMM_SMEM (2 * G_STAGE * 2)          // 75776 B

template<int NC, bool QKV>
__global__ __launch_bounds__(256, 2) void gemm_mma(float* __restrict__ Og) {
    constexpr int KD = 512;
    extern __shared__ __half sg[];

    const int tid  = threadIdx.x;
    const int lane = tid & 31;
    const int wid  = tid >> 5;
    const int wm   = wid >> 2;
    const int wn   = wid & 3;
    const int row0 = blockIdx.y * 128;
    const int col0 = blockIdx.x * 128;
    const int lrow = lane & 15;
    const int lko  = (lane >> 4) * 8;

    float C[4][4][4];
#pragma unroll
    for (int i = 0; i < 4; i++)
#pragma unroll
        for (int j = 0; j < 4; j++)
#pragma unroll
            for (int e = 0; e < 4; e++) C[i][j][e] = 0.f;

    const __half* asrc[2] = {QKV ? g_xh : g_aoh, QKV ? g_xl : g_aol};
    const __half* bsrc[2] = {QKV ? g_wqh : g_woh, QKV ? g_wql : g_wol};

    // prefetch (stage base, k-offset): 8 chunks of 16B per thread
    auto prefetch = [&](int sbase, int kk) {
#pragma unroll
        for (int i = 0; i < 4; i++) {          // A: 1024 chunks
            int cid = tid + 256 * i;
            int arr = cid >> 9, rem = cid & 511;
            int row = rem >> 2, ch = rem & 3;
            CP16(smem_u32(&sg[sbase + arr * G_ASTAGE + row * AST + ch * 8]),
                 asrc[arr] + (size_t)(row0 + row) * KD + kk + ch * 8);
        }
#pragma unroll
        for (int i = 0; i < 4; i++) {          // B: 1024 chunks
            int cid = tid + 256 * i;
            int arr = cid >> 9, rem = cid & 511;
            int row = rem >> 4, ch = rem & 15;
            CP16(smem_u32(&sg[sbase + 2 * G_ASTAGE + arr * G_BSTAGE + row * BST + ch * 8]),
                 bsrc[arr] + (size_t)(kk + row) * NC + col0 + ch * 8);
        }
        CPCOMMIT();
    };

    prefetch(0, 0);

    for (int kc = 0; kc < KD / 32; kc++) {
        CPWAIT0();
        __syncthreads();
        if (kc + 1 < KD / 32) prefetch(((kc + 1) & 1) * G_STAGE, (kc + 1) * 32);

        const __half* Ahs = sg + (kc & 1) * G_STAGE;
        const __half* Als = Ahs + G_ASTAGE;
        const __half* Bhs = Als + G_ASTAGE;
        const __half* Bls = Bhs + G_BSTAGE;

#pragma unroll
        for (int kq = 0; kq < 32; kq += 16) {
            uint32_t aH[4][4], aL[4][4];
#pragma unroll
            for (int mt = 0; mt < 4; mt++) {
                int r = wm * 64 + mt * 16 + lrow;
                ldsm_x4(aH[mt][0], aH[mt][1], aH[mt][2], aH[mt][3],
                        smem_u32(&Ahs[r * AST + kq + lko]));
                ldsm_x4(aL[mt][0], aL[mt][1], aL[mt][2], aL[mt][3],
                        smem_u32(&Als[r * AST + kq + lko]));
            }
#pragma unroll
            for (int ng = 0; ng < 2; ng++) {
                uint32_t bH[4], bL[4];
                int rr = kq + lrow;
                int cb = wn * 32 + ng * 16 + lko;
                ldsm_x4_t(bH[0], bH[1], bH[2], bH[3], smem_u32(&Bhs[rr * BST + cb]));
                ldsm_x4_t(bL[0], bL[1], bL[2], bL[3], smem_u32(&Bls[rr * BST + cb]));
#pragma unroll
                for (int mt = 0; mt < 4; mt++) {
                    mma2(C[mt][ng*2],     aH[mt], bH[0], bH[1]);
                    mma2(C[mt][ng*2],     aH[mt], bL[0], bL[1]);
                    mma2(C[mt][ng*2],     aL[mt], bH[0], bH[1]);
                    mma2(C[mt][ng*2 + 1], aH[mt], bH[2], bH[3]);
                    mma2(C[mt][ng*2 + 1], aH[mt], bL[2], bL[3]);
                    mma2(C[mt][ng*2 + 1], aL[mt], bH[2], bH[3]);
                }
            }
        }
        __syncthreads();
    }

    const int g  = lane >> 2;
    const int cc = (lane & 3) * 2;
    if (QKV) {
        const int sec     = col0 >> 9;
        const int rembase = (col0 & 511) + wn * 32;
        __half* dsth = (sec == 0) ? g_qh : (sec == 1 ? g_kh : g_vh);
        __half* dstl = (sec == 0) ? g_ql : (sec == 1 ? g_kl : g_vl);
        const float LOG2B = 13.287712379549449f;
#pragma unroll
        for (int nt = 0; nt < 4; nt++) {
            int rem   = rembase + nt * 8 + cc;
            int h     = rem >> 6;
            int dbase = rem & 63;
            float ifr = exp2f(-(float)dbase * (LOG2B / 64.f));
#pragma unroll
            for (int mt = 0; mt < 4; mt++) {
#pragma unroll
                for (int hf = 0; hf < 2; hf++) {
                    int R = row0 + wm * 64 + mt * 16 + g + hf * 8;
                    int b = R >> 10, n = R & 1023;
                    float v0 = C[mt][nt][hf*2 + 0];
                    float v1 = C[mt][nt][hf*2 + 1];
                    if (sec == 0) { v0 *= 0.125f; v1 *= 0.125f; }
                    if (sec < 2) {
                        float s, co;
                        sincosf((float)n * ifr, &s, &co);
                        float t0 = v0 * co - v1 * s;
                        float t1 = v1 * co + v0 * s;
                        v0 = t0; v1 = t1;
                    }
                    size_t idx = (((size_t)b * NH + h) * NSEQ + n) * HD + dbase;
                    __half h0 = __float2half_rn(v0), h1 = __float2half_rn(v1);
                    *(__half2*)&dsth[idx] = __halves2half2(h0, h1);
                    *(__half2*)&dstl[idx] = __halves2half2(
                        __float2half_rn(v0 - __half2float(h0)),
                        __float2half_rn(v1 - __half2float(h1)));
                }
            }
        }
    } else {
#pragma unroll
        for (int nt = 0; nt < 4; nt++) {
            int colg = col0 + wn * 32 + nt * 8 + cc;
#pragma unroll
            for (int mt = 0; mt < 4; mt++) {
#pragma unroll
                for (int hf = 0; hf < 2; hf++) {
                    int R = row0 + wm * 64 + mt * 16 + g + hf * 8;
                    *(float2*)&Og[(size_t)R * NC + colg] =
                        make_float2(C[mt][nt][hf*2], C[mt][nt][hf*2 + 1]);
                }
            }
        }
    }
}

// ---------------------------------------------------------------------------
// Flash attention (R4 structure), epilogue writes split O to g_aoh/g_aol.
// ---------------------------------------------------------------------------
#define QST 72
#define STAGE_H (4 * 64 * QST)
#define ATTN_SMEM (2 * STAGE_H * 2)

__global__ __launch_bounds__(256, 1) void k_attn_mma(const float* __restrict__ bias) {
    extern __shared__ __half sm[];

    const int b  = blockIdx.x;
    const int h  = blockIdx.y;
    const int i0 = blockIdx.z * 128;
    const int tid = threadIdx.x, lane = tid & 31, w = tid >> 5;
    const int lrow = lane & 15, lko = (lane >> 4) * 8;
    const int g = lane >> 2, c2 = (lane & 3) * 2;

    const size_t bh = (size_t)(b * NH + h) * NSEQ * HD;
    const __half* kv_src[4] = {g_kh + bh, g_kl + bh, g_vh + bh, g_vl + bh};
    const float* bg = bias + (size_t)h * NSEQ * NSEQ;

    {
        const __half* qh = g_qh + bh;
        const __half* ql = g_ql + bh;
#pragma unroll
        for (int i = 0; i < 8; i++) {
            int cid = tid + 256 * i;
            int arr = cid >> 10;
            int rem = cid & 1023;
            int row = rem >> 3, ch = rem & 7;
            const __half* src = (arr ? ql : qh) + (size_t)(i0 + row) * HD + ch * 8;
            CP16(smem_u32(&sm[arr * STAGE_H + row * QST + ch * 8]), src);
        }
        CPCOMMIT();
        CPWAIT0();
        __syncthreads();
    }
    uint32_t qH[4][4], qL[4][4];
#pragma unroll
    for (int ks = 0; ks < 4; ks++) {
        ldsm_x4(qH[ks][0], qH[ks][1], qH[ks][2], qH[ks][3],
                smem_u32(&sm[(w*16 + lrow)*QST + ks*16 + lko]));
        ldsm_x4(qL[ks][0], qL[ks][1], qL[ks][2], qL[ks][3],
                smem_u32(&sm[STAGE_H + (w*16 + lrow)*QST + ks*16 + lko]));
    }
    __syncthreads();

#pragma unroll
    for (int i = 0; i < 8; i++) {
        int cid = tid + 256 * i;
        int arr = cid >> 9;
        int rem = cid & 511;
        int row = rem >> 3, ch = rem & 7;
        CP16(smem_u32(&sm[arr * 64 * QST + row * QST + ch * 8]),
             kv_src[arr] + (size_t)row * HD + ch * 8);
    }
    CPCOMMIT();

    float Of[8][4];
#pragma unroll
    for (int nt = 0; nt < 8; nt++)
#pragma unroll
        for (int e = 0; e < 4; e++) Of[nt][e] = 0.f;
    float m0 = -INFINITY, m1 = -INFINITY, l0 = 0.f, l1 = 0.f;
    const int r0g = i0 + w * 16 + g;

    for (int jt = 0; jt < 16; jt++) {
        CPWAIT0();
        __syncthreads();
        if (jt < 15) {
            int j0n = (jt + 1) * 64;
            const int sb = ((jt + 1) & 1) * STAGE_H;
#pragma unroll
            for (int i = 0; i < 8; i++) {
                int cid = tid + 256 * i;
                int arr = cid >> 9;
                int rem = cid & 511;
                int row = rem >> 3, ch = rem & 7;
                CP16(smem_u32(&sm[sb + arr * 64 * QST + row * QST + ch * 8]),
                     kv_src[arr] + (size_t)(j0n + row) * HD + ch * 8);
            }
            CPCOMMIT();
        }
        const __half* st = sm + (jt & 1) * STAGE_H;
        const int j0 = jt * 64;

        float2 bu[8], bw[8];
        {
            const float* bp0 = bg + (size_t)r0g * NSEQ + j0 + c2;
            const float* bp1 = bp0 + 8 * NSEQ;
#pragma unroll
            for (int nt = 0; nt < 8; nt++) {
                bu[nt] = *(const float2*)(bp0 + nt * 8);
                bw[nt] = *(const float2*)(bp1 + nt * 8);
            }
        }

        float Sf[8][4];
#pragma unroll
        for (int nt = 0; nt < 8; nt++)
#pragma unroll
            for (int e = 0; e < 4; e++) Sf[nt][e] = 0.f;
#pragma unroll
        for (int ks = 0; ks < 4; ks++) {
#pragma unroll
            for (int ng = 0; ng < 4; ng++) {
                uint32_t kh_[4], kl_[4];
                ldsm_x4(kh_[0], kh_[1], kh_[2], kh_[3],
                        smem_u32(&st[(ng*16 + lrow)*QST + ks*16 + lko]));
                ldsm_x4(kl_[0], kl_[1], kl_[2], kl_[3],
                        smem_u32(&st[64*QST + (ng*16 + lrow)*QST + ks*16 + lko]));
                mma2(Sf[2*ng],   qH[ks], kh_[0], kh_[2]);
                mma2(Sf[2*ng],   qH[ks], kl_[0], kl_[2]);
                mma2(Sf[2*ng],   qL[ks], kh_[0], kh_[2]);
                mma2(Sf[2*ng+1], qH[ks], kh_[1], kh_[3]);
                mma2(Sf[2*ng+1], qH[ks], kl_[1], kl_[3]);
                mma2(Sf[2*ng+1], qL[ks], kh_[1], kh_[3]);
            }
        }
#pragma unroll
        for (int nt = 0; nt < 8; nt++) {
            Sf[nt][0] += bu[nt].x; Sf[nt][1] += bu[nt].y;
            Sf[nt][2] += bw[nt].x; Sf[nt][3] += bw[nt].y;
        }

        float mx0 = -INFINITY, mx1 = -INFINITY;
#pragma unroll
        for (int nt = 0; nt < 8; nt++) {
            mx0 = fmaxf(mx0, fmaxf(Sf[nt][0], Sf[nt][1]));
            mx1 = fmaxf(mx1, fmaxf(Sf[nt][2], Sf[nt][3]));
        }
        mx0 = fmaxf(mx0, __shfl_xor_sync(0xffffffffu, mx0, 1));
        mx0 = fmaxf(mx0, __shfl_xor_sync(0xffffffffu, mx0, 2));
        mx1 = fmaxf(mx1, __shfl_xor_sync(0xffffffffu, mx1, 1));
        mx1 = fmaxf(mx1, __shfl_xor_sync(0xffffffffu, mx1, 2));
        float mn0 = fmaxf(m0, mx0), mn1 = fmaxf(m1, mx1);
        float rs0 = __expf(m0 - mn0), rs1 = __expf(m1 - mn1);
        m0 = mn0; m1 = mn1;

        uint32_t pH0[8], pH1[8];
        float s0 = 0.f, s1 = 0.f;
#pragma unroll
        for (int nt = 0; nt < 8; nt++) {
            float p0 = __expf(Sf[nt][0] - mn0);
            float p1 = __expf(Sf[nt][1] - mn0);
            float p2 = __expf(Sf[nt][2] - mn1);
            float p3 = __expf(Sf[nt][3] - mn1);
            s0 += p0 + p1; s1 += p2 + p3;
            pH0[nt] = pkh2(__float2half_rn(p0), __float2half_rn(p1));
            pH1[nt] = pkh2(__float2half_rn(p2), __float2half_rn(p3));
        }
        s0 += __shfl_xor_sync(0xffffffffu, s0, 1);
        s0 += __shfl_xor_sync(0xffffffffu, s0, 2);
        s1 += __shfl_xor_sync(0xffffffffu, s1, 1);
        s1 += __shfl_xor_sync(0xffffffffu, s1, 2);
        l0 = l0 * rs0 + s0;
        l1 = l1 * rs1 + s1;
#pragma unroll
        for (int nt = 0; nt < 8; nt++) {
            Of[nt][0] *= rs0; Of[nt][1] *= rs0;
            Of[nt][2] *= rs1; Of[nt][3] *= rs1;
        }

#pragma unroll
        for (int ks = 0; ks < 4; ks++) {
            uint32_t aH[4] = {pH0[2*ks], pH1[2*ks], pH0[2*ks+1], pH1[2*ks+1]};
#pragma unroll
            for (int dg = 0; dg < 4; dg++) {
                uint32_t vh_[4], vl_[4];
                ldsm_x4_t(vh_[0], vh_[1], vh_[2], vh_[3],
                          smem_u32(&st[2*64*QST + (ks*16 + lrow)*QST + dg*16 + lko]));
                ldsm_x4_t(vl_[0], vl_[1], vl_[2], vl_[3],
                          smem_u32(&st[3*64*QST + (ks*16 + lrow)*QST + dg*16 + lko]));
                mma2(Of[2*dg],   aH, vh_[0], vh_[1]);
                mma2(Of[2*dg],   aH, vl_[0], vl_[1]);
                mma2(Of[2*dg+1], aH, vh_[2], vh_[3]);
                mma2(Of[2*dg+1], aH, vl_[2], vl_[3]);
            }
        }
    }

    // ---- normalize + store split O to g_aoh/g_aol [B,N,H*D] ----
    {
        float inv0 = 1.f / l0, inv1 = 1.f / l1;
        size_t base0 = ((size_t)b * NSEQ + r0g) * DIMM + h * HD + c2;
        size_t base1 = base0 + 8 * DIMM;
#pragma unroll
        for (int nt = 0; nt < 8; nt++) {
            float v0 = Of[nt][0] * inv0, v1 = Of[nt][1] * inv0;
            float v2 = Of[nt][2] * inv1, v3 = Of[nt][3] * inv1;
            __half h0 = __float2half_rn(v0), h1 = __float2half_rn(v1);
            __half h2 = __float2half_rn(v2), h3 = __float2half_rn(v3);
            *(__half2*)&g_aoh[base0 + nt*8] = __halves2half2(h0, h1);
            *(__half2*)&g_aol[base0 + nt*8] = __halves2half2(
                __float2half_rn(v0 - __half2float(h0)),
                __float2half_rn(v1 - __half2float(h1)));
            *(__half2*)&g_aoh[base1 + nt*8] = __halves2half2(h2, h3);
            *(__half2*)&g_aol[base1 + nt*8] = __halves2half2(
                __float2half_rn(v2 - __half2float(h2)),
                __float2half_rn(v3 - __half2float(h3)));
        }
    }
}

// ---------------------------------------------------------------------------
extern "C" void kernel_launch(void* const* d_in, const int* in_sizes, int n_in,
                              void* d_out, int out_size) {
    const float *x = nullptr, *pb = nullptr, *wq = nullptr, *wo = nullptr;
    for (int i = 0; i < n_in; i++) {
        switch (in_sizes[i]) {
            case 4194304: x  = (const float*)d_in[i]; break;  // x [8,1024,512]
            case 8388608: pb = (const float*)d_in[i]; break;  // pos_bias [8,1024,1024]
            case 786432:  wq = (const float*)d_in[i]; break;  // w_qkv [512,1536]
            case 262144:  wo = (const float*)d_in[i]; break;  // w_out [512,512]
        }
    }
    if (!x)  x  = (const float*)d_in[0];
    if (!pb) pb = (const float*)d_in[1];
    if (!wq) wq = (const float*)d_in[2];
    if (!wo) wo = (const float*)d_in[3];

    cudaFuncSetAttribute(k_attn_mma, cudaFuncAttributeMaxDynamicSharedMemorySize,
                         ATTN_SMEM);
    cudaFuncSetAttribute(gemm_mma<COLS3, true>,
                         cudaFuncAttributeMaxDynamicSharedMemorySize, GEMM_SMEM);
    cudaFuncSetAttribute(gemm_mma<DIMM, false>,
                         cudaFuncAttributeMaxDynamicSharedMemorySize, GEMM_SMEM);

    k_split<0><<<(MROWS*DIMM/4 + 255)/256, 256>>>(x,  MROWS*DIMM/4);
    k_split<1><<<(DIMM*COLS3/4 + 255)/256, 256>>>(wq, DIMM*COLS3/4);
    k_split<2><<<(DIMM*DIMM/4 + 255)/256, 256>>>(wo, DIMM*DIMM/4);

    gemm_mma<COLS3, true><<<dim3(12, 64), 256, GEMM_SMEM>>>(nullptr);
    k_attn_mma<<<dim3(BSZ, NH, 8), 256, ATTN_SMEM>>>(pb);
    gemm_mma<DIMM, false><<<dim3(4, 64), 256, GEMM_SMEM>>>((float*)d_out);
}

// round 7
// speedup vs baseline: 2.9641x; 1.1570x over previous
#include <cuda_runtime.h>
#include <cuda_fp16.h>
#include <math.h>
#include <stdint.h>

#define BSZ   8
#define NSEQ  1024
#define DIMM  512
#define NH    8
#define HD    64
#define COLS3 1536
#define MROWS (BSZ*NSEQ)

// Pre-split operands. A-side operands (x, attention output) need hi only;
// B-side (weights) and attention inputs q/k/v need hi+lo.
__device__ __align__(16) __half g_xh[MROWS*DIMM];
__device__ __align__(16) __half g_wqh[DIMM*COLS3], g_wql[DIMM*COLS3];
__device__ __align__(16) __half g_woh[DIMM*DIMM],  g_wol[DIMM*DIMM];
__device__ __align__(16) __half g_qh[MROWS*DIMM],  g_ql[MROWS*DIMM];
__device__ __align__(16) __half g_kh[MROWS*DIMM],  g_kl[MROWS*DIMM];
__device__ __align__(16) __half g_vh[MROWS*DIMM],  g_vl[MROWS*DIMM];
__device__ __align__(16) __half g_aoh[MROWS*DIMM];

// ---------------------------------------------------------------------------
// helpers
// ---------------------------------------------------------------------------
__device__ __forceinline__ uint32_t smem_u32(const void* p) {
    return (uint32_t)__cvta_generic_to_shared(p);
}
__device__ __forceinline__ void ldsm_x4(uint32_t& r0, uint32_t& r1,
                                        uint32_t& r2, uint32_t& r3, uint32_t a) {
    asm volatile("ldmatrix.sync.aligned.m8n8.x4.shared.b16 {%0,%1,%2,%3}, [%4];\n"
                 : "=r"(r0), "=r"(r1), "=r"(r2), "=r"(r3) : "r"(a));
}
__device__ __forceinline__ void ldsm_x4_t(uint32_t& r0, uint32_t& r1,
                                          uint32_t& r2, uint32_t& r3, uint32_t a) {
    asm volatile("ldmatrix.sync.aligned.m8n8.x4.trans.shared.b16 {%0,%1,%2,%3}, [%4];\n"
                 : "=r"(r0), "=r"(r1), "=r"(r2), "=r"(r3) : "r"(a));
}
__device__ __forceinline__ void mma2(float c[4], const uint32_t a[4],
                                     uint32_t b0, uint32_t b1) {
    asm volatile(
        "mma.sync.aligned.m16n8k16.row.col.f32.f16.f16.f32 "
        "{%0,%1,%2,%3}, {%4,%5,%6,%7}, {%8,%9}, {%0,%1,%2,%3};\n"
        : "+f"(c[0]), "+f"(c[1]), "+f"(c[2]), "+f"(c[3])
        : "r"(a[0]), "r"(a[1]), "r"(a[2]), "r"(a[3]), "r"(b0), "r"(b1));
}
__device__ __forceinline__ uint32_t pkh2(__half a, __half b) {
    __half2 t = __halves2half2(a, b);
    return *reinterpret_cast<uint32_t*>(&t);
}
#define CP16(dst, src) \
    asm volatile("cp.async.cg.shared.global [%0], [%1], 16;\n" :: "r"(dst), "l"(src))
#define CPCOMMIT() asm volatile("cp.async.commit_group;\n")
#define CPWAIT0()  asm volatile("cp.async.wait_group 0;\n")
#define CPWAIT1()  asm volatile("cp.async.wait_group 1;\n")

// ---------------------------------------------------------------------------
// fp32 -> fp16 split. SEL 0: x (hi only). SEL 1: w_qkv. SEL 2: w_out.
// ---------------------------------------------------------------------------
template<int SEL>
__global__ __launch_bounds__(256) void k_split(const float* __restrict__ s, int n4) {
    __half* hi = (SEL == 0) ? g_xh : (SEL == 1 ? g_wqh : g_woh);
    __half* lo = (SEL == 1) ? g_wql : g_wol;   // unused for SEL==0
    int i = blockIdx.x * blockDim.x + threadIdx.x;
    if (i >= n4) return;
    float4 v = ((const float4*)s)[i];
    float f[4] = {v.x, v.y, v.z, v.w};
    __half h[4], l[4];
#pragma unroll
    for (int e = 0; e < 4; e++) {
        h[e] = __float2half_rn(f[e]);
        l[e] = __float2half_rn(f[e] - __half2float(h[e]));
    }
    ((uint2*)hi)[i] = *(const uint2*)h;
    if (SEL != 0) ((uint2*)lo)[i] = *(const uint2*)l;
}

// ---------------------------------------------------------------------------
// GEMM: C = A * B, A hi-only (2-term split: aH*bH + aH*bL).
// Block 128x128, 8 warps (2x4), KC=32, 3-stage cp.async ring, 2 CTAs/SM.
// ---------------------------------------------------------------------------
#define AST 40
#define BST 136
#define G_ASTAGE (128*AST)                   // 5120 halves
#define G_BSTAGE (32*BST)                    // 4352 halves
#define G_STAGE  (G_ASTAGE + 2*G_BSTAGE)     // 13824 halves = 27648 B
#define GEMM_SMEM (3 * G_STAGE * 2)          // 82944 B

template<int NC, bool QKV>
__global__ __launch_bounds__(256, 2) void gemm_mma(float* __restrict__ Og) {
    constexpr int KD = 512;
    extern __shared__ __half sg[];

    const int tid  = threadIdx.x;
    const int lane = tid & 31;
    const int wid  = tid >> 5;
    const int wm   = wid >> 2;
    const int wn   = wid & 3;
    const int row0 = blockIdx.y * 128;
    const int col0 = blockIdx.x * 128;
    const int lrow = lane & 15;
    const int lko  = (lane >> 4) * 8;

    float C[4][4][4];
#pragma unroll
    for (int i = 0; i < 4; i++)
#pragma unroll
        for (int j = 0; j < 4; j++)
#pragma unroll
            for (int e = 0; e < 4; e++) C[i][j][e] = 0.f;

    const __half* Ahg = QKV ? g_xh : g_aoh;
    const __half* bsrc[2] = {QKV ? g_wqh : g_woh, QKV ? g_wql : g_wol};

    auto prefetch = [&](int sbase, int kk) {
#pragma unroll
        for (int i = 0; i < 2; i++) {          // A: 512 chunks of 16B
            int cid = tid + 256 * i;
            int row = cid >> 2, ch = cid & 3;
            CP16(smem_u32(&sg[sbase + row * AST + ch * 8]),
                 Ahg + (size_t)(row0 + row) * KD + kk + ch * 8);
        }
#pragma unroll
        for (int i = 0; i < 4; i++) {          // Bh+Bl: 1024 chunks
            int cid = tid + 256 * i;
            int arr = cid >> 9, rem = cid & 511;
            int row = rem >> 4, ch = rem & 15;
            CP16(smem_u32(&sg[sbase + G_ASTAGE + arr * G_BSTAGE + row * BST + ch * 8]),
                 bsrc[arr] + (size_t)(kk + row) * NC + col0 + ch * 8);
        }
        CPCOMMIT();
    };

    prefetch(0, 0);
    prefetch(G_STAGE, 32);

    for (int kc = 0; kc < KD / 32; kc++) {
        CPWAIT1();
        __syncthreads();
        if (kc + 2 < KD / 32) prefetch(((kc + 2) % 3) * G_STAGE, (kc + 2) * 32);
        else CPCOMMIT();   // empty group keeps wait_group invariant

        const __half* Ahs = sg + (kc % 3) * G_STAGE;
        const __half* Bhs = Ahs + G_ASTAGE;
        const __half* Bls = Bhs + G_BSTAGE;

#pragma unroll
        for (int kq = 0; kq < 32; kq += 16) {
            uint32_t aH[4][4];
#pragma unroll
            for (int mt = 0; mt < 4; mt++) {
                int r = wm * 64 + mt * 16 + lrow;
                ldsm_x4(aH[mt][0], aH[mt][1], aH[mt][2], aH[mt][3],
                        smem_u32(&Ahs[r * AST + kq + lko]));
            }
#pragma unroll
            for (int ng = 0; ng < 2; ng++) {
                uint32_t bH[4], bL[4];
                int rr = kq + lrow;
                int cb = wn * 32 + ng * 16 + lko;
                ldsm_x4_t(bH[0], bH[1], bH[2], bH[3], smem_u32(&Bhs[rr * BST + cb]));
                ldsm_x4_t(bL[0], bL[1], bL[2], bL[3], smem_u32(&Bls[rr * BST + cb]));
#pragma unroll
                for (int mt = 0; mt < 4; mt++) {
                    mma2(C[mt][ng*2],     aH[mt], bH[0], bH[1]);
                    mma2(C[mt][ng*2],     aH[mt], bL[0], bL[1]);
                    mma2(C[mt][ng*2 + 1], aH[mt], bH[2], bH[3]);
                    mma2(C[mt][ng*2 + 1], aH[mt], bL[2], bL[3]);
                }
            }
        }
    }

    const int g  = lane >> 2;
    const int cc = (lane & 3) * 2;
    if (QKV) {
        const int sec     = col0 >> 9;
        const int rembase = (col0 & 511) + wn * 32;
        __half* dsth = (sec == 0) ? g_qh : (sec == 1 ? g_kh : g_vh);
        __half* dstl = (sec == 0) ? g_ql : (sec == 1 ? g_kl : g_vl);
        const float LOG2B = 13.287712379549449f;
#pragma unroll
        for (int nt = 0; nt < 4; nt++) {
            int rem   = rembase + nt * 8 + cc;
            int h     = rem >> 6;
            int dbase = rem & 63;
            float ifr = exp2f(-(float)dbase * (LOG2B / 64.f));
#pragma unroll
            for (int mt = 0; mt < 4; mt++) {
#pragma unroll
                for (int hf = 0; hf < 2; hf++) {
                    int R = row0 + wm * 64 + mt * 16 + g + hf * 8;
                    int b = R >> 10, n = R & 1023;
                    float v0 = C[mt][nt][hf*2 + 0];
                    float v1 = C[mt][nt][hf*2 + 1];
                    if (sec == 0) { v0 *= 0.125f; v1 *= 0.125f; }
                    if (sec < 2) {
                        float s, co;
                        sincosf((float)n * ifr, &s, &co);
                        float t0 = v0 * co - v1 * s;
                        float t1 = v1 * co + v0 * s;
                        v0 = t0; v1 = t1;
                    }
                    size_t idx = (((size_t)b * NH + h) * NSEQ + n) * HD + dbase;
                    __half h0 = __float2half_rn(v0), h1 = __float2half_rn(v1);
                    *(__half2*)&dsth[idx] = __halves2half2(h0, h1);
                    *(__half2*)&dstl[idx] = __halves2half2(
                        __float2half_rn(v0 - __half2float(h0)),
                        __float2half_rn(v1 - __half2float(h1)));
                }
            }
        }
    } else {
#pragma unroll
        for (int nt = 0; nt < 4; nt++) {
            int colg = col0 + wn * 32 + nt * 8 + cc;
#pragma unroll
            for (int mt = 0; mt < 4; mt++) {
#pragma unroll
                for (int hf = 0; hf < 2; hf++) {
                    int R = row0 + wm * 64 + mt * 16 + g + hf * 8;
                    *(float2*)&Og[(size_t)R * NC + colg] =
                        make_float2(C[mt][nt][hf*2], C[mt][nt][hf*2 + 1]);
                }
            }
        }
    }
}

// ---------------------------------------------------------------------------
// Flash attention: 3-term S, 2-term PV, 3-stage cp.async KV ring.
// Epilogue writes hi-only O (the out-GEMM's A operand is 2-term now).
// ---------------------------------------------------------------------------
#define QST 72
#define STAGE_H (4 * 64 * QST)          // 18432 halves per KV stage
#define ATTN_SMEM (3 * STAGE_H * 2)     // 110592 B

__global__ __launch_bounds__(256, 1) void k_attn_mma(const float* __restrict__ bias) {
    extern __shared__ __half sm[];

    const int b  = blockIdx.x;      // fastest: batches share bias slice in L2
    const int h  = blockIdx.y;
    const int i0 = blockIdx.z * 128;
    const int tid = threadIdx.x, lane = tid & 31, w = tid >> 5;
    const int lrow = lane & 15, lko = (lane >> 4) * 8;
    const int g = lane >> 2, c2 = (lane & 3) * 2;

    const size_t bh = (size_t)(b * NH + h) * NSEQ * HD;
    const __half* kv_src[4] = {g_kh + bh, g_kl + bh, g_vh + bh, g_vl + bh};
    const float* bg = bias + (size_t)h * NSEQ * NSEQ;

    // ---- stage Q (hi -> stage0 area, lo -> stage1 area), extract frags ----
    {
        const __half* qh = g_qh + bh;
        const __half* ql = g_ql + bh;
#pragma unroll
        for (int i = 0; i < 8; i++) {
            int cid = tid + 256 * i;
            int arr = cid >> 10;
            int rem = cid & 1023;
            int row = rem >> 3, ch = rem & 7;
            const __half* src = (arr ? ql : qh) + (size_t)(i0 + row) * HD + ch * 8;
            CP16(smem_u32(&sm[arr * STAGE_H + row * QST + ch * 8]), src);
        }
        CPCOMMIT();
        CPWAIT0();
        __syncthreads();
    }
    uint32_t qH[4][4], qL[4][4];
#pragma unroll
    for (int ks = 0; ks < 4; ks++) {
        ldsm_x4(qH[ks][0], qH[ks][1], qH[ks][2], qH[ks][3],
                smem_u32(&sm[(w*16 + lrow)*QST + ks*16 + lko]));
        ldsm_x4(qL[ks][0], qL[ks][1], qL[ks][2], qL[ks][3],
                smem_u32(&sm[STAGE_H + (w*16 + lrow)*QST + ks*16 + lko]));
    }
    __syncthreads();

    // KV tile loader: 2048 chunks of 16B -> stage sbase
    auto kvload = [&](int sbase, int j0) {
#pragma unroll
        for (int i = 0; i < 8; i++) {
            int cid = tid + 256 * i;
            int arr = cid >> 9;
            int rem = cid & 511;
            int row = rem >> 3, ch = rem & 7;
            CP16(smem_u32(&sm[sbase + arr * 64 * QST + row * QST + ch * 8]),
                 kv_src[arr] + (size_t)(j0 + row) * HD + ch * 8);
        }
        CPCOMMIT();
    };

    kvload(0, 0);
    kvload(STAGE_H, 64);

    float Of[8][4];
#pragma unroll
    for (int nt = 0; nt < 8; nt++)
#pragma unroll
        for (int e = 0; e < 4; e++) Of[nt][e] = 0.f;
    float m0 = -INFINITY, m1 = -INFINITY, l0 = 0.f, l1 = 0.f;
    const int r0g = i0 + w * 16 + g;

    for (int jt = 0; jt < 16; jt++) {
        CPWAIT1();
        __syncthreads();
        if (jt + 2 < 16) kvload(((jt + 2) % 3) * STAGE_H, (jt + 2) * 64);
        else CPCOMMIT();   // empty group keeps wait_group invariant

        const __half* st = sm + (jt % 3) * STAGE_H;
        const int j0 = jt * 64;

        // bias prefetch (long-latency LDGs issued before the MMA burst)
        float2 bu[8], bw[8];
        {
            const float* bp0 = bg + (size_t)r0g * NSEQ + j0 + c2;
            const float* bp1 = bp0 + 8 * NSEQ;
#pragma unroll
            for (int nt = 0; nt < 8; nt++) {
                bu[nt] = *(const float2*)(bp0 + nt * 8);
                bw[nt] = *(const float2*)(bp1 + nt * 8);
            }
        }

        // ---- S = Q K^T (3-term) ----
        float Sf[8][4];
#pragma unroll
        for (int nt = 0; nt < 8; nt++)
#pragma unroll
            for (int e = 0; e < 4; e++) Sf[nt][e] = 0.f;
#pragma unroll
        for (int ks = 0; ks < 4; ks++) {
#pragma unroll
            for (int ng = 0; ng < 4; ng++) {
                uint32_t kh_[4], kl_[4];
                ldsm_x4(kh_[0], kh_[1], kh_[2], kh_[3],
                        smem_u32(&st[(ng*16 + lrow)*QST + ks*16 + lko]));
                ldsm_x4(kl_[0], kl_[1], kl_[2], kl_[3],
                        smem_u32(&st[64*QST + (ng*16 + lrow)*QST + ks*16 + lko]));
                mma2(Sf[2*ng],   qH[ks], kh_[0], kh_[2]);
                mma2(Sf[2*ng],   qH[ks], kl_[0], kl_[2]);
                mma2(Sf[2*ng],   qL[ks], kh_[0], kh_[2]);
                mma2(Sf[2*ng+1], qH[ks], kh_[1], kh_[3]);
                mma2(Sf[2*ng+1], qH[ks], kl_[1], kl_[3]);
                mma2(Sf[2*ng+1], qL[ks], kh_[1], kh_[3]);
            }
        }
#pragma unroll
        for (int nt = 0; nt < 8; nt++) {
            Sf[nt][0] += bu[nt].x; Sf[nt][1] += bu[nt].y;
            Sf[nt][2] += bw[nt].x; Sf[nt][3] += bw[nt].y;
        }

        // ---- online softmax ----
        float mx0 = -INFINITY, mx1 = -INFINITY;
#pragma unroll
        for (int nt = 0; nt < 8; nt++) {
            mx0 = fmaxf(mx0, fmaxf(Sf[nt][0], Sf[nt][1]));
            mx1 = fmaxf(mx1, fmaxf(Sf[nt][2], Sf[nt][3]));
        }
        mx0 = fmaxf(mx0, __shfl_xor_sync(0xffffffffu, mx0, 1));
        mx0 = fmaxf(mx0, __shfl_xor_sync(0xffffffffu, mx0, 2));
        mx1 = fmaxf(mx1, __shfl_xor_sync(0xffffffffu, mx1, 1));
        mx1 = fmaxf(mx1, __shfl_xor_sync(0xffffffffu, mx1, 2));
        float mn0 = fmaxf(m0, mx0), mn1 = fmaxf(m1, mx1);
        float rs0 = __expf(m0 - mn0), rs1 = __expf(m1 - mn1);
        m0 = mn0; m1 = mn1;

        uint32_t pH0[8], pH1[8];
        float s0 = 0.f, s1 = 0.f;
#pragma unroll
        for (int nt = 0; nt < 8; nt++) {
            float p0 = __expf(Sf[nt][0] - mn0);
            float p1 = __expf(Sf[nt][1] - mn0);
            float p2 = __expf(Sf[nt][2] - mn1);
            float p3 = __expf(Sf[nt][3] - mn1);
            s0 += p0 + p1; s1 += p2 + p3;
            pH0[nt] = pkh2(__float2half_rn(p0), __float2half_rn(p1));
            pH1[nt] = pkh2(__float2half_rn(p2), __float2half_rn(p3));
        }
        s0 += __shfl_xor_sync(0xffffffffu, s0, 1);
        s0 += __shfl_xor_sync(0xffffffffu, s0, 2);
        s1 += __shfl_xor_sync(0xffffffffu, s1, 1);
        s1 += __shfl_xor_sync(0xffffffffu, s1, 2);
        l0 = l0 * rs0 + s0;
        l1 = l1 * rs1 + s1;
#pragma unroll
        for (int nt = 0; nt < 8; nt++) {
            Of[nt][0] *= rs0; Of[nt][1] *= rs0;
            Of[nt][2] *= rs1; Of[nt][3] *= rs1;
        }

        // ---- O += P V (2-term) ----
#pragma unroll
        for (int ks = 0; ks < 4; ks++) {
            uint32_t aH[4] = {pH0[2*ks], pH1[2*ks], pH0[2*ks+1], pH1[2*ks+1]};
#pragma unroll
            for (int dg = 0; dg < 4; dg++) {
                uint32_t vh_[4], vl_[4];
                ldsm_x4_t(vh_[0], vh_[1], vh_[2], vh_[3],
                          smem_u32(&st[2*64*QST + (ks*16 + lrow)*QST + dg*16 + lko]));
                ldsm_x4_t(vl_[0], vl_[1], vl_[2], vl_[3],
                          smem_u32(&st[3*64*QST + (ks*16 + lrow)*QST + dg*16 + lko]));
                mma2(Of[2*dg],   aH, vh_[0], vh_[1]);
                mma2(Of[2*dg],   aH, vl_[0], vl_[1]);
                mma2(Of[2*dg+1], aH, vh_[2], vh_[3]);
                mma2(Of[2*dg+1], aH, vl_[2], vl_[3]);
            }
        }
    }

    // ---- normalize + store hi-only O to g_aoh [B,N,H*D] ----
    {
        float inv0 = 1.f / l0, inv1 = 1.f / l1;
        size_t base0 = ((size_t)b * NSEQ + r0g) * DIMM + h * HD + c2;
        size_t base1 = base0 + 8 * DIMM;
#pragma unroll
        for (int nt = 0; nt < 8; nt++) {
            *(__half2*)&g_aoh[base0 + nt*8] = __halves2half2(
                __float2half_rn(Of[nt][0] * inv0), __float2half_rn(Of[nt][1] * inv0));
            *(__half2*)&g_aoh[base1 + nt*8] = __halves2half2(
                __float2half_rn(Of[nt][2] * inv1), __float2half_rn(Of[nt][3] * inv1));
        }
    }
}

// ---------------------------------------------------------------------------
extern "C" void kernel_launch(void* const* d_in, const int* in_sizes, int n_in,
                              void* d_out, int out_size) {
    const float *x = nullptr, *pb = nullptr, *wq = nullptr, *wo = nullptr;
    for (int i = 0; i < n_in; i++) {
        switch (in_sizes[i]) {
            case 4194304: x  = (const float*)d_in[i]; break;  // x [8,1024,512]
            case 8388608: pb = (const float*)d_in[i]; break;  // pos_bias [8,1024,1024]
            case 786432:  wq = (const float*)d_in[i]; break;  // w_qkv [512,1536]
            case 262144:  wo = (const float*)d_in[i]; break;  // w_out [512,512]
        }
    }
    if (!x)  x  = (const float*)d_in[0];
    if (!pb) pb = (const float*)d_in[1];
    if (!wq) wq = (const float*)d_in[2];
    if (!wo) wo = (const float*)d_in[3];

    cudaFuncSetAttribute(k_attn_mma, cudaFuncAttributeMaxDynamicSharedMemorySize,
                         ATTN_SMEM);
    cudaFuncSetAttribute(gemm_mma<COLS3, true>,
                         cudaFuncAttributeMaxDynamicSharedMemorySize, GEMM_SMEM);
    cudaFuncSetAttribute(gemm_mma<DIMM, false>,
                         cudaFuncAttributeMaxDynamicSharedMemorySize, GEMM_SMEM);

    k_split<0><<<(MROWS*DIMM/4 + 255)/256, 256>>>(x,  MROWS*DIMM/4);
    k_split<1><<<(DIMM*COLS3/4 + 255)/256, 256>>>(wq, DIMM*COLS3/4);
    k_split<2><<<(DIMM*DIMM/4 + 255)/256, 256>>>(wo, DIMM*DIMM/4);

    gemm_mma<COLS3, true><<<dim3(12, 64), 256, GEMM_SMEM>>>(nullptr);
    k_attn_mma<<<dim3(BSZ, NH, 8), 256, ATTN_SMEM>>>(pb);
    gemm_mma<DIMM, false><<<dim3(4, 64), 256, GEMM_SMEM>>>((float*)d_out);
}

// round 8
// speedup vs baseline: 3.2039x; 1.0809x over previous
#include <cuda_runtime.h>
#include <cuda_fp16.h>
#include <math.h>
#include <stdint.h>

#define BSZ   8
#define NSEQ  1024
#define DIMM  512
#define NH    8
#define HD    64
#define COLS3 1536
#define MROWS (BSZ*NSEQ)

// Pre-split operands. A-side operands (x, attention output) need hi only;
// B-side (weights) and attention inputs q/k/v need hi+lo.
__device__ __align__(16) __half g_xh[MROWS*DIMM];
__device__ __align__(16) __half g_wqh[DIMM*COLS3], g_wql[DIMM*COLS3];
__device__ __align__(16) __half g_woh[DIMM*DIMM],  g_wol[DIMM*DIMM];
__device__ __align__(16) __half g_qh[MROWS*DIMM],  g_ql[MROWS*DIMM];
__device__ __align__(16) __half g_kh[MROWS*DIMM],  g_kl[MROWS*DIMM];
__device__ __align__(16) __half g_vh[MROWS*DIMM],  g_vl[MROWS*DIMM];
__device__ __align__(16) __half g_aoh[MROWS*DIMM];

// ---------------------------------------------------------------------------
// helpers
// ---------------------------------------------------------------------------
__device__ __forceinline__ uint32_t smem_u32(const void* p) {
    return (uint32_t)__cvta_generic_to_shared(p);
}
__device__ __forceinline__ void ldsm_x4(uint32_t& r0, uint32_t& r1,
                                        uint32_t& r2, uint32_t& r3, uint32_t a) {
    asm volatile("ldmatrix.sync.aligned.m8n8.x4.shared.b16 {%0,%1,%2,%3}, [%4];\n"
                 : "=r"(r0), "=r"(r1), "=r"(r2), "=r"(r3) : "r"(a));
}
__device__ __forceinline__ void ldsm_x4_t(uint32_t& r0, uint32_t& r1,
                                          uint32_t& r2, uint32_t& r3, uint32_t a) {
    asm volatile("ldmatrix.sync.aligned.m8n8.x4.trans.shared.b16 {%0,%1,%2,%3}, [%4];\n"
                 : "=r"(r0), "=r"(r1), "=r"(r2), "=r"(r3) : "r"(a));
}
__device__ __forceinline__ void mma2(float c[4], const uint32_t a[4],
                                     uint32_t b0, uint32_t b1) {
    asm volatile(
        "mma.sync.aligned.m16n8k16.row.col.f32.f16.f16.f32 "
        "{%0,%1,%2,%3}, {%4,%5,%6,%7}, {%8,%9}, {%0,%1,%2,%3};\n"
        : "+f"(c[0]), "+f"(c[1]), "+f"(c[2]), "+f"(c[3])
        : "r"(a[0]), "r"(a[1]), "r"(a[2]), "r"(a[3]), "r"(b0), "r"(b1));
}
__device__ __forceinline__ uint32_t pkh2(__half a, __half b) {
    __half2 t = __halves2half2(a, b);
    return *reinterpret_cast<uint32_t*>(&t);
}
#define CP16(dst, src) \
    asm volatile("cp.async.cg.shared.global [%0], [%1], 16;\n" :: "r"(dst), "l"(src))
#define CPCOMMIT() asm volatile("cp.async.commit_group;\n")
#define CPWAIT0()  asm volatile("cp.async.wait_group 0;\n")
#define CPWAIT1()  asm volatile("cp.async.wait_group 1;\n")

// ---------------------------------------------------------------------------
// fp32 -> fp16 split. SEL 0: x (hi only). SEL 1: w_qkv. SEL 2: w_out.
// ---------------------------------------------------------------------------
template<int SEL>
__global__ __launch_bounds__(256) void k_split(const float* __restrict__ s, int n4) {
    __half* hi = (SEL == 0) ? g_xh : (SEL == 1 ? g_wqh : g_woh);
    __half* lo = (SEL == 1) ? g_wql : g_wol;   // unused for SEL==0
    int i = blockIdx.x * blockDim.x + threadIdx.x;
    if (i >= n4) return;
    float4 v = ((const float4*)s)[i];
    float f[4] = {v.x, v.y, v.z, v.w};
    __half h[4], l[4];
#pragma unroll
    for (int e = 0; e < 4; e++) {
        h[e] = __float2half_rn(f[e]);
        l[e] = __float2half_rn(f[e] - __half2float(h[e]));
    }
    ((uint2*)hi)[i] = *(const uint2*)h;
    if (SEL != 0) ((uint2*)lo)[i] = *(const uint2*)l;
}

// ---------------------------------------------------------------------------
// GEMM (unchanged from R7): A hi-only 2-term split, 3-stage ring, 2 CTAs/SM.
// ---------------------------------------------------------------------------
#define AST 40
#define BST 136
#define G_ASTAGE (128*AST)
#define G_BSTAGE (32*BST)
#define G_STAGE  (G_ASTAGE + 2*G_BSTAGE)     // 13824 halves = 27648 B
#define GEMM_SMEM (3 * G_STAGE * 2)          // 82944 B

template<int NC, bool QKV>
__global__ __launch_bounds__(256, 2) void gemm_mma(float* __restrict__ Og) {
    constexpr int KD = 512;
    extern __shared__ __half sg[];

    const int tid  = threadIdx.x;
    const int lane = tid & 31;
    const int wid  = tid >> 5;
    const int wm   = wid >> 2;
    const int wn   = wid & 3;
    const int row0 = blockIdx.y * 128;
    const int col0 = blockIdx.x * 128;
    const int lrow = lane & 15;
    const int lko  = (lane >> 4) * 8;

    float C[4][4][4];
#pragma unroll
    for (int i = 0; i < 4; i++)
#pragma unroll
        for (int j = 0; j < 4; j++)
#pragma unroll
            for (int e = 0; e < 4; e++) C[i][j][e] = 0.f;

    const __half* Ahg = QKV ? g_xh : g_aoh;
    const __half* bsrc[2] = {QKV ? g_wqh : g_woh, QKV ? g_wql : g_wol};

    auto prefetch = [&](int sbase, int kk) {
#pragma unroll
        for (int i = 0; i < 2; i++) {
            int cid = tid + 256 * i;
            int row = cid >> 2, ch = cid & 3;
            CP16(smem_u32(&sg[sbase + row * AST + ch * 8]),
                 Ahg + (size_t)(row0 + row) * KD + kk + ch * 8);
        }
#pragma unroll
        for (int i = 0; i < 4; i++) {
            int cid = tid + 256 * i;
            int arr = cid >> 9, rem = cid & 511;
            int row = rem >> 4, ch = rem & 15;
            CP16(smem_u32(&sg[sbase + G_ASTAGE + arr * G_BSTAGE + row * BST + ch * 8]),
                 bsrc[arr] + (size_t)(kk + row) * NC + col0 + ch * 8);
        }
        CPCOMMIT();
    };

    prefetch(0, 0);
    prefetch(G_STAGE, 32);

    for (int kc = 0; kc < KD / 32; kc++) {
        CPWAIT1();
        __syncthreads();
        if (kc + 2 < KD / 32) prefetch(((kc + 2) % 3) * G_STAGE, (kc + 2) * 32);
        else CPCOMMIT();

        const __half* Ahs = sg + (kc % 3) * G_STAGE;
        const __half* Bhs = Ahs + G_ASTAGE;
        const __half* Bls = Bhs + G_BSTAGE;

#pragma unroll
        for (int kq = 0; kq < 32; kq += 16) {
            uint32_t aH[4][4];
#pragma unroll
            for (int mt = 0; mt < 4; mt++) {
                int r = wm * 64 + mt * 16 + lrow;
                ldsm_x4(aH[mt][0], aH[mt][1], aH[mt][2], aH[mt][3],
                        smem_u32(&Ahs[r * AST + kq + lko]));
            }
#pragma unroll
            for (int ng = 0; ng < 2; ng++) {
                uint32_t bH[4], bL[4];
                int rr = kq + lrow;
                int cb = wn * 32 + ng * 16 + lko;
                ldsm_x4_t(bH[0], bH[1], bH[2], bH[3], smem_u32(&Bhs[rr * BST + cb]));
                ldsm_x4_t(bL[0], bL[1], bL[2], bL[3], smem_u32(&Bls[rr * BST + cb]));
#pragma unroll
                for (int mt = 0; mt < 4; mt++) {
                    mma2(C[mt][ng*2],     aH[mt], bH[0], bH[1]);
                    mma2(C[mt][ng*2],     aH[mt], bL[0], bL[1]);
                    mma2(C[mt][ng*2 + 1], aH[mt], bH[2], bH[3]);
                    mma2(C[mt][ng*2 + 1], aH[mt], bL[2], bL[3]);
                }
            }
        }
    }

    const int g  = lane >> 2;
    const int cc = (lane & 3) * 2;
    if (QKV) {
        const int sec     = col0 >> 9;
        const int rembase = (col0 & 511) + wn * 32;
        __half* dsth = (sec == 0) ? g_qh : (sec == 1 ? g_kh : g_vh);
        __half* dstl = (sec == 0) ? g_ql : (sec == 1 ? g_kl : g_vl);
        const float LOG2B = 13.287712379549449f;
#pragma unroll
        for (int nt = 0; nt < 4; nt++) {
            int rem   = rembase + nt * 8 + cc;
            int h     = rem >> 6;
            int dbase = rem & 63;
            float ifr = exp2f(-(float)dbase * (LOG2B / 64.f));
#pragma unroll
            for (int mt = 0; mt < 4; mt++) {
#pragma unroll
                for (int hf = 0; hf < 2; hf++) {
                    int R = row0 + wm * 64 + mt * 16 + g + hf * 8;
                    int b = R >> 10, n = R & 1023;
                    float v0 = C[mt][nt][hf*2 + 0];
                    float v1 = C[mt][nt][hf*2 + 1];
                    if (sec == 0) { v0 *= 0.125f; v1 *= 0.125f; }
                    if (sec < 2) {
                        float s, co;
                        sincosf((float)n * ifr, &s, &co);
                        float t0 = v0 * co - v1 * s;
                        float t1 = v1 * co + v0 * s;
                        v0 = t0; v1 = t1;
                    }
                    size_t idx = (((size_t)b * NH + h) * NSEQ + n) * HD + dbase;
                    __half h0 = __float2half_rn(v0), h1 = __float2half_rn(v1);
                    *(__half2*)&dsth[idx] = __halves2half2(h0, h1);
                    *(__half2*)&dstl[idx] = __halves2half2(
                        __float2half_rn(v0 - __half2float(h0)),
                        __float2half_rn(v1 - __half2float(h1)));
                }
            }
        }
    } else {
#pragma unroll
        for (int nt = 0; nt < 4; nt++) {
            int colg = col0 + wn * 32 + nt * 8 + cc;
#pragma unroll
            for (int mt = 0; mt < 4; mt++) {
#pragma unroll
                for (int hf = 0; hf < 2; hf++) {
                    int R = row0 + wm * 64 + mt * 16 + g + hf * 8;
                    *(float2*)&Og[(size_t)R * NC + colg] =
                        make_float2(C[mt][nt][hf*2], C[mt][nt][hf*2 + 1]);
                }
            }
        }
    }
}

// ---------------------------------------------------------------------------
// Flash attention, 2 CTAs/SM ping-pong:
//  - smem: [Q-lo 128x72 persistent][KV stage0][KV stage1] = 92160 B
//  - Q-hi fragments in registers; Q-lo re-ldmatrix'd per tile
//  - 2-stage KV ring: load(jt+2) issued after compute(jt), overlaps jt+1
//  - 3-term S, 2-term PV (numerics identical to R7)
// ---------------------------------------------------------------------------
#define QST 72
#define STQ (128 * QST)                  // Q-lo region, halves
#define STAGE_H (4 * 64 * QST)           // KV stage, halves
#define ATTN_SMEM ((STQ + 2 * STAGE_H) * 2)   // 92160 B

__global__ __launch_bounds__(256, 2) void k_attn_mma(const float* __restrict__ bias) {
    extern __shared__ __half sm[];

    const int b  = blockIdx.x;      // fastest: batches share bias slice in L2
    const int h  = blockIdx.y;
    const int i0 = blockIdx.z * 128;
    const int tid = threadIdx.x, lane = tid & 31, w = tid >> 5;
    const int lrow = lane & 15, lko = (lane >> 4) * 8;
    const int g = lane >> 2, c2 = (lane & 3) * 2;

    const size_t bh = (size_t)(b * NH + h) * NSEQ * HD;
    const __half* kv_src[4] = {g_kh + bh, g_kl + bh, g_vh + bh, g_vl + bh};
    const float* bg = bias + (size_t)h * NSEQ * NSEQ;

    // ---- stage Q: hi -> stage0 area (temp), lo -> persistent region 0 ----
    {
        const __half* qh = g_qh + bh;
        const __half* ql = g_ql + bh;
#pragma unroll
        for (int i = 0; i < 8; i++) {
            int cid = tid + 256 * i;            // 2048 chunks
            int arr = cid >> 10;                // 0: hi, 1: lo
            int rem = cid & 1023;
            int row = rem >> 3, ch = rem & 7;
            const __half* src = (arr ? ql : qh) + (size_t)(i0 + row) * HD + ch * 8;
            uint32_t dst = arr ? smem_u32(&sm[row * QST + ch * 8])
                               : smem_u32(&sm[STQ + row * QST + ch * 8]);
            CP16(dst, src);
        }
        CPCOMMIT();
        CPWAIT0();
        __syncthreads();
    }
    uint32_t qH[4][4];
#pragma unroll
    for (int ks = 0; ks < 4; ks++)
        ldsm_x4(qH[ks][0], qH[ks][1], qH[ks][2], qH[ks][3],
                smem_u32(&sm[STQ + (w*16 + lrow)*QST + ks*16 + lko]));
    __syncthreads();

    // KV tile loader into absolute stage base
    auto kvload = [&](int sbase, int j0) {
#pragma unroll
        for (int i = 0; i < 8; i++) {
            int cid = tid + 256 * i;
            int arr = cid >> 9;
            int rem = cid & 511;
            int row = rem >> 3, ch = rem & 7;
            CP16(smem_u32(&sm[sbase + arr * 64 * QST + row * QST + ch * 8]),
                 kv_src[arr] + (size_t)(j0 + row) * HD + ch * 8);
        }
        CPCOMMIT();
    };

    kvload(STQ, 0);
    kvload(STQ + STAGE_H, 64);

    float Of[8][4];
#pragma unroll
    for (int nt = 0; nt < 8; nt++)
#pragma unroll
        for (int e = 0; e < 4; e++) Of[nt][e] = 0.f;
    float m0 = -INFINITY, m1 = -INFINITY, l0 = 0.f, l1 = 0.f;
    const int r0g = i0 + w * 16 + g;

    for (int jt = 0; jt < 16; jt++) {
        CPWAIT1();
        __syncthreads();
        const __half* st = sm + STQ + (jt & 1) * STAGE_H;
        const int j0 = jt * 64;

        // bias prefetch (long-latency LDGs issued before the MMA burst)
        float2 bu[8], bw[8];
        {
            const float* bp0 = bg + (size_t)r0g * NSEQ + j0 + c2;
            const float* bp1 = bp0 + 8 * NSEQ;
#pragma unroll
            for (int nt = 0; nt < 8; nt++) {
                bu[nt] = *(const float2*)(bp0 + nt * 8);
                bw[nt] = *(const float2*)(bp1 + nt * 8);
            }
        }

        // ---- S = Q K^T (3-term; qL re-ldmatrix'd from persistent smem) ----
        float Sf[8][4];
#pragma unroll
        for (int nt = 0; nt < 8; nt++)
#pragma unroll
            for (int e = 0; e < 4; e++) Sf[nt][e] = 0.f;
#pragma unroll
        for (int ks = 0; ks < 4; ks++) {
            uint32_t qL[4];
            ldsm_x4(qL[0], qL[1], qL[2], qL[3],
                    smem_u32(&sm[(w*16 + lrow)*QST + ks*16 + lko]));
#pragma unroll
            for (int ng = 0; ng < 4; ng++) {
                uint32_t kh_[4], kl_[4];
                ldsm_x4(kh_[0], kh_[1], kh_[2], kh_[3],
                        smem_u32(&st[(ng*16 + lrow)*QST + ks*16 + lko]));
                ldsm_x4(kl_[0], kl_[1], kl_[2], kl_[3],
                        smem_u32(&st[64*QST + (ng*16 + lrow)*QST + ks*16 + lko]));
                mma2(Sf[2*ng],   qH[ks], kh_[0], kh_[2]);
                mma2(Sf[2*ng],   qH[ks], kl_[0], kl_[2]);
                mma2(Sf[2*ng],   qL,     kh_[0], kh_[2]);
                mma2(Sf[2*ng+1], qH[ks], kh_[1], kh_[3]);
                mma2(Sf[2*ng+1], qH[ks], kl_[1], kl_[3]);
                mma2(Sf[2*ng+1], qL,     kh_[1], kh_[3]);
            }
        }
#pragma unroll
        for (int nt = 0; nt < 8; nt++) {
            Sf[nt][0] += bu[nt].x; Sf[nt][1] += bu[nt].y;
            Sf[nt][2] += bw[nt].x; Sf[nt][3] += bw[nt].y;
        }

        // ---- online softmax ----
        float mx0 = -INFINITY, mx1 = -INFINITY;
#pragma unroll
        for (int nt = 0; nt < 8; nt++) {
            mx0 = fmaxf(mx0, fmaxf(Sf[nt][0], Sf[nt][1]));
            mx1 = fmaxf(mx1, fmaxf(Sf[nt][2], Sf[nt][3]));
        }
        mx0 = fmaxf(mx0, __shfl_xor_sync(0xffffffffu, mx0, 1));
        mx0 = fmaxf(mx0, __shfl_xor_sync(0xffffffffu, mx0, 2));
        mx1 = fmaxf(mx1, __shfl_xor_sync(0xffffffffu, mx1, 1));
        mx1 = fmaxf(mx1, __shfl_xor_sync(0xffffffffu, mx1, 2));
        float mn0 = fmaxf(m0, mx0), mn1 = fmaxf(m1, mx1);
        float rs0 = __expf(m0 - mn0), rs1 = __expf(m1 - mn1);
        m0 = mn0; m1 = mn1;

        uint32_t pH0[8], pH1[8];
        float s0 = 0.f, s1 = 0.f;
#pragma unroll
        for (int nt = 0; nt < 8; nt++) {
            float p0 = __expf(Sf[nt][0] - mn0);
            float p1 = __expf(Sf[nt][1] - mn0);
            float p2 = __expf(Sf[nt][2] - mn1);
            float p3 = __expf(Sf[nt][3] - mn1);
            s0 += p0 + p1; s1 += p2 + p3;
            pH0[nt] = pkh2(__float2half_rn(p0), __float2half_rn(p1));
            pH1[nt] = pkh2(__float2half_rn(p2), __float2half_rn(p3));
        }
        s0 += __shfl_xor_sync(0xffffffffu, s0, 1);
        s0 += __shfl_xor_sync(0xffffffffu, s0, 2);
        s1 += __shfl_xor_sync(0xffffffffu, s1, 1);
        s1 += __shfl_xor_sync(0xffffffffu, s1, 2);
        l0 = l0 * rs0 + s0;
        l1 = l1 * rs1 + s1;
#pragma unroll
        for (int nt = 0; nt < 8; nt++) {
            Of[nt][0] *= rs0; Of[nt][1] *= rs0;
            Of[nt][2] *= rs1; Of[nt][3] *= rs1;
        }

        // ---- O += P V (2-term) ----
#pragma unroll
        for (int ks = 0; ks < 4; ks++) {
            uint32_t aH[4] = {pH0[2*ks], pH1[2*ks], pH0[2*ks+1], pH1[2*ks+1]};
#pragma unroll
            for (int dg = 0; dg < 4; dg++) {
                uint32_t vh_[4], vl_[4];
                ldsm_x4_t(vh_[0], vh_[1], vh_[2], vh_[3],
                          smem_u32(&st[2*64*QST + (ks*16 + lrow)*QST + dg*16 + lko]));
                ldsm_x4_t(vl_[0], vl_[1], vl_[2], vl_[3],
                          smem_u32(&st[3*64*QST + (ks*16 + lrow)*QST + dg*16 + lko]));
                mma2(Of[2*dg],   aH, vh_[0], vh_[1]);
                mma2(Of[2*dg],   aH, vl_[0], vl_[1]);
                mma2(Of[2*dg+1], aH, vh_[2], vh_[3]);
                mma2(Of[2*dg+1], aH, vl_[2], vl_[3]);
            }
        }

        __syncthreads();    // everyone done reading stage jt&1
        if (jt + 2 < 16) kvload(STQ + (jt & 1) * STAGE_H, (jt + 2) * 64);
        else CPCOMMIT();    // keep wait_group invariant
    }

    // ---- normalize + store hi-only O to g_aoh [B,N,H*D] ----
    {
        float inv0 = 1.f / l0, inv1 = 1.f / l1;
        size_t base0 = ((size_t)b * NSEQ + r0g) * DIMM + h * HD + c2;
        size_t base1 = base0 + 8 * DIMM;
#pragma unroll
        for (int nt = 0; nt < 8; nt++) {
            *(__half2*)&g_aoh[base0 + nt*8] = __halves2half2(
                __float2half_rn(Of[nt][0] * inv0), __float2half_rn(Of[nt][1] * inv0));
            *(__half2*)&g_aoh[base1 + nt*8] = __halves2half2(
                __float2half_rn(Of[nt][2] * inv1), __float2half_rn(Of[nt][3] * inv1));
        }
    }
}

// ---------------------------------------------------------------------------
extern "C" void kernel_launch(void* const* d_in, const int* in_sizes, int n_in,
                              void* d_out, int out_size) {
    const float *x = nullptr, *pb = nullptr, *wq = nullptr, *wo = nullptr;
    for (int i = 0; i < n_in; i++) {
        switch (in_sizes[i]) {
            case 4194304: x  = (const float*)d_in[i]; break;  // x [8,1024,512]
            case 8388608: pb = (const float*)d_in[i]; break;  // pos_bias [8,1024,1024]
            case 786432:  wq = (const float*)d_in[i]; break;  // w_qkv [512,1536]
            case 262144:  wo = (const float*)d_in[i]; break;  // w_out [512,512]
        }
    }
    if (!x)  x  = (const float*)d_in[0];
    if (!pb) pb = (const float*)d_in[1];
    if (!wq) wq = (const float*)d_in[2];
    if (!wo) wo = (const float*)d_in[3];

    cudaFuncSetAttribute(k_attn_mma, cudaFuncAttributeMaxDynamicSharedMemorySize,
                         ATTN_SMEM);
    cudaFuncSetAttribute(gemm_mma<COLS3, true>,
                         cudaFuncAttributeMaxDynamicSharedMemorySize, GEMM_SMEM);
    cudaFuncSetAttribute(gemm_mma<DIMM, false>,
                         cudaFuncAttributeMaxDynamicSharedMemorySize, GEMM_SMEM);

    k_split<0><<<(MROWS*DIMM/4 + 255)/256, 256>>>(x,  MROWS*DIMM/4);
    k_split<1><<<(DIMM*COLS3/4 + 255)/256, 256>>>(wq, DIMM*COLS3/4);
    k_split<2><<<(DIMM*DIMM/4 + 255)/256, 256>>>(wo, DIMM*DIMM/4);

    gemm_mma<COLS3, true><<<dim3(12, 64), 256, GEMM_SMEM>>>(nullptr);
    k_attn_mma<<<dim3(BSZ, NH, 8), 256, ATTN_SMEM>>>(pb);
    gemm_mma<DIMM, false><<<dim3(4, 64), 256, GEMM_SMEM>>>((float*)d_out);
}

// round 10
// speedup vs baseline: 3.4045x; 1.0626x over previous
#include <cuda_runtime.h>
#include <cuda_fp16.h>
#include <math.h>
#include <stdint.h>

#define BSZ   8
#define NSEQ  1024
#define DIMM  512
#define NH    8
#define HD    64
#define COLS3 1536
#define MROWS (BSZ*NSEQ)

// Pre-split operands. A-side operands (x, attention output) hi-only;
// weights and k/v hi+lo; q hi-only (S uses 2-term split: qH*(kH+kL)).
__device__ __align__(16) __half g_xh[MROWS*DIMM];
__device__ __align__(16) __half g_wqh[DIMM*COLS3], g_wql[DIMM*COLS3];
__device__ __align__(16) __half g_woh[DIMM*DIMM],  g_wol[DIMM*DIMM];
__device__ __align__(16) __half g_qh[MROWS*DIMM];
__device__ __align__(16) __half g_kh[MROWS*DIMM],  g_kl[MROWS*DIMM];
__device__ __align__(16) __half g_vh[MROWS*DIMM],  g_vl[MROWS*DIMM];
__device__ __align__(16) __half g_aoh[MROWS*DIMM];

// ---------------------------------------------------------------------------
// helpers
// ---------------------------------------------------------------------------
__device__ __forceinline__ uint32_t smem_u32(const void* p) {
    return (uint32_t)__cvta_generic_to_shared(p);
}
__device__ __forceinline__ void ldsm_x4(uint32_t& r0, uint32_t& r1,
                                        uint32_t& r2, uint32_t& r3, uint32_t a) {
    asm volatile("ldmatrix.sync.aligned.m8n8.x4.shared.b16 {%0,%1,%2,%3}, [%4];\n"
                 : "=r"(r0), "=r"(r1), "=r"(r2), "=r"(r3) : "r"(a));
}
__device__ __forceinline__ void ldsm_x4_t(uint32_t& r0, uint32_t& r1,
                                          uint32_t& r2, uint32_t& r3, uint32_t a) {
    asm volatile("ldmatrix.sync.aligned.m8n8.x4.trans.shared.b16 {%0,%1,%2,%3}, [%4];\n"
                 : "=r"(r0), "=r"(r1), "=r"(r2), "=r"(r3) : "r"(a));
}
__device__ __forceinline__ void mma2(float c[4], const uint32_t a[4],
                                     uint32_t b0, uint32_t b1) {
    asm volatile(
        "mma.sync.aligned.m16n8k16.row.col.f32.f16.f16.f32 "
        "{%0,%1,%2,%3}, {%4,%5,%6,%7}, {%8,%9}, {%0,%1,%2,%3};\n"
        : "+f"(c[0]), "+f"(c[1]), "+f"(c[2]), "+f"(c[3])
        : "r"(a[0]), "r"(a[1]), "r"(a[2]), "r"(a[3]), "r"(b0), "r"(b1));
}
__device__ __forceinline__ uint32_t pkh2(__half a, __half b) {
    __half2 t = __halves2half2(a, b);
    return *reinterpret_cast<uint32_t*>(&t);
}
#define CP16(dst, src) \
    asm volatile("cp.async.cg.shared.global [%0], [%1], 16;\n" :: "r"(dst), "l"(src))
#define CPCOMMIT() asm volatile("cp.async.commit_group;\n")
#define CPWAIT0()  asm volatile("cp.async.wait_group 0;\n")
#define CPWAIT1()  asm volatile("cp.async.wait_group 1;\n")

// ---------------------------------------------------------------------------
// fp32 -> fp16 split. SEL 0: x (hi only). SEL 1: w_qkv. SEL 2: w_out.
// ---------------------------------------------------------------------------
template<int SEL>
__global__ __launch_bounds__(256) void k_split(const float* __restrict__ s, int n4) {
    __half* hi = (SEL == 0) ? g_xh : (SEL == 1 ? g_wqh : g_woh);
    __half* lo = (SEL == 1) ? g_wql : g_wol;   // unused for SEL==0
    int i = blockIdx.x * blockDim.x + threadIdx.x;
    if (i >= n4) return;
    float4 v = ((const float4*)s)[i];
    float f[4] = {v.x, v.y, v.z, v.w};
    __half h[4], l[4];
#pragma unroll
    for (int e = 0; e < 4; e++) {
        h[e] = __float2half_rn(f[e]);
        l[e] = __float2half_rn(f[e] - __half2float(h[e]));
    }
    ((uint2*)hi)[i] = *(const uint2*)h;
    if (SEL != 0) ((uint2*)lo)[i] = *(const uint2*)l;
}

// ---------------------------------------------------------------------------
// GEMM (R8 structure): A hi-only 2-term split, 3-stage ring, 2 CTAs/SM.
// QKV epilogue: q gets hi only; k/v get hi+lo.
// ---------------------------------------------------------------------------
#define AST 40
#define BST 136
#define G_ASTAGE (128*AST)
#define G_BSTAGE (32*BST)
#define G_STAGE  (G_ASTAGE + 2*G_BSTAGE)     // 13824 halves = 27648 B
#define GEMM_SMEM (3 * G_STAGE * 2)          // 82944 B

template<int NC, bool QKV>
__global__ __launch_bounds__(256, 2) void gemm_mma(float* __restrict__ Og) {
    constexpr int KD = 512;
    extern __shared__ __half sg[];

    const int tid  = threadIdx.x;
    const int lane = tid & 31;
    const int wid  = tid >> 5;
    const int wm   = wid >> 2;
    const int wn   = wid & 3;
    const int row0 = blockIdx.y * 128;
    const int col0 = blockIdx.x * 128;
    const int lrow = lane & 15;
    const int lko  = (lane >> 4) * 8;

    float C[4][4][4];
#pragma unroll
    for (int i = 0; i < 4; i++)
#pragma unroll
        for (int j = 0; j < 4; j++)
#pragma unroll
            for (int e = 0; e < 4; e++) C[i][j][e] = 0.f;

    const __half* Ahg = QKV ? g_xh : g_aoh;
    const __half* bsrc[2] = {QKV ? g_wqh : g_woh, QKV ? g_wql : g_wol};

    auto prefetch = [&](int sbase, int kk) {
#pragma unroll
        for (int i = 0; i < 2; i++) {
            int cid = tid + 256 * i;
            int row = cid >> 2, ch = cid & 3;
            CP16(smem_u32(&sg[sbase + row * AST + ch * 8]),
                 Ahg + (size_t)(row0 + row) * KD + kk + ch * 8);
        }
#pragma unroll
        for (int i = 0; i < 4; i++) {
            int cid = tid + 256 * i;
            int arr = cid >> 9, rem = cid & 511;
            int row = rem >> 4, ch = rem & 15;
            CP16(smem_u32(&sg[sbase + G_ASTAGE + arr * G_BSTAGE + row * BST + ch * 8]),
                 bsrc[arr] + (size_t)(kk + row) * NC + col0 + ch * 8);
        }
        CPCOMMIT();
    };

    prefetch(0, 0);
    prefetch(G_STAGE, 32);

    for (int kc = 0; kc < KD / 32; kc++) {
        CPWAIT1();
        __syncthreads();
        if (kc + 2 < KD / 32) prefetch(((kc + 2) % 3) * G_STAGE, (kc + 2) * 32);
        else CPCOMMIT();

        const __half* Ahs = sg + (kc % 3) * G_STAGE;
        const __half* Bhs = Ahs + G_ASTAGE;
        const __half* Bls = Bhs + G_BSTAGE;

#pragma unroll
        for (int kq = 0; kq < 32; kq += 16) {
            uint32_t aH[4][4];
#pragma unroll
            for (int mt = 0; mt < 4; mt++) {
                int r = wm * 64 + mt * 16 + lrow;
                ldsm_x4(aH[mt][0], aH[mt][1], aH[mt][2], aH[mt][3],
                        smem_u32(&Ahs[r * AST + kq + lko]));
            }
#pragma unroll
            for (int ng = 0; ng < 2; ng++) {
                uint32_t bH[4], bL[4];
                int rr = kq + lrow;
                int cb = wn * 32 + ng * 16 + lko;
                ldsm_x4_t(bH[0], bH[1], bH[2], bH[3], smem_u32(&Bhs[rr * BST + cb]));
                ldsm_x4_t(bL[0], bL[1], bL[2], bL[3], smem_u32(&Bls[rr * BST + cb]));
#pragma unroll
                for (int mt = 0; mt < 4; mt++) {
                    mma2(C[mt][ng*2],     aH[mt], bH[0], bH[1]);
                    mma2(C[mt][ng*2],     aH[mt], bL[0], bL[1]);
                    mma2(C[mt][ng*2 + 1], aH[mt], bH[2], bH[3]);
                    mma2(C[mt][ng*2 + 1], aH[mt], bL[2], bL[3]);
                }
            }
        }
    }

    const int g  = lane >> 2;
    const int cc = (lane & 3) * 2;
    if (QKV) {
        const int sec     = col0 >> 9;
        const int rembase = (col0 & 511) + wn * 32;
        __half* dsth = (sec == 0) ? g_qh : (sec == 1 ? g_kh : g_vh);
        __half* dstl = (sec == 1) ? g_kl : g_vl;   // no lo for q
        const float LOG2B = 13.287712379549449f;
#pragma unroll
        for (int nt = 0; nt < 4; nt++) {
            int rem   = rembase + nt * 8 + cc;
            int h     = rem >> 6;
            int dbase = rem & 63;
            float ifr = exp2f(-(float)dbase * (LOG2B / 64.f));
#pragma unroll
            for (int mt = 0; mt < 4; mt++) {
#pragma unroll
                for (int hf = 0; hf < 2; hf++) {
                    int R = row0 + wm * 64 + mt * 16 + g + hf * 8;
                    int b = R >> 10, n = R & 1023;
                    float v0 = C[mt][nt][hf*2 + 0];
                    float v1 = C[mt][nt][hf*2 + 1];
                    if (sec == 0) { v0 *= 0.125f; v1 *= 0.125f; }
                    if (sec < 2) {
                        float s, co;
                        sincosf((float)n * ifr, &s, &co);
                        float t0 = v0 * co - v1 * s;
                        float t1 = v1 * co + v0 * s;
                        v0 = t0; v1 = t1;
                    }
                    size_t idx = (((size_t)b * NH + h) * NSEQ + n) * HD + dbase;
                    __half h0 = __float2half_rn(v0), h1 = __float2half_rn(v1);
                    *(__half2*)&dsth[idx] = __halves2half2(h0, h1);
                    if (sec != 0)
                        *(__half2*)&dstl[idx] = __halves2half2(
                            __float2half_rn(v0 - __half2float(h0)),
                            __float2half_rn(v1 - __half2float(h1)));
                }
            }
        }
    } else {
#pragma unroll
        for (int nt = 0; nt < 4; nt++) {
            int colg = col0 + wn * 32 + nt * 8 + cc;
#pragma unroll
            for (int mt = 0; mt < 4; mt++) {
#pragma unroll
                for (int hf = 0; hf < 2; hf++) {
                    int R = row0 + wm * 64 + mt * 16 + g + hf * 8;
                    *(float2*)&Og[(size_t)R * NC + colg] =
                        make_float2(C[mt][nt][hf*2], C[mt][nt][hf*2 + 1]);
                }
            }
        }
    }
}

// ---------------------------------------------------------------------------
// Flash attention, 2 CTAs/SM:
//  - S = qH*(kH+kL)  (2-term; qL term dropped — q hi-only)
//  - PV = pH*(vH+vL) (2-term)
//  - 2-stage KV cp.async ring; Q staged through stage0, frags in registers
//  - smem = 2 * 36864 B = 73728 B
// ---------------------------------------------------------------------------
#define QST 72
#define STAGE_H (4 * 64 * QST)
#define ATTN_SMEM (2 * STAGE_H * 2)      // 73728 B

__global__ __launch_bounds__(256, 2) void k_attn_mma(const float* __restrict__ bias) {
    extern __shared__ __half sm[];

    const int b  = blockIdx.x;      // fastest: batches share bias slice in L2
    const int h  = blockIdx.y;
    const int i0 = blockIdx.z * 128;
    const int tid = threadIdx.x, lane = tid & 31, w = tid >> 5;
    const int lrow = lane & 15, lko = (lane >> 4) * 8;
    const int g = lane >> 2, c2 = (lane & 3) * 2;

    const size_t bh = (size_t)(b * NH + h) * NSEQ * HD;
    const __half* kv_src[4] = {g_kh + bh, g_kl + bh, g_vh + bh, g_vl + bh};
    const float* bg = bias + (size_t)h * NSEQ * NSEQ;

    // ---- stage Q-hi through stage0, extract fragments ----
    {
        const __half* qh = g_qh + bh;
#pragma unroll
        for (int i = 0; i < 4; i++) {
            int cid = tid + 256 * i;            // 1024 chunks: 128 rows x 8
            int row = cid >> 3, ch = cid & 7;
            CP16(smem_u32(&sm[row * QST + ch * 8]),
                 qh + (size_t)(i0 + row) * HD + ch * 8);
        }
        CPCOMMIT();
        CPWAIT0();
        __syncthreads();
    }
    uint32_t qH[4][4];
#pragma unroll
    for (int ks = 0; ks < 4; ks++)
        ldsm_x4(qH[ks][0], qH[ks][1], qH[ks][2], qH[ks][3],
                smem_u32(&sm[(w*16 + lrow)*QST + ks*16 + lko]));
    __syncthreads();

    auto kvload = [&](int sbase, int j0) {
#pragma unroll
        for (int i = 0; i < 8; i++) {
            int cid = tid + 256 * i;
            int arr = cid >> 9;
            int rem = cid & 511;
            int row = rem >> 3, ch = rem & 7;
            CP16(smem_u32(&sm[sbase + arr * 64 * QST + row * QST + ch * 8]),
                 kv_src[arr] + (size_t)(j0 + row) * HD + ch * 8);
        }
        CPCOMMIT();
    };

    kvload(0, 0);
    kvload(STAGE_H, 64);

    float Of[8][4];
#pragma unroll
    for (int nt = 0; nt < 8; nt++)
#pragma unroll
        for (int e = 0; e < 4; e++) Of[nt][e] = 0.f;
    float m0 = -INFINITY, m1 = -INFINITY, l0 = 0.f, l1 = 0.f;
    const int r0g = i0 + w * 16 + g;

    for (int jt = 0; jt < 16; jt++) {
        CPWAIT1();
        __syncthreads();
        const __half* st = sm + (jt & 1) * STAGE_H;
        const int j0 = jt * 64;

        // bias prefetch (long-latency LDGs before the MMA burst)
        float2 bu[8], bw[8];
        {
            const float* bp0 = bg + (size_t)r0g * NSEQ + j0 + c2;
            const float* bp1 = bp0 + 8 * NSEQ;
#pragma unroll
            for (int nt = 0; nt < 8; nt++) {
                bu[nt] = *(const float2*)(bp0 + nt * 8);
                bw[nt] = *(const float2*)(bp1 + nt * 8);
            }
        }

        // ---- S = qH * (kH + kL)  (2-term) ----
        float Sf[8][4];
#pragma unroll
        for (int nt = 0; nt < 8; nt++)
#pragma unroll
            for (int e = 0; e < 4; e++) Sf[nt][e] = 0.f;
#pragma unroll
        for (int ks = 0; ks < 4; ks++) {
#pragma unroll
            for (int ng = 0; ng < 4; ng++) {
                uint32_t kh_[4], kl_[4];
                ldsm_x4(kh_[0], kh_[1], kh_[2], kh_[3],
                        smem_u32(&st[(ng*16 + lrow)*QST + ks*16 + lko]));
                ldsm_x4(kl_[0], kl_[1], kl_[2], kl_[3],
                        smem_u32(&st[64*QST + (ng*16 + lrow)*QST + ks*16 + lko]));
                mma2(Sf[2*ng],   qH[ks], kh_[0], kh_[2]);
                mma2(Sf[2*ng],   qH[ks], kl_[0], kl_[2]);
                mma2(Sf[2*ng+1], qH[ks], kh_[1], kh_[3]);
                mma2(Sf[2*ng+1], qH[ks], kl_[1], kl_[3]);
            }
        }
#pragma unroll
        for (int nt = 0; nt < 8; nt++) {
            Sf[nt][0] += bu[nt].x; Sf[nt][1] += bu[nt].y;
            Sf[nt][2] += bw[nt].x; Sf[nt][3] += bw[nt].y;
        }

        // ---- online softmax ----
        float mx0 = -INFINITY, mx1 = -INFINITY;
#pragma unroll
        for (int nt = 0; nt < 8; nt++) {
            mx0 = fmaxf(mx0, fmaxf(Sf[nt][0], Sf[nt][1]));
            mx1 = fmaxf(mx1, fmaxf(Sf[nt][2], Sf[nt][3]));
        }
        mx0 = fmaxf(mx0, __shfl_xor_sync(0xffffffffu, mx0, 1));
        mx0 = fmaxf(mx0, __shfl_xor_sync(0xffffffffu, mx0, 2));
        mx1 = fmaxf(mx1, __shfl_xor_sync(0xffffffffu, mx1, 1));
        mx1 = fmaxf(mx1, __shfl_xor_sync(0xffffffffu, mx1, 2));
        float mn0 = fmaxf(m0, mx0), mn1 = fmaxf(m1, mx1);
        float rs0 = __expf(m0 - mn0), rs1 = __expf(m1 - mn1);
        m0 = mn0; m1 = mn1;

        uint32_t pH0[8], pH1[8];
        float s0 = 0.f, s1 = 0.f;
#pragma unroll
        for (int nt = 0; nt < 8; nt++) {
            float p0 = __expf(Sf[nt][0] - mn0);
            float p1 = __expf(Sf[nt][1] - mn0);
            float p2 = __expf(Sf[nt][2] - mn1);
            float p3 = __expf(Sf[nt][3] - mn1);
            s0 += p0 + p1; s1 += p2 + p3;
            pH0[nt] = pkh2(__float2half_rn(p0), __float2half_rn(p1));
            pH1[nt] = pkh2(__float2half_rn(p2), __float2half_rn(p3));
        }
        s0 += __shfl_xor_sync(0xffffffffu, s0, 1);
        s0 += __shfl_xor_sync(0xffffffffu, s0, 2);
        s1 += __shfl_xor_sync(0xffffffffu, s1, 1);
        s1 += __shfl_xor_sync(0xffffffffu, s1, 2);
        l0 = l0 * rs0 + s0;
        l1 = l1 * rs1 + s1;
#pragma unroll
        for (int nt = 0; nt < 8; nt++) {
            Of[nt][0] *= rs0; Of[nt][1] *= rs0;
            Of[nt][2] *= rs1; Of[nt][3] *= rs1;
        }

        // ---- O += pH * (vH + vL)  (2-term) ----
#pragma unroll
        for (int ks = 0; ks < 4; ks++) {
            uint32_t aH[4] = {pH0[2*ks], pH1[2*ks], pH0[2*ks+1], pH1[2*ks+1]};
#pragma unroll
            for (int dg = 0; dg < 4; dg++) {
                uint32_t vh_[4], vl_[4];
                ldsm_x4_t(vh_[0], vh_[1], vh_[2], vh_[3],
                          smem_u32(&st[2*64*QST + (ks*16 + lrow)*QST + dg*16 + lko]));
                ldsm_x4_t(vl_[0], vl_[1], vl_[2], vl_[3],
                          smem_u32(&st[3*64*QST + (ks*16 + lrow)*QST + dg*16 + lko]));
                mma2(Of[2*dg],   aH, vh_[0], vh_[1]);
                mma2(Of[2*dg],   aH, vl_[0], vl_[1]);
                mma2(Of[2*dg+1], aH, vh_[2], vh_[3]);
                mma2(Of[2*dg+1], aH, vl_[2], vl_[3]);
            }
        }

        __syncthreads();    // everyone done reading stage jt&1
        if (jt + 2 < 16) kvload((jt & 1) * STAGE_H, (jt + 2) * 64);
        else CPCOMMIT();    // keep wait_group invariant
    }

    // ---- normalize + store hi-only O to g_aoh [B,N,H*D] ----
    {
        float inv0 = 1.f / l0, inv1 = 1.f / l1;
        size_t base0 = ((size_t)b * NSEQ + r0g) * DIMM + h * HD + c2;
        size_t base1 = base0 + 8 * DIMM;
#pragma unroll
        for (int nt = 0; nt < 8; nt++) {
            *(__half2*)&g_aoh[base0 + nt*8] = __halves2half2(
                __float2half_rn(Of[nt][0] * inv0), __float2half_rn(Of[nt][1] * inv0));
            *(__half2*)&g_aoh[base1 + nt*8] = __halves2half2(
                __float2half_rn(Of[nt][2] * inv1), __float2half_rn(Of[nt][3] * inv1));
        }
    }
}

// ---------------------------------------------------------------------------
extern "C" void kernel_launch(void* const* d_in, const int* in_sizes, int n_in,
                              void* d_out, int out_size) {
    const float *x = nullptr, *pb = nullptr, *wq = nullptr, *wo = nullptr;
    for (int i = 0; i < n_in; i++) {
        switch (in_sizes[i]) {
            case 4194304: x  = (const float*)d_in[i]; break;  // x [8,1024,512]
            case 8388608: pb = (const float*)d_in[i]; break;  // pos_bias [8,1024,1024]
            case 786432:  wq = (const float*)d_in[i]; break;  // w_qkv [512,1536]
            case 262144:  wo = (const float*)d_in[i]; break;  // w_out [512,512]
        }
    }
    if (!x)  x  = (const float*)d_in[0];
    if (!pb) pb = (const float*)d_in[1];
    if (!wq) wq = (const float*)d_in[2];
    if (!wo) wo = (const float*)d_in[3];

    cudaFuncSetAttribute(k_attn_mma, cudaFuncAttributeMaxDynamicSharedMemorySize,
                         ATTN_SMEM);
    cudaFuncSetAttribute(gemm_mma<COLS3, true>,
                         cudaFuncAttributeMaxDynamicSharedMemorySize, GEMM_SMEM);
    cudaFuncSetAttribute(gemm_mma<DIMM, false>,
                         cudaFuncAttributeMaxDynamicSharedMemorySize, GEMM_SMEM);

    k_split<0><<<(MROWS*DIMM/4 + 255)/256, 256>>>(x,  MROWS*DIMM/4);
    k_split<1><<<(DIMM*COLS3/4 + 255)/256, 256>>>(wq, DIMM*COLS3/4);
    k_split<2><<<(DIMM*DIMM/4 + 255)/256, 256>>>(wo, DIMM*DIMM/4);

    gemm_mma<COLS3, true><<<dim3(12, 64), 256, GEMM_SMEM>>>(nullptr);
    k_attn_mma<<<dim3(BSZ, NH, 8), 256, ATTN_SMEM>>>(pb);
    gemm_mma<DIMM, false><<<dim3(4, 64), 256, GEMM_SMEM>>>((float*)d_out);
}

// round 12
// speedup vs baseline: 3.4514x; 1.0138x over previous
#include <cuda_runtime.h>
#include <cuda_fp16.h>
#include <math.h>
#include <stdint.h>

#define BSZ   8
#define NSEQ  1024
#define DIMM  512
#define NH    8
#define HD    64
#define COLS3 1536
#define MROWS (BSZ*NSEQ)

// Pre-split operands. A-side operands (x, attention output) hi-only;
// weights and k/v hi+lo; q hi-only.
__device__ __align__(16) __half g_xh[MROWS*DIMM];
__device__ __align__(16) __half g_wqh[DIMM*COLS3], g_wql[DIMM*COLS3];
__device__ __align__(16) __half g_woh[DIMM*DIMM],  g_wol[DIMM*DIMM];
__device__ __align__(16) __half g_qh[MROWS*DIMM];
__device__ __align__(16) __half g_kh[MROWS*DIMM],  g_kl[MROWS*DIMM];
__device__ __align__(16) __half g_vh[MROWS*DIMM],  g_vl[MROWS*DIMM];
__device__ __align__(16) __half g_aoh[MROWS*DIMM];

// ---------------------------------------------------------------------------
// helpers
// ---------------------------------------------------------------------------
__device__ __forceinline__ uint32_t smem_u32(const void* p) {
    return (uint32_t)__cvta_generic_to_shared(p);
}
__device__ __forceinline__ void ldsm_x4(uint32_t& r0, uint32_t& r1,
                                        uint32_t& r2, uint32_t& r3, uint32_t a) {
    asm volatile("ldmatrix.sync.aligned.m8n8.x4.shared.b16 {%0,%1,%2,%3}, [%4];\n"
                 : "=r"(r0), "=r"(r1), "=r"(r2), "=r"(r3) : "r"(a));
}
__device__ __forceinline__ void ldsm_x4_t(uint32_t& r0, uint32_t& r1,
                                          uint32_t& r2, uint32_t& r3, uint32_t a) {
    asm volatile("ldmatrix.sync.aligned.m8n8.x4.trans.shared.b16 {%0,%1,%2,%3}, [%4];\n"
                 : "=r"(r0), "=r"(r1), "=r"(r2), "=r"(r3) : "r"(a));
}
__device__ __forceinline__ void mma2(float c[4], const uint32_t a[4],
                                     uint32_t b0, uint32_t b1) {
    asm volatile(
        "mma.sync.aligned.m16n8k16.row.col.f32.f16.f16.f32 "
        "{%0,%1,%2,%3}, {%4,%5,%6,%7}, {%8,%9}, {%0,%1,%2,%3};\n"
        : "+f"(c[0]), "+f"(c[1]), "+f"(c[2]), "+f"(c[3])
        : "r"(a[0]), "r"(a[1]), "r"(a[2]), "r"(a[3]), "r"(b0), "r"(b1));
}
__device__ __forceinline__ uint32_t pkh2(__half a, __half b) {
    __half2 t = __halves2half2(a, b);
    return *reinterpret_cast<uint32_t*>(&t);
}
#define CP16(dst, src) \
    asm volatile("cp.async.cg.shared.global [%0], [%1], 16;\n" :: "r"(dst), "l"(src))
#define CPCOMMIT() asm volatile("cp.async.commit_group;\n")
#define CPWAIT0()  asm volatile("cp.async.wait_group 0;\n")
#define CPWAIT1()  asm volatile("cp.async.wait_group 1;\n")

// ---------------------------------------------------------------------------
// fp32 -> fp16 split. SEL 0: x (hi only). SEL 1: w_qkv. SEL 2: w_out.
// ---------------------------------------------------------------------------
template<int SEL>
__global__ __launch_bounds__(256) void k_split(const float* __restrict__ s, int n4) {
    __half* hi = (SEL == 0) ? g_xh : (SEL == 1 ? g_wqh : g_woh);
    __half* lo = (SEL == 1) ? g_wql : g_wol;   // unused for SEL==0
    int i = blockIdx.x * blockDim.x + threadIdx.x;
    if (i >= n4) return;
    float4 v = ((const float4*)s)[i];
    float f[4] = {v.x, v.y, v.z, v.w};
    __half h[4], l[4];
#pragma unroll
    for (int e = 0; e < 4; e++) {
        h[e] = __float2half_rn(f[e]);
        l[e] = __float2half_rn(f[e] - __half2float(h[e]));
    }
    ((uint2*)hi)[i] = *(const uint2*)h;
    if (SEL != 0) ((uint2*)lo)[i] = *(const uint2*)l;
}

// ---------------------------------------------------------------------------
// GEMM: A hi-only 2-term split, 3-stage ring, 2 CTAs/SM.
// MMA issue reordered: hi pass over all fragments, then lo pass — same-C
// reuse distance >= 8 MMAs, per-C accumulation order unchanged (bit-identical).
// ---------------------------------------------------------------------------
#define AST 40
#define BST 136
#define G_ASTAGE (128*AST)
#define G_BSTAGE (32*BST)
#define G_STAGE  (G_ASTAGE + 2*G_BSTAGE)     // 13824 halves = 27648 B
#define GEMM_SMEM (3 * G_STAGE * 2)          // 82944 B

template<int NC, bool QKV>
__global__ __launch_bounds__(256, 2) void gemm_mma(float* __restrict__ Og) {
    constexpr int KD = 512;
    extern __shared__ __half sg[];

    const int tid  = threadIdx.x;
    const int lane = tid & 31;
    const int wid  = tid >> 5;
    const int wm   = wid >> 2;
    const int wn   = wid & 3;
    const int row0 = blockIdx.y * 128;
    const int col0 = blockIdx.x * 128;
    const int lrow = lane & 15;
    const int lko  = (lane >> 4) * 8;

    float C[4][4][4];
#pragma unroll
    for (int i = 0; i < 4; i++)
#pragma unroll
        for (int j = 0; j < 4; j++)
#pragma unroll
            for (int e = 0; e < 4; e++) C[i][j][e] = 0.f;

    const __half* Ahg = QKV ? g_xh : g_aoh;
    const __half* bsrc[2] = {QKV ? g_wqh : g_woh, QKV ? g_wql : g_wol};

    auto prefetch = [&](int sbase, int kk) {
#pragma unroll
        for (int i = 0; i < 2; i++) {
            int cid = tid + 256 * i;
            int row = cid >> 2, ch = cid & 3;
            CP16(smem_u32(&sg[sbase + row * AST + ch * 8]),
                 Ahg + (size_t)(row0 + row) * KD + kk + ch * 8);
        }
#pragma unroll
        for (int i = 0; i < 4; i++) {
            int cid = tid + 256 * i;
            int arr = cid >> 9, rem = cid & 511;
            int row = rem >> 4, ch = rem & 15;
            CP16(smem_u32(&sg[sbase + G_ASTAGE + arr * G_BSTAGE + row * BST + ch * 8]),
                 bsrc[arr] + (size_t)(kk + row) * NC + col0 + ch * 8);
        }
        CPCOMMIT();
    };

    prefetch(0, 0);
    prefetch(G_STAGE, 32);

    for (int kc = 0; kc < KD / 32; kc++) {
        CPWAIT1();
        __syncthreads();
        if (kc + 2 < KD / 32) prefetch(((kc + 2) % 3) * G_STAGE, (kc + 2) * 32);
        else CPCOMMIT();

        const __half* Ahs = sg + (kc % 3) * G_STAGE;
        const __half* Bhs = Ahs + G_ASTAGE;
        const __half* Bls = Bhs + G_BSTAGE;

#pragma unroll
        for (int kq = 0; kq < 32; kq += 16) {
            uint32_t aH[4][4];
#pragma unroll
            for (int mt = 0; mt < 4; mt++) {
                int r = wm * 64 + mt * 16 + lrow;
                ldsm_x4(aH[mt][0], aH[mt][1], aH[mt][2], aH[mt][3],
                        smem_u32(&Ahs[r * AST + kq + lko]));
            }
            int rr = kq + lrow;
            // ---- pass 1: B-hi (8 distinct C fragments back-to-back) ----
#pragma unroll
            for (int ng = 0; ng < 2; ng++) {
                uint32_t bH[4];
                int cb = wn * 32 + ng * 16 + lko;
                ldsm_x4_t(bH[0], bH[1], bH[2], bH[3], smem_u32(&Bhs[rr * BST + cb]));
#pragma unroll
                for (int mt = 0; mt < 4; mt++)
                    mma2(C[mt][ng*2],     aH[mt], bH[0], bH[1]);
#pragma unroll
                for (int mt = 0; mt < 4; mt++)
                    mma2(C[mt][ng*2 + 1], aH[mt], bH[2], bH[3]);
            }
            // ---- pass 2: B-lo ----
#pragma unroll
            for (int ng = 0; ng < 2; ng++) {
                uint32_t bL[4];
                int cb = wn * 32 + ng * 16 + lko;
                ldsm_x4_t(bL[0], bL[1], bL[2], bL[3], smem_u32(&Bls[rr * BST + cb]));
#pragma unroll
                for (int mt = 0; mt < 4; mt++)
                    mma2(C[mt][ng*2],     aH[mt], bL[0], bL[1]);
#pragma unroll
                for (int mt = 0; mt < 4; mt++)
                    mma2(C[mt][ng*2 + 1], aH[mt], bL[2], bL[3]);
            }
        }
    }

    const int g  = lane >> 2;
    const int cc = (lane & 3) * 2;
    if (QKV) {
        const int sec     = col0 >> 9;
        const int rembase = (col0 & 511) + wn * 32;
        __half* dsth = (sec == 0) ? g_qh : (sec == 1 ? g_kh : g_vh);
        __half* dstl = (sec == 1) ? g_kl : g_vl;   // no lo for q
        const float LOG2B = 13.287712379549449f;
#pragma unroll
        for (int nt = 0; nt < 4; nt++) {
            int rem   = rembase + nt * 8 + cc;
            int h     = rem >> 6;
            int dbase = rem & 63;
            float ifr = exp2f(-(float)dbase * (LOG2B / 64.f));
#pragma unroll
            for (int mt = 0; mt < 4; mt++) {
#pragma unroll
                for (int hf = 0; hf < 2; hf++) {
                    int R = row0 + wm * 64 + mt * 16 + g + hf * 8;
                    int b = R >> 10, n = R & 1023;
                    float v0 = C[mt][nt][hf*2 + 0];
                    float v1 = C[mt][nt][hf*2 + 1];
                    if (sec == 0) { v0 *= 0.125f; v1 *= 0.125f; }
                    if (sec < 2) {
                        float s, co;
                        sincosf((float)n * ifr, &s, &co);
                        float t0 = v0 * co - v1 * s;
                        float t1 = v1 * co + v0 * s;
                        v0 = t0; v1 = t1;
                    }
                    size_t idx = (((size_t)b * NH + h) * NSEQ + n) * HD + dbase;
                    __half h0 = __float2half_rn(v0), h1 = __float2half_rn(v1);
                    *(__half2*)&dsth[idx] = __halves2half2(h0, h1);
                    if (sec != 0)
                        *(__half2*)&dstl[idx] = __halves2half2(
                            __float2half_rn(v0 - __half2float(h0)),
                            __float2half_rn(v1 - __half2float(h1)));
                }
            }
        }
    } else {
#pragma unroll
        for (int nt = 0; nt < 4; nt++) {
            int colg = col0 + wn * 32 + nt * 8 + cc;
#pragma unroll
            for (int mt = 0; mt < 4; mt++) {
#pragma unroll
                for (int hf = 0; hf < 2; hf++) {
                    int R = row0 + wm * 64 + mt * 16 + g + hf * 8;
                    *(float2*)&Og[(size_t)R * NC + colg] =
                        make_float2(C[mt][nt][hf*2], C[mt][nt][hf*2 + 1]);
                }
            }
        }
    }
}

// ---------------------------------------------------------------------------
// Flash attention, 2 CTAs/SM. S = qH*(kH+kL), PV = pH*(vH+vL), both issued
// as hi-pass-then-lo-pass (same-C distance >= 8; per-C order unchanged).
// ---------------------------------------------------------------------------
#define QST 72
#define STAGE_H (4 * 64 * QST)
#define ATTN_SMEM (2 * STAGE_H * 2)      // 73728 B

__global__ __launch_bounds__(256, 2) void k_attn_mma(const float* __restrict__ bias) {
    extern __shared__ __half sm[];

    const int b  = blockIdx.x;      // fastest: batches share bias slice in L2
    const int h  = blockIdx.y;
    const int i0 = blockIdx.z * 128;
    const int tid = threadIdx.x, lane = tid & 31, w = tid >> 5;
    const int lrow = lane & 15, lko = (lane >> 4) * 8;
    const int g = lane >> 2, c2 = (lane & 3) * 2;

    const size_t bh = (size_t)(b * NH + h) * NSEQ * HD;
    const __half* kv_src[4] = {g_kh + bh, g_kl + bh, g_vh + bh, g_vl + bh};
    const float* bg = bias + (size_t)h * NSEQ * NSEQ;

    // ---- stage Q-hi through stage0, extract fragments ----
    {
        const __half* qh = g_qh + bh;
#pragma unroll
        for (int i = 0; i < 4; i++) {
            int cid = tid + 256 * i;
            int row = cid >> 3, ch = cid & 7;
            CP16(smem_u32(&sm[row * QST + ch * 8]),
                 qh + (size_t)(i0 + row) * HD + ch * 8);
        }
        CPCOMMIT();
        CPWAIT0();
        __syncthreads();
    }
    uint32_t qH[4][4];
#pragma unroll
    for (int ks = 0; ks < 4; ks++)
        ldsm_x4(qH[ks][0], qH[ks][1], qH[ks][2], qH[ks][3],
                smem_u32(&sm[(w*16 + lrow)*QST + ks*16 + lko]));
    __syncthreads();

    auto kvload = [&](int sbase, int j0) {
#pragma unroll
        for (int i = 0; i < 8; i++) {
            int cid = tid + 256 * i;
            int arr = cid >> 9;
            int rem = cid & 511;
            int row = rem >> 3, ch = rem & 7;
            CP16(smem_u32(&sm[sbase + arr * 64 * QST + row * QST + ch * 8]),
                 kv_src[arr] + (size_t)(j0 + row) * HD + ch * 8);
        }
        CPCOMMIT();
    };

    kvload(0, 0);
    kvload(STAGE_H, 64);

    float Of[8][4];
#pragma unroll
    for (int nt = 0; nt < 8; nt++)
#pragma unroll
        for (int e = 0; e < 4; e++) Of[nt][e] = 0.f;
    float m0 = -INFINITY, m1 = -INFINITY, l0 = 0.f, l1 = 0.f;
    const int r0g = i0 + w * 16 + g;

    for (int jt = 0; jt < 16; jt++) {
        CPWAIT1();
        __syncthreads();
        const __half* st = sm + (jt & 1) * STAGE_H;
        const int j0 = jt * 64;

        // bias prefetch (long-latency LDGs before the MMA burst)
        float2 bu[8], bw[8];
        {
            const float* bp0 = bg + (size_t)r0g * NSEQ + j0 + c2;
            const float* bp1 = bp0 + 8 * NSEQ;
#pragma unroll
            for (int nt = 0; nt < 8; nt++) {
                bu[nt] = *(const float2*)(bp0 + nt * 8);
                bw[nt] = *(const float2*)(bp1 + nt * 8);
            }
        }

        // ---- S = qH*(kH + kL): hi pass over all ng, then lo pass ----
        float Sf[8][4];
#pragma unroll
        for (int nt = 0; nt < 8; nt++)
#pragma unroll
            for (int e = 0; e < 4; e++) Sf[nt][e] = 0.f;
#pragma unroll
        for (int ks = 0; ks < 4; ks++) {
#pragma unroll
            for (int ng = 0; ng < 4; ng++) {
                uint32_t kh_[4];
                ldsm_x4(kh_[0], kh_[1], kh_[2], kh_[3],
                        smem_u32(&st[(ng*16 + lrow)*QST + ks*16 + lko]));
                mma2(Sf[2*ng],   qH[ks], kh_[0], kh_[2]);
                mma2(Sf[2*ng+1], qH[ks], kh_[1], kh_[3]);
            }
#pragma unroll
            for (int ng = 0; ng < 4; ng++) {
                uint32_t kl_[4];
                ldsm_x4(kl_[0], kl_[1], kl_[2], kl_[3],
                        smem_u32(&st[64*QST + (ng*16 + lrow)*QST + ks*16 + lko]));
                mma2(Sf[2*ng],   qH[ks], kl_[0], kl_[2]);
                mma2(Sf[2*ng+1], qH[ks], kl_[1], kl_[3]);
            }
        }
#pragma unroll
        for (int nt = 0; nt < 8; nt++) {
            Sf[nt][0] += bu[nt].x; Sf[nt][1] += bu[nt].y;
            Sf[nt][2] += bw[nt].x; Sf[nt][3] += bw[nt].y;
        }

        // ---- online softmax ----
        float mx0 = -INFINITY, mx1 = -INFINITY;
#pragma unroll
        for (int nt = 0; nt < 8; nt++) {
            mx0 = fmaxf(mx0, fmaxf(Sf[nt][0], Sf[nt][1]));
            mx1 = fmaxf(mx1, fmaxf(Sf[nt][2], Sf[nt][3]));
        }
        mx0 = fmaxf(mx0, __shfl_xor_sync(0xffffffffu, mx0, 1));
        mx0 = fmaxf(mx0, __shfl_xor_sync(0xffffffffu, mx0, 2));
        mx1 = fmaxf(mx1, __shfl_xor_sync(0xffffffffu, mx1, 1));
        mx1 = fmaxf(mx1, __shfl_xor_sync(0xffffffffu, mx1, 2));
        float mn0 = fmaxf(m0, mx0), mn1 = fmaxf(m1, mx1);
        float rs0 = __expf(m0 - mn0), rs1 = __expf(m1 - mn1);
        m0 = mn0; m1 = mn1;

        uint32_t pH0[8], pH1[8];
        float s0 = 0.f, s1 = 0.f;
#pragma unroll
        for (int nt = 0; nt < 8; nt++) {
            float p0 = __expf(Sf[nt][0] - mn0);
            float p1 = __expf(Sf[nt][1] - mn0);
            float p2 = __expf(Sf[nt][2] - mn1);
            float p3 = __expf(Sf[nt][3] - mn1);
            s0 += p0 + p1; s1 += p2 + p3;
            pH0[nt] = pkh2(__float2half_rn(p0), __float2half_rn(p1));
            pH1[nt] = pkh2(__float2half_rn(p2), __float2half_rn(p3));
        }
        s0 += __shfl_xor_sync(0xffffffffu, s0, 1);
        s0 += __shfl_xor_sync(0xffffffffu, s0, 2);
        s1 += __shfl_xor_sync(0xffffffffu, s1, 1);
        s1 += __shfl_xor_sync(0xffffffffu, s1, 2);
        l0 = l0 * rs0 + s0;
        l1 = l1 * rs1 + s1;
#pragma unroll
        for (int nt = 0; nt < 8; nt++) {
            Of[nt][0] *= rs0; Of[nt][1] *= rs0;
            Of[nt][2] *= rs1; Of[nt][3] *= rs1;
        }

        // ---- O += pH*(vH + vL): hi pass over all dg, then lo pass ----
#pragma unroll
        for (int ks = 0; ks < 4; ks++) {
            uint32_t aH[4] = {pH0[2*ks], pH1[2*ks], pH0[2*ks+1], pH1[2*ks+1]};
#pragma unroll
            for (int dg = 0; dg < 4; dg++) {
                uint32_t vh_[4];
                ldsm_x4_t(vh_[0], vh_[1], vh_[2], vh_[3],
                          smem_u32(&st[2*64*QST + (ks*16 + lrow)*QST + dg*16 + lko]));
                mma2(Of[2*dg],   aH, vh_[0], vh_[1]);
                mma2(Of[2*dg+1], aH, vh_[2], vh_[3]);
            }
#pragma unroll
            for (int dg = 0; dg < 4; dg++) {
                uint32_t vl_[4];
                ldsm_x4_t(vl_[0], vl_[1], vl_[2], vl_[3],
                          smem_u32(&st[3*64*QST + (ks*16 + lrow)*QST + dg*16 + lko]));
                mma2(Of[2*dg],   aH, vl_[0], vl_[1]);
                mma2(Of[2*dg+1], aH, vl_[2], vl_[3]);
            }
        }

        __syncthreads();    // everyone done reading stage jt&1
        if (jt + 2 < 16) kvload((jt & 1) * STAGE_H, (jt + 2) * 64);
        else CPCOMMIT();    // keep wait_group invariant
    }

    // ---- normalize + store hi-only O to g_aoh [B,N,H*D] ----
    {
        float inv0 = 1.f / l0, inv1 = 1.f / l1;
        size_t base0 = ((size_t)b * NSEQ + r0g) * DIMM + h * HD + c2;
        size_t base1 = base0 + 8 * DIMM;
#pragma unroll
        for (int nt = 0; nt < 8; nt++) {
            *(__half2*)&g_aoh[base0 + nt*8] = __halves2half2(
                __float2half_rn(Of[nt][0] * inv0), __float2half_rn(Of[nt][1] * inv0));
            *(__half2*)&g_aoh[base1 + nt*8] = __halves2half2(
                __float2half_rn(Of[nt][2] * inv1), __float2half_rn(Of[nt][3] * inv1));
        }
    }
}

// ---------------------------------------------------------------------------
extern "C" void kernel_launch(void* const* d_in, const int* in_sizes, int n_in,
                              void* d_out, int out_size) {
    const float *x = nullptr, *pb = nullptr, *wq = nullptr, *wo = nullptr;
    for (int i = 0; i < n_in; i++) {
        switch (in_sizes[i]) {
            case 4194304: x  = (const float*)d_in[i]; break;  // x [8,1024,512]
            case 8388608: pb = (const float*)d_in[i]; break;  // pos_bias [8,1024,1024]
            case 786432:  wq = (const float*)d_in[i]; break;  // w_qkv [512,1536]
            case 262144:  wo = (const float*)d_in[i]; break;  // w_out [512,512]
        }
    }
    if (!x)  x  = (const float*)d_in[0];
    if (!pb) pb = (const float*)d_in[1];
    if (!wq) wq = (const float*)d_in[2];
    if (!wo) wo = (const float*)d_in[3];

    cudaFuncSetAttribute(k_attn_mma, cudaFuncAttributeMaxDynamicSharedMemorySize,
                         ATTN_SMEM);
    cudaFuncSetAttribute(gemm_mma<COLS3, true>,
                         cudaFuncAttributeMaxDynamicSharedMemorySize, GEMM_SMEM);
    cudaFuncSetAttribute(gemm_mma<DIMM, false>,
                         cudaFuncAttributeMaxDynamicSharedMemorySize, GEMM_SMEM);

    k_split<0><<<(MROWS*DIMM/4 + 255)/256, 256>>>(x,  MROWS*DIMM/4);
    k_split<1><<<(DIMM*COLS3/4 + 255)/256, 256>>>(wq, DIMM*COLS3/4);
    k_split<2><<<(DIMM*DIMM/4 + 255)/256, 256>>>(wo, DIMM*DIMM/4);

    gemm_mma<COLS3, true><<<dim3(12, 64), 256, GEMM_SMEM>>>(nullptr);
    k_attn_mma<<<dim3(BSZ, NH, 8), 256, ATTN_SMEM>>>(pb);
    gemm_mma<DIMM, false><<<dim3(4, 64), 256, GEMM_SMEM>>>((float*)d_out);
}

// round 14
// speedup vs baseline: 4.2828x; 1.2409x over previous
#include <cuda_runtime.h>
#include <cuda_fp16.h>
#include <math.h>
#include <stdint.h>

#define BSZ   8
#define NSEQ  1024
#define DIMM  512
#define NH    8
#define HD    64
#define COLS3 1536
#define MROWS (BSZ*NSEQ)

// Pre-split operands. q/k/v and x, attention output: fp16 hi only.
// Weights keep hi+lo (2-term GEMM split).
__device__ __align__(16) __half g_xh[MROWS*DIMM];
__device__ __align__(16) __half g_wqh[DIMM*COLS3], g_wql[DIMM*COLS3];
__device__ __align__(16) __half g_woh[DIMM*DIMM],  g_wol[DIMM*DIMM];
__device__ __align__(16) __half g_qh[MROWS*DIMM];
__device__ __align__(16) __half g_kh[MROWS*DIMM];
__device__ __align__(16) __half g_vh[MROWS*DIMM];
__device__ __align__(16) __half g_aoh[MROWS*DIMM];

// ---------------------------------------------------------------------------
// helpers
// ---------------------------------------------------------------------------
__device__ __forceinline__ uint32_t smem_u32(const void* p) {
    return (uint32_t)__cvta_generic_to_shared(p);
}
__device__ __forceinline__ void ldsm_x4(uint32_t& r0, uint32_t& r1,
                                        uint32_t& r2, uint32_t& r3, uint32_t a) {
    asm volatile("ldmatrix.sync.aligned.m8n8.x4.shared.b16 {%0,%1,%2,%3}, [%4];\n"
                 : "=r"(r0), "=r"(r1), "=r"(r2), "=r"(r3) : "r"(a));
}
__device__ __forceinline__ void ldsm_x4_t(uint32_t& r0, uint32_t& r1,
                                          uint32_t& r2, uint32_t& r3, uint32_t a) {
    asm volatile("ldmatrix.sync.aligned.m8n8.x4.trans.shared.b16 {%0,%1,%2,%3}, [%4];\n"
                 : "=r"(r0), "=r"(r1), "=r"(r2), "=r"(r3) : "r"(a));
}
__device__ __forceinline__ void mma2(float c[4], const uint32_t a[4],
                                     uint32_t b0, uint32_t b1) {
    asm volatile(
        "mma.sync.aligned.m16n8k16.row.col.f32.f16.f16.f32 "
        "{%0,%1,%2,%3}, {%4,%5,%6,%7}, {%8,%9}, {%0,%1,%2,%3};\n"
        : "+f"(c[0]), "+f"(c[1]), "+f"(c[2]), "+f"(c[3])
        : "r"(a[0]), "r"(a[1]), "r"(a[2]), "r"(a[3]), "r"(b0), "r"(b1));
}
__device__ __forceinline__ uint32_t pkh2(__half a, __half b) {
    __half2 t = __halves2half2(a, b);
    return *reinterpret_cast<uint32_t*>(&t);
}
#define CP16(dst, src) \
    asm volatile("cp.async.cg.shared.global [%0], [%1], 16;\n" :: "r"(dst), "l"(src))
#define CPCOMMIT() asm volatile("cp.async.commit_group;\n")
#define CPWAIT0()  asm volatile("cp.async.wait_group 0;\n")
#define CPWAIT1()  asm volatile("cp.async.wait_group 1;\n")

// ---------------------------------------------------------------------------
// fp32 -> fp16 split. SEL 0: x (hi only). SEL 1: w_qkv. SEL 2: w_out.
// ---------------------------------------------------------------------------
template<int SEL>
__global__ __launch_bounds__(256) void k_split(const float* __restrict__ s, int n4) {
    __half* hi = (SEL == 0) ? g_xh : (SEL == 1 ? g_wqh : g_woh);
    __half* lo = (SEL == 1) ? g_wql : g_wol;   // unused for SEL==0
    int i = blockIdx.x * blockDim.x + threadIdx.x;
    if (i >= n4) return;
    float4 v = ((const float4*)s)[i];
    float f[4] = {v.x, v.y, v.z, v.w};
    __half h[4], l[4];
#pragma unroll
    for (int e = 0; e < 4; e++) {
        h[e] = __float2half_rn(f[e]);
        l[e] = __float2half_rn(f[e] - __half2float(h[e]));
    }
    ((uint2*)hi)[i] = *(const uint2*)h;
    if (SEL != 0) ((uint2*)lo)[i] = *(const uint2*)l;
}

// ---------------------------------------------------------------------------
// GEMM (R12 structure, unchanged): A hi-only, B hi+lo, 3-stage ring, 2 CTAs/SM.
// QKV epilogue stores hi-only q/k/v (attention is pure fp16).
// ---------------------------------------------------------------------------
#define AST 40
#define BST 136
#define G_ASTAGE (128*AST)
#define G_BSTAGE (32*BST)
#define G_STAGE  (G_ASTAGE + 2*G_BSTAGE)     // 13824 halves = 27648 B
#define GEMM_SMEM (3 * G_STAGE * 2)          // 82944 B

template<int NC, bool QKV>
__global__ __launch_bounds__(256, 2) void gemm_mma(float* __restrict__ Og) {
    constexpr int KD = 512;
    extern __shared__ __half sg[];

    const int tid  = threadIdx.x;
    const int lane = tid & 31;
    const int wid  = tid >> 5;
    const int wm   = wid >> 2;
    const int wn   = wid & 3;
    const int row0 = blockIdx.y * 128;
    const int col0 = blockIdx.x * 128;
    const int lrow = lane & 15;
    const int lko  = (lane >> 4) * 8;

    float C[4][4][4];
#pragma unroll
    for (int i = 0; i < 4; i++)
#pragma unroll
        for (int j = 0; j < 4; j++)
#pragma unroll
            for (int e = 0; e < 4; e++) C[i][j][e] = 0.f;

    const __half* Ahg = QKV ? g_xh : g_aoh;
    const __half* bsrc[2] = {QKV ? g_wqh : g_woh, QKV ? g_wql : g_wol};

    auto prefetch = [&](int sbase, int kk) {
#pragma unroll
        for (int i = 0; i < 2; i++) {
            int cid = tid + 256 * i;
            int row = cid >> 2, ch = cid & 3;
            CP16(smem_u32(&sg[sbase + row * AST + ch * 8]),
                 Ahg + (size_t)(row0 + row) * KD + kk + ch * 8);
        }
#pragma unroll
        for (int i = 0; i < 4; i++) {
            int cid = tid + 256 * i;
            int arr = cid >> 9, rem = cid & 511;
            int row = rem >> 4, ch = rem & 15;
            CP16(smem_u32(&sg[sbase + G_ASTAGE + arr * G_BSTAGE + row * BST + ch * 8]),
                 bsrc[arr] + (size_t)(kk + row) * NC + col0 + ch * 8);
        }
        CPCOMMIT();
    };

    prefetch(0, 0);
    prefetch(G_STAGE, 32);

    for (int kc = 0; kc < KD / 32; kc++) {
        CPWAIT1();
        __syncthreads();
        if (kc + 2 < KD / 32) prefetch(((kc + 2) % 3) * G_STAGE, (kc + 2) * 32);
        else CPCOMMIT();

        const __half* Ahs = sg + (kc % 3) * G_STAGE;
        const __half* Bhs = Ahs + G_ASTAGE;
        const __half* Bls = Bhs + G_BSTAGE;

#pragma unroll
        for (int kq = 0; kq < 32; kq += 16) {
            uint32_t aH[4][4];
#pragma unroll
            for (int mt = 0; mt < 4; mt++) {
                int r = wm * 64 + mt * 16 + lrow;
                ldsm_x4(aH[mt][0], aH[mt][1], aH[mt][2], aH[mt][3],
                        smem_u32(&Ahs[r * AST + kq + lko]));
            }
            int rr = kq + lrow;
#pragma unroll
            for (int ng = 0; ng < 2; ng++) {
                uint32_t bH[4];
                int cb = wn * 32 + ng * 16 + lko;
                ldsm_x4_t(bH[0], bH[1], bH[2], bH[3], smem_u32(&Bhs[rr * BST + cb]));
#pragma unroll
                for (int mt = 0; mt < 4; mt++)
                    mma2(C[mt][ng*2],     aH[mt], bH[0], bH[1]);
#pragma unroll
                for (int mt = 0; mt < 4; mt++)
                    mma2(C[mt][ng*2 + 1], aH[mt], bH[2], bH[3]);
            }
#pragma unroll
            for (int ng = 0; ng < 2; ng++) {
                uint32_t bL[4];
                int cb = wn * 32 + ng * 16 + lko;
                ldsm_x4_t(bL[0], bL[1], bL[2], bL[3], smem_u32(&Bls[rr * BST + cb]));
#pragma unroll
                for (int mt = 0; mt < 4; mt++)
                    mma2(C[mt][ng*2],     aH[mt], bL[0], bL[1]);
#pragma unroll
                for (int mt = 0; mt < 4; mt++)
                    mma2(C[mt][ng*2 + 1], aH[mt], bL[2], bL[3]);
            }
        }
    }

    const int g  = lane >> 2;
    const int cc = (lane & 3) * 2;
    if (QKV) {
        const int sec     = col0 >> 9;
        const int rembase = (col0 & 511) + wn * 32;
        __half* dsth = (sec == 0) ? g_qh : (sec == 1 ? g_kh : g_vh);
        const float LOG2B = 13.287712379549449f;
#pragma unroll
        for (int nt = 0; nt < 4; nt++) {
            int rem   = rembase + nt * 8 + cc;
            int h     = rem >> 6;
            int dbase = rem & 63;
            float ifr = exp2f(-(float)dbase * (LOG2B / 64.f));
#pragma unroll
            for (int mt = 0; mt < 4; mt++) {
#pragma unroll
                for (int hf = 0; hf < 2; hf++) {
                    int R = row0 + wm * 64 + mt * 16 + g + hf * 8;
                    int b = R >> 10, n = R & 1023;
                    float v0 = C[mt][nt][hf*2 + 0];
                    float v1 = C[mt][nt][hf*2 + 1];
                    if (sec == 0) { v0 *= 0.125f; v1 *= 0.125f; }
                    if (sec < 2) {
                        float s, co;
                        sincosf((float)n * ifr, &s, &co);
                        float t0 = v0 * co - v1 * s;
                        float t1 = v1 * co + v0 * s;
                        v0 = t0; v1 = t1;
                    }
                    size_t idx = (((size_t)b * NH + h) * NSEQ + n) * HD + dbase;
                    *(__half2*)&dsth[idx] = __halves2half2(
                        __float2half_rn(v0), __float2half_rn(v1));
                }
            }
        }
    } else {
#pragma unroll
        for (int nt = 0; nt < 4; nt++) {
            int colg = col0 + wn * 32 + nt * 8 + cc;
#pragma unroll
            for (int mt = 0; mt < 4; mt++) {
#pragma unroll
                for (int hf = 0; hf < 2; hf++) {
                    int R = row0 + wm * 64 + mt * 16 + g + hf * 8;
                    *(float2*)&Og[(size_t)R * NC + colg] =
                        make_float2(C[mt][nt][hf*2], C[mt][nt][hf*2 + 1]);
                }
            }
        }
    }
}

// ---------------------------------------------------------------------------
// Flash attention, pure fp16 operands: S = qH*kH, PV = pH*vH.
// 2 CTAs/SM, 2-stage KV ring (stage = Kh + Vh = 18432 B).
// ---------------------------------------------------------------------------
#define QST 72
#define STAGE_H (2 * 64 * QST)           // Kh + Vh per stage
#define ATTN_SMEM (2 * STAGE_H * 2)      // 36864 B

__global__ __launch_bounds__(256, 2) void k_attn_mma(const float* __restrict__ bias) {
    extern __shared__ __half sm[];

    const int b  = blockIdx.x;      // fastest: batches share bias slice in L2
    const int h  = blockIdx.y;
    const int i0 = blockIdx.z * 128;
    const int tid = threadIdx.x, lane = tid & 31, w = tid >> 5;
    const int lrow = lane & 15, lko = (lane >> 4) * 8;
    const int g = lane >> 2, c2 = (lane & 3) * 2;

    const size_t bh = (size_t)(b * NH + h) * NSEQ * HD;
    const __half* kv_src[2] = {g_kh + bh, g_vh + bh};
    const float* bg = bias + (size_t)h * NSEQ * NSEQ;

    // ---- stage Q-hi through stage0, extract fragments ----
    {
        const __half* qh = g_qh + bh;
#pragma unroll
        for (int i = 0; i < 4; i++) {
            int cid = tid + 256 * i;            // 1024 chunks: 128 rows x 8
            int row = cid >> 3, ch = cid & 7;
            CP16(smem_u32(&sm[row * QST + ch * 8]),
                 qh + (size_t)(i0 + row) * HD + ch * 8);
        }
        CPCOMMIT();
        CPWAIT0();
        __syncthreads();
    }
    uint32_t qH[4][4];
#pragma unroll
    for (int ks = 0; ks < 4; ks++)
        ldsm_x4(qH[ks][0], qH[ks][1], qH[ks][2], qH[ks][3],
                smem_u32(&sm[(w*16 + lrow)*QST + ks*16 + lko]));
    __syncthreads();

    auto kvload = [&](int sbase, int j0) {
#pragma unroll
        for (int i = 0; i < 4; i++) {
            int cid = tid + 256 * i;            // 1024 chunks: 2 arr x 64 r x 8
            int arr = cid >> 9;
            int rem = cid & 511;
            int row = rem >> 3, ch = rem & 7;
            CP16(smem_u32(&sm[sbase + arr * 64 * QST + row * QST + ch * 8]),
                 kv_src[arr] + (size_t)(j0 + row) * HD + ch * 8);
        }
        CPCOMMIT();
    };

    kvload(0, 0);
    kvload(STAGE_H, 64);

    float Of[8][4];
#pragma unroll
    for (int nt = 0; nt < 8; nt++)
#pragma unroll
        for (int e = 0; e < 4; e++) Of[nt][e] = 0.f;
    float m0 = -INFINITY, m1 = -INFINITY, l0 = 0.f, l1 = 0.f;
    const int r0g = i0 + w * 16 + g;

    for (int jt = 0; jt < 16; jt++) {
        CPWAIT1();
        __syncthreads();
        const __half* st = sm + (jt & 1) * STAGE_H;
        const int j0 = jt * 64;

        // bias prefetch (long-latency LDGs before the MMA burst)
        float2 bu[8], bw[8];
        {
            const float* bp0 = bg + (size_t)r0g * NSEQ + j0 + c2;
            const float* bp1 = bp0 + 8 * NSEQ;
#pragma unroll
            for (int nt = 0; nt < 8; nt++) {
                bu[nt] = *(const float2*)(bp0 + nt * 8);
                bw[nt] = *(const float2*)(bp1 + nt * 8);
            }
        }

        // ---- S = qH * kH ----
        float Sf[8][4];
#pragma unroll
        for (int nt = 0; nt < 8; nt++)
#pragma unroll
            for (int e = 0; e < 4; e++) Sf[nt][e] = 0.f;
#pragma unroll
        for (int ks = 0; ks < 4; ks++) {
#pragma unroll
            for (int ng = 0; ng < 4; ng++) {
                uint32_t kh_[4];
                ldsm_x4(kh_[0], kh_[1], kh_[2], kh_[3],
                        smem_u32(&st[(ng*16 + lrow)*QST + ks*16 + lko]));
                mma2(Sf[2*ng],   qH[ks], kh_[0], kh_[2]);
                mma2(Sf[2*ng+1], qH[ks], kh_[1], kh_[3]);
            }
        }
#pragma unroll
        for (int nt = 0; nt < 8; nt++) {
            Sf[nt][0] += bu[nt].x; Sf[nt][1] += bu[nt].y;
            Sf[nt][2] += bw[nt].x; Sf[nt][3] += bw[nt].y;
        }

        // ---- online softmax ----
        float mx0 = -INFINITY, mx1 = -INFINITY;
#pragma unroll
        for (int nt = 0; nt < 8; nt++) {
            mx0 = fmaxf(mx0, fmaxf(Sf[nt][0], Sf[nt][1]));
            mx1 = fmaxf(mx1, fmaxf(Sf[nt][2], Sf[nt][3]));
        }
        mx0 = fmaxf(mx0, __shfl_xor_sync(0xffffffffu, mx0, 1));
        mx0 = fmaxf(mx0, __shfl_xor_sync(0xffffffffu, mx0, 2));
        mx1 = fmaxf(mx1, __shfl_xor_sync(0xffffffffu, mx1, 1));
        mx1 = fmaxf(mx1, __shfl_xor_sync(0xffffffffu, mx1, 2));
        float mn0 = fmaxf(m0, mx0), mn1 = fmaxf(m1, mx1);
        float rs0 = __expf(m0 - mn0), rs1 = __expf(m1 - mn1);
        m0 = mn0; m1 = mn1;

        uint32_t pH0[8], pH1[8];
        float s0 = 0.f, s1 = 0.f;
#pragma unroll
        for (int nt = 0; nt < 8; nt++) {
            float p0 = __expf(Sf[nt][0] - mn0);
            float p1 = __expf(Sf[nt][1] - mn0);
            float p2 = __expf(Sf[nt][2] - mn1);
            float p3 = __expf(Sf[nt][3] - mn1);
            s0 += p0 + p1; s1 += p2 + p3;
            pH0[nt] = pkh2(__float2half_rn(p0), __float2half_rn(p1));
            pH1[nt] = pkh2(__float2half_rn(p2), __float2half_rn(p3));
        }
        s0 += __shfl_xor_sync(0xffffffffu, s0, 1);
        s0 += __shfl_xor_sync(0xffffffffu, s0, 2);
        s1 += __shfl_xor_sync(0xffffffffu, s1, 1);
        s1 += __shfl_xor_sync(0xffffffffu, s1, 2);
        l0 = l0 * rs0 + s0;
        l1 = l1 * rs1 + s1;
#pragma unroll
        for (int nt = 0; nt < 8; nt++) {
            Of[nt][0] *= rs0; Of[nt][1] *= rs0;
            Of[nt][2] *= rs1; Of[nt][3] *= rs1;
        }

        // ---- O += pH * vH ----
#pragma unroll
        for (int ks = 0; ks < 4; ks++) {
            uint32_t aH[4] = {pH0[2*ks], pH1[2*ks], pH0[2*ks+1], pH1[2*ks+1]};
#pragma unroll
            for (int dg = 0; dg < 4; dg++) {
                uint32_t vh_[4];
                ldsm_x4_t(vh_[0], vh_[1], vh_[2], vh_[3],
                          smem_u32(&st[64*QST + (ks*16 + lrow)*QST + dg*16 + lko]));
                mma2(Of[2*dg],   aH, vh_[0], vh_[1]);
                mma2(Of[2*dg+1], aH, vh_[2], vh_[3]);
            }
        }

        __syncthreads();    // everyone done reading stage jt&1
        if (jt + 2 < 16) kvload((jt & 1) * STAGE_H, (jt + 2) * 64);
        else CPCOMMIT();    // keep wait_group invariant
    }

    // ---- normalize + store hi-only O to g_aoh [B,N,H*D] ----
    {
        float inv0 = 1.f / l0, inv1 = 1.f / l1;
        size_t base0 = ((size_t)b * NSEQ + r0g) * DIMM + h * HD + c2;
        size_t base1 = base0 + 8 * DIMM;
#pragma unroll
        for (int nt = 0; nt < 8; nt++) {
            *(__half2*)&g_aoh[base0 + nt*8] = __halves2half2(
                __float2half_rn(Of[nt][0] * inv0), __float2half_rn(Of[nt][1] * inv0));
            *(__half2*)&g_aoh[base1 + nt*8] = __halves2half2(
                __float2half_rn(Of[nt][2] * inv1), __float2half_rn(Of[nt][3] * inv1));
        }
    }
}

// ---------------------------------------------------------------------------
extern "C" void kernel_launch(void* const* d_in, const int* in_sizes, int n_in,
                              void* d_out, int out_size) {
    const float *x = nullptr, *pb = nullptr, *wq = nullptr, *wo = nullptr;
    for (int i = 0; i < n_in; i++) {
        switch (in_sizes[i]) {
            case 4194304: x  = (const float*)d_in[i]; break;  // x [8,1024,512]
            case 8388608: pb = (const float*)d_in[i]; break;  // pos_bias [8,1024,1024]
            case 786432:  wq = (const float*)d_in[i]; break;  // w_qkv [512,1536]
            case 262144:  wo = (const float*)d_in[i]; break;  // w_out [512,512]
        }
    }
    if (!x)  x  = (const float*)d_in[0];
    if (!pb) pb = (const float*)d_in[1];
    if (!wq) wq = (const float*)d_in[2];
    if (!wo) wo = (const float*)d_in[3];

    cudaFuncSetAttribute(k_attn_mma, cudaFuncAttributeMaxDynamicSharedMemorySize,
                         ATTN_SMEM);
    cudaFuncSetAttribute(gemm_mma<COLS3, true>,
                         cudaFuncAttributeMaxDynamicSharedMemorySize, GEMM_SMEM);
    cudaFuncSetAttribute(gemm_mma<DIMM, false>,
                         cudaFuncAttributeMaxDynamicSharedMemorySize, GEMM_SMEM);

    k_split<0><<<(MROWS*DIMM/4 + 255)/256, 256>>>(x,  MROWS*DIMM/4);
    k_split<1><<<(DIMM*COLS3/4 + 255)/256, 256>>>(wq, DIMM*COLS3/4);
    k_split<2><<<(DIMM*DIMM/4 + 255)/256, 256>>>(wo, DIMM*DIMM/4);

    gemm_mma<COLS3, true><<<dim3(12, 64), 256, GEMM_SMEM>>>(nullptr);
    k_attn_mma<<<dim3(BSZ, NH, 8), 256, ATTN_SMEM>>>(pb);
    gemm_mma<DIMM, false><<<dim3(4, 64), 256, GEMM_SMEM>>>((float*)d_out);
}

// round 15
// speedup vs baseline: 5.2732x; 1.2313x over previous
#include <cuda_runtime.h>
#include <cuda_fp16.h>
#include <math.h>
#include <stdint.h>

#define BSZ   8
#define NSEQ  1024
#define DIMM  512
#define NH    8
#define HD    64
#define COLS3 1536
#define MROWS (BSZ*NSEQ)

// All operands pure fp16 (fp32 accumulation everywhere).
__device__ __align__(16) __half g_xh[MROWS*DIMM];
__device__ __align__(16) __half g_wqh[DIMM*COLS3];
__device__ __align__(16) __half g_woh[DIMM*DIMM];
__device__ __align__(16) __half g_qh[MROWS*DIMM];
__device__ __align__(16) __half g_kh[MROWS*DIMM];
__device__ __align__(16) __half g_vh[MROWS*DIMM];
__device__ __align__(16) __half g_aoh[MROWS*DIMM];

// ---------------------------------------------------------------------------
// helpers
// ---------------------------------------------------------------------------
__device__ __forceinline__ uint32_t smem_u32(const void* p) {
    return (uint32_t)__cvta_generic_to_shared(p);
}
__device__ __forceinline__ void ldsm_x4(uint32_t& r0, uint32_t& r1,
                                        uint32_t& r2, uint32_t& r3, uint32_t a) {
    asm volatile("ldmatrix.sync.aligned.m8n8.x4.shared.b16 {%0,%1,%2,%3}, [%4];\n"
                 : "=r"(r0), "=r"(r1), "=r"(r2), "=r"(r3) : "r"(a));
}
__device__ __forceinline__ void ldsm_x4_t(uint32_t& r0, uint32_t& r1,
                                          uint32_t& r2, uint32_t& r3, uint32_t a) {
    asm volatile("ldmatrix.sync.aligned.m8n8.x4.trans.shared.b16 {%0,%1,%2,%3}, [%4];\n"
                 : "=r"(r0), "=r"(r1), "=r"(r2), "=r"(r3) : "r"(a));
}
__device__ __forceinline__ void mma2(float c[4], const uint32_t a[4],
                                     uint32_t b0, uint32_t b1) {
    asm volatile(
        "mma.sync.aligned.m16n8k16.row.col.f32.f16.f16.f32 "
        "{%0,%1,%2,%3}, {%4,%5,%6,%7}, {%8,%9}, {%0,%1,%2,%3};\n"
        : "+f"(c[0]), "+f"(c[1]), "+f"(c[2]), "+f"(c[3])
        : "r"(a[0]), "r"(a[1]), "r"(a[2]), "r"(a[3]), "r"(b0), "r"(b1));
}
__device__ __forceinline__ uint32_t pkh2(__half a, __half b) {
    __half2 t = __halves2half2(a, b);
    return *reinterpret_cast<uint32_t*>(&t);
}
#define CP16(dst, src) \
    asm volatile("cp.async.cg.shared.global [%0], [%1], 16;\n" :: "r"(dst), "l"(src))
#define CPCOMMIT() asm volatile("cp.async.commit_group;\n")
#define CPWAIT0()  asm volatile("cp.async.wait_group 0;\n")
#define CPWAIT1()  asm volatile("cp.async.wait_group 1;\n")

// ---------------------------------------------------------------------------
// fp32 -> fp16 (hi only). SEL 0: x. SEL 1: w_qkv. SEL 2: w_out.
// ---------------------------------------------------------------------------
template<int SEL>
__global__ __launch_bounds__(256) void k_split(const float* __restrict__ s, int n4) {
    __half* hi = (SEL == 0) ? g_xh : (SEL == 1 ? g_wqh : g_woh);
    int i = blockIdx.x * blockDim.x + threadIdx.x;
    if (i >= n4) return;
    float4 v = ((const float4*)s)[i];
    __half h[4] = {__float2half_rn(v.x), __float2half_rn(v.y),
                   __float2half_rn(v.z), __float2half_rn(v.w)};
    ((uint2*)hi)[i] = *(const uint2*)h;
}

// ---------------------------------------------------------------------------
// GEMM: pure fp16 operands, fp32 accum. 128x128 block, 8 warps (2x4),
// KC=32, 3-stage cp.async ring, 2 CTAs/SM.
// ---------------------------------------------------------------------------
#define AST 40
#define BST 136
#define G_ASTAGE (128*AST)
#define G_BSTAGE (32*BST)
#define G_STAGE  (G_ASTAGE + G_BSTAGE)       // 9472 halves = 18944 B
#define GEMM_SMEM (3 * G_STAGE * 2)          // 56832 B

template<int NC, bool QKV>
__global__ __launch_bounds__(256, 2) void gemm_mma(float* __restrict__ Og) {
    constexpr int KD = 512;
    extern __shared__ __half sg[];

    const int tid  = threadIdx.x;
    const int lane = tid & 31;
    const int wid  = tid >> 5;
    const int wm   = wid >> 2;
    const int wn   = wid & 3;
    const int row0 = blockIdx.y * 128;
    const int col0 = blockIdx.x * 128;
    const int lrow = lane & 15;
    const int lko  = (lane >> 4) * 8;

    float C[4][4][4];
#pragma unroll
    for (int i = 0; i < 4; i++)
#pragma unroll
        for (int j = 0; j < 4; j++)
#pragma unroll
            for (int e = 0; e < 4; e++) C[i][j][e] = 0.f;

    const __half* Ahg = QKV ? g_xh : g_aoh;
    const __half* Bhg = QKV ? g_wqh : g_woh;

    auto prefetch = [&](int sbase, int kk) {
#pragma unroll
        for (int i = 0; i < 2; i++) {          // A: 512 chunks of 16B
            int cid = tid + 256 * i;
            int row = cid >> 2, ch = cid & 3;
            CP16(smem_u32(&sg[sbase + row * AST + ch * 8]),
                 Ahg + (size_t)(row0 + row) * KD + kk + ch * 8);
        }
#pragma unroll
        for (int i = 0; i < 2; i++) {          // B: 512 chunks of 16B
            int cid = tid + 256 * i;
            int row = cid >> 4, ch = cid & 15;
            CP16(smem_u32(&sg[sbase + G_ASTAGE + row * BST + ch * 8]),
                 Bhg + (size_t)(kk + row) * NC + col0 + ch * 8);
        }
        CPCOMMIT();
    };

    prefetch(0, 0);
    prefetch(G_STAGE, 32);

    for (int kc = 0; kc < KD / 32; kc++) {
        CPWAIT1();
        __syncthreads();
        if (kc + 2 < KD / 32) prefetch(((kc + 2) % 3) * G_STAGE, (kc + 2) * 32);
        else CPCOMMIT();

        const __half* Ahs = sg + (kc % 3) * G_STAGE;
        const __half* Bhs = Ahs + G_ASTAGE;

#pragma unroll
        for (int kq = 0; kq < 32; kq += 16) {
            uint32_t aH[4][4];
#pragma unroll
            for (int mt = 0; mt < 4; mt++) {
                int r = wm * 64 + mt * 16 + lrow;
                ldsm_x4(aH[mt][0], aH[mt][1], aH[mt][2], aH[mt][3],
                        smem_u32(&Ahs[r * AST + kq + lko]));
            }
            int rr = kq + lrow;
#pragma unroll
            for (int ng = 0; ng < 2; ng++) {
                uint32_t bH[4];
                int cb = wn * 32 + ng * 16 + lko;
                ldsm_x4_t(bH[0], bH[1], bH[2], bH[3], smem_u32(&Bhs[rr * BST + cb]));
#pragma unroll
                for (int mt = 0; mt < 4; mt++)
                    mma2(C[mt][ng*2],     aH[mt], bH[0], bH[1]);
#pragma unroll
                for (int mt = 0; mt < 4; mt++)
                    mma2(C[mt][ng*2 + 1], aH[mt], bH[2], bH[3]);
            }
        }
    }

    const int g  = lane >> 2;
    const int cc = (lane & 3) * 2;
    if (QKV) {
        const int sec     = col0 >> 9;
        const int rembase = (col0 & 511) + wn * 32;
        __half* dsth = (sec == 0) ? g_qh : (sec == 1 ? g_kh : g_vh);
        const float LOG2B = 13.287712379549449f;
#pragma unroll
        for (int nt = 0; nt < 4; nt++) {
            int rem   = rembase + nt * 8 + cc;
            int h     = rem >> 6;
            int dbase = rem & 63;
            float ifr = exp2f(-(float)dbase * (LOG2B / 64.f));
#pragma unroll
            for (int mt = 0; mt < 4; mt++) {
#pragma unroll
                for (int hf = 0; hf < 2; hf++) {
                    int R = row0 + wm * 64 + mt * 16 + g + hf * 8;
                    int b = R >> 10, n = R & 1023;
                    float v0 = C[mt][nt][hf*2 + 0];
                    float v1 = C[mt][nt][hf*2 + 1];
                    if (sec == 0) { v0 *= 0.125f; v1 *= 0.125f; }
                    if (sec < 2) {
                        float s, co;
                        sincosf((float)n * ifr, &s, &co);
                        float t0 = v0 * co - v1 * s;
                        float t1 = v1 * co + v0 * s;
                        v0 = t0; v1 = t1;
                    }
                    size_t idx = (((size_t)b * NH + h) * NSEQ + n) * HD + dbase;
                    *(__half2*)&dsth[idx] = __halves2half2(
                        __float2half_rn(v0), __float2half_rn(v1));
                }
            }
        }
    } else {
#pragma unroll
        for (int nt = 0; nt < 4; nt++) {
            int colg = col0 + wn * 32 + nt * 8 + cc;
#pragma unroll
            for (int mt = 0; mt < 4; mt++) {
#pragma unroll
                for (int hf = 0; hf < 2; hf++) {
                    int R = row0 + wm * 64 + mt * 16 + g + hf * 8;
                    *(float2*)&Og[(size_t)R * NC + colg] =
                        make_float2(C[mt][nt][hf*2], C[mt][nt][hf*2 + 1]);
                }
            }
        }
    }
}

// ---------------------------------------------------------------------------
// Flash attention (R14 structure, unchanged): pure fp16, 2 CTAs/SM,
// 2-stage KV ring.
// ---------------------------------------------------------------------------
#define QST 72
#define STAGE_H (2 * 64 * QST)           // Kh + Vh per stage
#define ATTN_SMEM (2 * STAGE_H * 2)      // 36864 B

__global__ __launch_bounds__(256, 2) void k_attn_mma(const float* __restrict__ bias) {
    extern __shared__ __half sm[];

    const int b  = blockIdx.x;
    const int h  = blockIdx.y;
    const int i0 = blockIdx.z * 128;
    const int tid = threadIdx.x, lane = tid & 31, w = tid >> 5;
    const int lrow = lane & 15, lko = (lane >> 4) * 8;
    const int g = lane >> 2, c2 = (lane & 3) * 2;

    const size_t bh = (size_t)(b * NH + h) * NSEQ * HD;
    const __half* kv_src[2] = {g_kh + bh, g_vh + bh};
    const float* bg = bias + (size_t)h * NSEQ * NSEQ;

    {
        const __half* qh = g_qh + bh;
#pragma unroll
        for (int i = 0; i < 4; i++) {
            int cid = tid + 256 * i;
            int row = cid >> 3, ch = cid & 7;
            CP16(smem_u32(&sm[row * QST + ch * 8]),
                 qh + (size_t)(i0 + row) * HD + ch * 8);
        }
        CPCOMMIT();
        CPWAIT0();
        __syncthreads();
    }
    uint32_t qH[4][4];
#pragma unroll
    for (int ks = 0; ks < 4; ks++)
        ldsm_x4(qH[ks][0], qH[ks][1], qH[ks][2], qH[ks][3],
                smem_u32(&sm[(w*16 + lrow)*QST + ks*16 + lko]));
    __syncthreads();

    auto kvload = [&](int sbase, int j0) {
#pragma unroll
        for (int i = 0; i < 4; i++) {
            int cid = tid + 256 * i;
            int arr = cid >> 9;
            int rem = cid & 511;
            int row = rem >> 3, ch = rem & 7;
            CP16(smem_u32(&sm[sbase + arr * 64 * QST + row * QST + ch * 8]),
                 kv_src[arr] + (size_t)(j0 + row) * HD + ch * 8);
        }
        CPCOMMIT();
    };

    kvload(0, 0);
    kvload(STAGE_H, 64);

    float Of[8][4];
#pragma unroll
    for (int nt = 0; nt < 8; nt++)
#pragma unroll
        for (int e = 0; e < 4; e++) Of[nt][e] = 0.f;
    float m0 = -INFINITY, m1 = -INFINITY, l0 = 0.f, l1 = 0.f;
    const int r0g = i0 + w * 16 + g;

    for (int jt = 0; jt < 16; jt++) {
        CPWAIT1();
        __syncthreads();
        const __half* st = sm + (jt & 1) * STAGE_H;
        const int j0 = jt * 64;

        float2 bu[8], bw[8];
        {
            const float* bp0 = bg + (size_t)r0g * NSEQ + j0 + c2;
            const float* bp1 = bp0 + 8 * NSEQ;
#pragma unroll
            for (int nt = 0; nt < 8; nt++) {
                bu[nt] = *(const float2*)(bp0 + nt * 8);
                bw[nt] = *(const float2*)(bp1 + nt * 8);
            }
        }

        float Sf[8][4];
#pragma unroll
        for (int nt = 0; nt < 8; nt++)
#pragma unroll
            for (int e = 0; e < 4; e++) Sf[nt][e] = 0.f;
#pragma unroll
        for (int ks = 0; ks < 4; ks++) {
#pragma unroll
            for (int ng = 0; ng < 4; ng++) {
                uint32_t kh_[4];
                ldsm_x4(kh_[0], kh_[1], kh_[2], kh_[3],
                        smem_u32(&st[(ng*16 + lrow)*QST + ks*16 + lko]));
                mma2(Sf[2*ng],   qH[ks], kh_[0], kh_[2]);
                mma2(Sf[2*ng+1], qH[ks], kh_[1], kh_[3]);
            }
        }
#pragma unroll
        for (int nt = 0; nt < 8; nt++) {
            Sf[nt][0] += bu[nt].x; Sf[nt][1] += bu[nt].y;
            Sf[nt][2] += bw[nt].x; Sf[nt][3] += bw[nt].y;
        }

        float mx0 = -INFINITY, mx1 = -INFINITY;
#pragma unroll
        for (int nt = 0; nt < 8; nt++) {
            mx0 = fmaxf(mx0, fmaxf(Sf[nt][0], Sf[nt][1]));
            mx1 = fmaxf(mx1, fmaxf(Sf[nt][2], Sf[nt][3]));
        }
        mx0 = fmaxf(mx0, __shfl_xor_sync(0xffffffffu, mx0, 1));
        mx0 = fmaxf(mx0, __shfl_xor_sync(0xffffffffu, mx0, 2));
        mx1 = fmaxf(mx1, __shfl_xor_sync(0xffffffffu, mx1, 1));
        mx1 = fmaxf(mx1, __shfl_xor_sync(0xffffffffu, mx1, 2));
        float mn0 = fmaxf(m0, mx0), mn1 = fmaxf(m1, mx1);
        float rs0 = __expf(m0 - mn0), rs1 = __expf(m1 - mn1);
        m0 = mn0; m1 = mn1;

        uint32_t pH0[8], pH1[8];
        float s0 = 0.f, s1 = 0.f;
#pragma unroll
        for (int nt = 0; nt < 8; nt++) {
            float p0 = __expf(Sf[nt][0] - mn0);
            float p1 = __expf(Sf[nt][1] - mn0);
            float p2 = __expf(Sf[nt][2] - mn1);
            float p3 = __expf(Sf[nt][3] - mn1);
            s0 += p0 + p1; s1 += p2 + p3;
            pH0[nt] = pkh2(__float2half_rn(p0), __float2half_rn(p1));
            pH1[nt] = pkh2(__float2half_rn(p2), __float2half_rn(p3));
        }
        s0 += __shfl_xor_sync(0xffffffffu, s0, 1);
        s0 += __shfl_xor_sync(0xffffffffu, s0, 2);
        s1 += __shfl_xor_sync(0xffffffffu, s1, 1);
        s1 += __shfl_xor_sync(0xffffffffu, s1, 2);
        l0 = l0 * rs0 + s0;
        l1 = l1 * rs1 + s1;
#pragma unroll
        for (int nt = 0; nt < 8; nt++) {
            Of[nt][0] *= rs0; Of[nt][1] *= rs0;
            Of[nt][2] *= rs1; Of[nt][3] *= rs1;
        }

#pragma unroll
        for (int ks = 0; ks < 4; ks++) {
            uint32_t aH[4] = {pH0[2*ks], pH1[2*ks], pH0[2*ks+1], pH1[2*ks+1]};
#pragma unroll
            for (int dg = 0; dg < 4; dg++) {
                uint32_t vh_[4];
                ldsm_x4_t(vh_[0], vh_[1], vh_[2], vh_[3],
                          smem_u32(&st[64*QST + (ks*16 + lrow)*QST + dg*16 + lko]));
                mma2(Of[2*dg],   aH, vh_[0], vh_[1]);
                mma2(Of[2*dg+1], aH, vh_[2], vh_[3]);
            }
        }

        __syncthreads();
        if (jt + 2 < 16) kvload((jt & 1) * STAGE_H, (jt + 2) * 64);
        else CPCOMMIT();
    }

    {
        float inv0 = 1.f / l0, inv1 = 1.f / l1;
        size_t base0 = ((size_t)b * NSEQ + r0g) * DIMM + h * HD + c2;
        size_t base1 = base0 + 8 * DIMM;
#pragma unroll
        for (int nt = 0; nt < 8; nt++) {
            *(__half2*)&g_aoh[base0 + nt*8] = __halves2half2(
                __float2half_rn(Of[nt][0] * inv0), __float2half_rn(Of[nt][1] * inv0));
            *(__half2*)&g_aoh[base1 + nt*8] = __halves2half2(
                __float2half_rn(Of[nt][2] * inv1), __float2half_rn(Of[nt][3] * inv1));
        }
    }
}

// ---------------------------------------------------------------------------
extern "C" void kernel_launch(void* const* d_in, const int* in_sizes, int n_in,
                              void* d_out, int out_size) {
    const float *x = nullptr, *pb = nullptr, *wq = nullptr, *wo = nullptr;
    for (int i = 0; i < n_in; i++) {
        switch (in_sizes[i]) {
            case 4194304: x  = (const float*)d_in[i]; break;  // x [8,1024,512]
            case 8388608: pb = (const float*)d_in[i]; break;  // pos_bias [8,1024,1024]
            case 786432:  wq = (const float*)d_in[i]; break;  // w_qkv [512,1536]
            case 262144:  wo = (const float*)d_in[i]; break;  // w_out [512,512]
        }
    }
    if (!x)  x  = (const float*)d_in[0];
    if (!pb) pb = (const float*)d_in[1];
    if (!wq) wq = (const float*)d_in[2];
    if (!wo) wo = (const float*)d_in[3];

    cudaFuncSetAttribute(k_attn_mma, cudaFuncAttributeMaxDynamicSharedMemorySize,
                         ATTN_SMEM);
    cudaFuncSetAttribute(gemm_mma<COLS3, true>,
                         cudaFuncAttributeMaxDynamicSharedMemorySize, GEMM_SMEM);
    cudaFuncSetAttribute(gemm_mma<DIMM, false>,
                         cudaFuncAttributeMaxDynamicSharedMemorySize, GEMM_SMEM);

    k_split<0><<<(MROWS*DIMM/4 + 255)/256, 256>>>(x,  MROWS*DIMM/4);
    k_split<1><<<(DIMM*COLS3/4 + 255)/256, 256>>>(wq, DIMM*COLS3/4);
    k_split<2><<<(DIMM*DIMM/4 + 255)/256, 256>>>(wo, DIMM*DIMM/4);

    gemm_mma<COLS3, true><<<dim3(12, 64), 256, GEMM_SMEM>>>(nullptr);
    k_attn_mma<<<dim3(BSZ, NH, 8), 256, ATTN_SMEM>>>(pb);
    gemm_mma<DIMM, false><<<dim3(4, 64), 256, GEMM_SMEM>>>((float*)d_out);
}

// round 16
// speedup vs baseline: 5.4215x; 1.0281x over previous
#include <cuda_runtime.h>
#include <cuda_fp16.h>
#include <math.h>
#include <stdint.h>

#define BSZ   8
#define NSEQ  1024
#define DIMM  512
#define NH    8
#define HD    64
#define COLS3 1536
#define MROWS (BSZ*NSEQ)

// All operands pure fp16 (fp32 accumulation everywhere).
__device__ __align__(16) __half g_xh[MROWS*DIMM];
__device__ __align__(16) __half g_wqh[DIMM*COLS3];
__device__ __align__(16) __half g_woh[DIMM*DIMM];
__device__ __align__(16) __half g_qh[MROWS*DIMM];
__device__ __align__(16) __half g_kh[MROWS*DIMM];
__device__ __align__(16) __half g_vh[MROWS*DIMM];
__device__ __align__(16) __half g_aoh[MROWS*DIMM];

// ---------------------------------------------------------------------------
// helpers
// ---------------------------------------------------------------------------
__device__ __forceinline__ uint32_t smem_u32(const void* p) {
    return (uint32_t)__cvta_generic_to_shared(p);
}
__device__ __forceinline__ void ldsm_x4(uint32_t& r0, uint32_t& r1,
                                        uint32_t& r2, uint32_t& r3, uint32_t a) {
    asm volatile("ldmatrix.sync.aligned.m8n8.x4.shared.b16 {%0,%1,%2,%3}, [%4];\n"
                 : "=r"(r0), "=r"(r1), "=r"(r2), "=r"(r3) : "r"(a));
}
__device__ __forceinline__ void ldsm_x4_t(uint32_t& r0, uint32_t& r1,
                                          uint32_t& r2, uint32_t& r3, uint32_t a) {
    asm volatile("ldmatrix.sync.aligned.m8n8.x4.trans.shared.b16 {%0,%1,%2,%3}, [%4];\n"
                 : "=r"(r0), "=r"(r1), "=r"(r2), "=r"(r3) : "r"(a));
}
__device__ __forceinline__ void mma2(float c[4], const uint32_t a[4],
                                     uint32_t b0, uint32_t b1) {
    asm volatile(
        "mma.sync.aligned.m16n8k16.row.col.f32.f16.f16.f32 "
        "{%0,%1,%2,%3}, {%4,%5,%6,%7}, {%8,%9}, {%0,%1,%2,%3};\n"
        : "+f"(c[0]), "+f"(c[1]), "+f"(c[2]), "+f"(c[3])
        : "r"(a[0]), "r"(a[1]), "r"(a[2]), "r"(a[3]), "r"(b0), "r"(b1));
}
__device__ __forceinline__ uint32_t pkh2(__half a, __half b) {
    __half2 t = __halves2half2(a, b);
    return *reinterpret_cast<uint32_t*>(&t);
}
#define CP16(dst, src) \
    asm volatile("cp.async.cg.shared.global [%0], [%1], 16;\n" :: "r"(dst), "l"(src))
#define CPCOMMIT() asm volatile("cp.async.commit_group;\n")
#define CPWAIT0()  asm volatile("cp.async.wait_group 0;\n")
#define CPWAIT1()  asm volatile("cp.async.wait_group 1;\n")

// ---------------------------------------------------------------------------
// Merged fp32 -> fp16 conversion for x, w_qkv, w_out (one launch).
// ---------------------------------------------------------------------------
#define N4_X  (MROWS*DIMM/4)
#define N4_WQ (DIMM*COLS3/4)
#define N4_WO (DIMM*DIMM/4)
__global__ __launch_bounds__(256) void k_split_all(const float* __restrict__ x,
                                                   const float* __restrict__ wq,
                                                   const float* __restrict__ wo) {
    int i = blockIdx.x * blockDim.x + threadIdx.x;
    const float* s;
    __half* hi;
    int j;
    if (i < N4_X)                 { s = x;  hi = g_xh;  j = i; }
    else if (i < N4_X + N4_WQ)    { s = wq; hi = g_wqh; j = i - N4_X; }
    else if (i < N4_X + N4_WQ + N4_WO) { s = wo; hi = g_woh; j = i - N4_X - N4_WQ; }
    else return;
    float4 v = ((const float4*)s)[j];
    __half h[4] = {__float2half_rn(v.x), __float2half_rn(v.y),
                   __float2half_rn(v.z), __float2half_rn(v.w)};
    ((uint2*)hi)[j] = *(const uint2*)h;
}

// ---------------------------------------------------------------------------
// GEMM: pure fp16 operands, fp32 accum. 128x128 block, 8 warps (2x4),
// KC=64 (8 chunks), 3-stage cp.async ring, 2 CTAs/SM.
// ---------------------------------------------------------------------------
#define AST 72
#define BST 136
#define G_ASTAGE (128*AST)                   // 9216 halves
#define G_BSTAGE (64*BST)                    // 8704 halves
#define G_STAGE  (G_ASTAGE + G_BSTAGE)       // 17920 halves = 35840 B
#define GEMM_SMEM (3 * G_STAGE * 2)          // 107520 B

template<int NC, bool QKV>
__global__ __launch_bounds__(256, 2) void gemm_mma(float* __restrict__ Og) {
    constexpr int KD = 512;
    constexpr int NKC = KD / 64;             // 8 chunks
    extern __shared__ __half sg[];

    const int tid  = threadIdx.x;
    const int lane = tid & 31;
    const int wid  = tid >> 5;
    const int wm   = wid >> 2;
    const int wn   = wid & 3;
    const int row0 = blockIdx.y * 128;
    const int col0 = blockIdx.x * 128;
    const int lrow = lane & 15;
    const int lko  = (lane >> 4) * 8;

    float C[4][4][4];
#pragma unroll
    for (int i = 0; i < 4; i++)
#pragma unroll
        for (int j = 0; j < 4; j++)
#pragma unroll
            for (int e = 0; e < 4; e++) C[i][j][e] = 0.f;

    const __half* Ahg = QKV ? g_xh : g_aoh;
    const __half* Bhg = QKV ? g_wqh : g_woh;

    auto prefetch = [&](int sbase, int kk) {
#pragma unroll
        for (int i = 0; i < 4; i++) {          // A: 1024 chunks (128 r x 8 ch)
            int cid = tid + 256 * i;
            int row = cid >> 3, ch = cid & 7;
            CP16(smem_u32(&sg[sbase + row * AST + ch * 8]),
                 Ahg + (size_t)(row0 + row) * KD + kk + ch * 8);
        }
#pragma unroll
        for (int i = 0; i < 4; i++) {          // B: 1024 chunks (64 r x 16 ch)
            int cid = tid + 256 * i;
            int row = cid >> 4, ch = cid & 15;
            CP16(smem_u32(&sg[sbase + G_ASTAGE + row * BST + ch * 8]),
                 Bhg + (size_t)(kk + row) * NC + col0 + ch * 8);
        }
        CPCOMMIT();
    };

    prefetch(0, 0);
    prefetch(G_STAGE, 64);

    for (int kc = 0; kc < NKC; kc++) {
        CPWAIT1();
        __syncthreads();
        if (kc + 2 < NKC) prefetch(((kc + 2) % 3) * G_STAGE, (kc + 2) * 64);
        else CPCOMMIT();   // empty group keeps wait_group invariant

        const __half* Ahs = sg + (kc % 3) * G_STAGE;
        const __half* Bhs = Ahs + G_ASTAGE;

#pragma unroll
        for (int kq = 0; kq < 64; kq += 16) {
            uint32_t aH[4][4];
#pragma unroll
            for (int mt = 0; mt < 4; mt++) {
                int r = wm * 64 + mt * 16 + lrow;
                ldsm_x4(aH[mt][0], aH[mt][1], aH[mt][2], aH[mt][3],
                        smem_u32(&Ahs[r * AST + kq + lko]));
            }
            int rr = kq + lrow;
#pragma unroll
            for (int ng = 0; ng < 2; ng++) {
                uint32_t bH[4];
                int cb = wn * 32 + ng * 16 + lko;
                ldsm_x4_t(bH[0], bH[1], bH[2], bH[3], smem_u32(&Bhs[rr * BST + cb]));
#pragma unroll
                for (int mt = 0; mt < 4; mt++)
                    mma2(C[mt][ng*2],     aH[mt], bH[0], bH[1]);
#pragma unroll
                for (int mt = 0; mt < 4; mt++)
                    mma2(C[mt][ng*2 + 1], aH[mt], bH[2], bH[3]);
            }
        }
    }

    const int g  = lane >> 2;
    const int cc = (lane & 3) * 2;
    if (QKV) {
        const int sec     = col0 >> 9;
        const int rembase = (col0 & 511) + wn * 32;
        __half* dsth = (sec == 0) ? g_qh : (sec == 1 ? g_kh : g_vh);
        const float LOG2B = 13.287712379549449f;
#pragma unroll
        for (int nt = 0; nt < 4; nt++) {
            int rem   = rembase + nt * 8 + cc;
            int h     = rem >> 6;
            int dbase = rem & 63;
            float ifr = exp2f(-(float)dbase * (LOG2B / 64.f));
#pragma unroll
            for (int mt = 0; mt < 4; mt++) {
#pragma unroll
                for (int hf = 0; hf < 2; hf++) {
                    int R = row0 + wm * 64 + mt * 16 + g + hf * 8;
                    int b = R >> 10, n = R & 1023;
                    float v0 = C[mt][nt][hf*2 + 0];
                    float v1 = C[mt][nt][hf*2 + 1];
                    if (sec == 0) { v0 *= 0.125f; v1 *= 0.125f; }
                    if (sec < 2) {
                        float s, co;
                        sincosf((float)n * ifr, &s, &co);
                        float t0 = v0 * co - v1 * s;
                        float t1 = v1 * co + v0 * s;
                        v0 = t0; v1 = t1;
                    }
                    size_t idx = (((size_t)b * NH + h) * NSEQ + n) * HD + dbase;
                    *(__half2*)&dsth[idx] = __halves2half2(
                        __float2half_rn(v0), __float2half_rn(v1));
                }
            }
        }
    } else {
#pragma unroll
        for (int nt = 0; nt < 4; nt++) {
            int colg = col0 + wn * 32 + nt * 8 + cc;
#pragma unroll
            for (int mt = 0; mt < 4; mt++) {
#pragma unroll
                for (int hf = 0; hf < 2; hf++) {
                    int R = row0 + wm * 64 + mt * 16 + g + hf * 8;
                    *(float2*)&Og[(size_t)R * NC + colg] =
                        make_float2(C[mt][nt][hf*2], C[mt][nt][hf*2 + 1]);
                }
            }
        }
    }
}

// ---------------------------------------------------------------------------
// Flash attention: pure fp16, 2 CTAs/SM, 3-stage KV ring -> ONE sync per tile
// (stage jt+2 == stage jt-1, free after the top sync of tile jt).
// ---------------------------------------------------------------------------
#define QST 72
#define STAGE_H (2 * 64 * QST)           // Kh + Vh per stage = 9216 halves
#define ATTN_SMEM (3 * STAGE_H * 2)      // 55296 B

__global__ __launch_bounds__(256, 2) void k_attn_mma(const float* __restrict__ bias) {
    extern __shared__ __half sm[];

    const int b  = blockIdx.x;      // fastest: batches share bias slice in L2
    const int h  = blockIdx.y;
    const int i0 = blockIdx.z * 128;
    const int tid = threadIdx.x, lane = tid & 31, w = tid >> 5;
    const int lrow = lane & 15, lko = (lane >> 4) * 8;
    const int g = lane >> 2, c2 = (lane & 3) * 2;

    const size_t bh = (size_t)(b * NH + h) * NSEQ * HD;
    const __half* kv_src[2] = {g_kh + bh, g_vh + bh};
    const float* bg = bias + (size_t)h * NSEQ * NSEQ;

    // ---- stage Q-hi through stage0 (overwritten later), extract frags ----
    {
        const __half* qh = g_qh + bh;
#pragma unroll
        for (int i = 0; i < 4; i++) {
            int cid = tid + 256 * i;
            int row = cid >> 3, ch = cid & 7;
            CP16(smem_u32(&sm[row * QST + ch * 8]),
                 qh + (size_t)(i0 + row) * HD + ch * 8);
        }
        CPCOMMIT();
        CPWAIT0();
        __syncthreads();
    }
    uint32_t qH[4][4];
#pragma unroll
    for (int ks = 0; ks < 4; ks++)
        ldsm_x4(qH[ks][0], qH[ks][1], qH[ks][2], qH[ks][3],
                smem_u32(&sm[(w*16 + lrow)*QST + ks*16 + lko]));
    __syncthreads();

    auto kvload = [&](int sbase, int j0) {
#pragma unroll
        for (int i = 0; i < 4; i++) {
            int cid = tid + 256 * i;
            int arr = cid >> 9;
            int rem = cid & 511;
            int row = rem >> 3, ch = rem & 7;
            CP16(smem_u32(&sm[sbase + arr * 64 * QST + row * QST + ch * 8]),
                 kv_src[arr] + (size_t)(j0 + row) * HD + ch * 8);
        }
        CPCOMMIT();
    };

    kvload(0, 0);
    kvload(STAGE_H, 64);

    float Of[8][4];
#pragma unroll
    for (int nt = 0; nt < 8; nt++)
#pragma unroll
        for (int e = 0; e < 4; e++) Of[nt][e] = 0.f;
    float m0 = -INFINITY, m1 = -INFINITY, l0 = 0.f, l1 = 0.f;
    const int r0g = i0 + w * 16 + g;

    for (int jt = 0; jt < 16; jt++) {
        CPWAIT1();
        __syncthreads();
        // stage (jt+2)%3 == stage (jt-1)%3: all reads of it finished before
        // this tile's sync, so the prefetch is safe with a single sync/tile.
        if (jt + 2 < 16) kvload(((jt + 2) % 3) * STAGE_H, (jt + 2) * 64);
        else CPCOMMIT();   // keep wait_group invariant

        const __half* st = sm + (jt % 3) * STAGE_H;
        const int j0 = jt * 64;

        // bias prefetch (long-latency LDGs before the MMA burst)
        float2 bu[8], bw[8];
        {
            const float* bp0 = bg + (size_t)r0g * NSEQ + j0 + c2;
            const float* bp1 = bp0 + 8 * NSEQ;
#pragma unroll
            for (int nt = 0; nt < 8; nt++) {
                bu[nt] = *(const float2*)(bp0 + nt * 8);
                bw[nt] = *(const float2*)(bp1 + nt * 8);
            }
        }

        // ---- S = qH * kH ----
        float Sf[8][4];
#pragma unroll
        for (int nt = 0; nt < 8; nt++)
#pragma unroll
            for (int e = 0; e < 4; e++) Sf[nt][e] = 0.f;
#pragma unroll
        for (int ks = 0; ks < 4; ks++) {
#pragma unroll
            for (int ng = 0; ng < 4; ng++) {
                uint32_t kh_[4];
                ldsm_x4(kh_[0], kh_[1], kh_[2], kh_[3],
                        smem_u32(&st[(ng*16 + lrow)*QST + ks*16 + lko]));
                mma2(Sf[2*ng],   qH[ks], kh_[0], kh_[2]);
                mma2(Sf[2*ng+1], qH[ks], kh_[1], kh_[3]);
            }
        }
#pragma unroll
        for (int nt = 0; nt < 8; nt++) {
            Sf[nt][0] += bu[nt].x; Sf[nt][1] += bu[nt].y;
            Sf[nt][2] += bw[nt].x; Sf[nt][3] += bw[nt].y;
        }

        // ---- online softmax ----
        float mx0 = -INFINITY, mx1 = -INFINITY;
#pragma unroll
        for (int nt = 0; nt < 8; nt++) {
            mx0 = fmaxf(mx0, fmaxf(Sf[nt][0], Sf[nt][1]));
            mx1 = fmaxf(mx1, fmaxf(Sf[nt][2], Sf[nt][3]));
        }
        mx0 = fmaxf(mx0, __shfl_xor_sync(0xffffffffu, mx0, 1));
        mx0 = fmaxf(mx0, __shfl_xor_sync(0xffffffffu, mx0, 2));
        mx1 = fmaxf(mx1, __shfl_xor_sync(0xffffffffu, mx1, 1));
        mx1 = fmaxf(mx1, __shfl_xor_sync(0xffffffffu, mx1, 2));
        float mn0 = fmaxf(m0, mx0), mn1 = fmaxf(m1, mx1);
        float rs0 = __expf(m0 - mn0), rs1 = __expf(m1 - mn1);
        m0 = mn0; m1 = mn1;

        uint32_t pH0[8], pH1[8];
        float s0 = 0.f, s1 = 0.f;
#pragma unroll
        for (int nt = 0; nt < 8; nt++) {
            float p0 = __expf(Sf[nt][0] - mn0);
            float p1 = __expf(Sf[nt][1] - mn0);
            float p2 = __expf(Sf[nt][2] - mn1);
            float p3 = __expf(Sf[nt][3] - mn1);
            s0 += p0 + p1; s1 += p2 + p3;
            pH0[nt] = pkh2(__float2half_rn(p0), __float2half_rn(p1));
            pH1[nt] = pkh2(__float2half_rn(p2), __float2half_rn(p3));
        }
        s0 += __shfl_xor_sync(0xffffffffu, s0, 1);
        s0 += __shfl_xor_sync(0xffffffffu, s0, 2);
        s1 += __shfl_xor_sync(0xffffffffu, s1, 1);
        s1 += __shfl_xor_sync(0xffffffffu, s1, 2);
        l0 = l0 * rs0 + s0;
        l1 = l1 * rs1 + s1;
#pragma unroll
        for (int nt = 0; nt < 8; nt++) {
            Of[nt][0] *= rs0; Of[nt][1] *= rs0;
            Of[nt][2] *= rs1; Of[nt][3] *= rs1;
        }

        // ---- O += pH * vH ----
#pragma unroll
        for (int ks = 0; ks < 4; ks++) {
            uint32_t aH[4] = {pH0[2*ks], pH1[2*ks], pH0[2*ks+1], pH1[2*ks+1]};
#pragma unroll
            for (int dg = 0; dg < 4; dg++) {
                uint32_t vh_[4];
                ldsm_x4_t(vh_[0], vh_[1], vh_[2], vh_[3],
                          smem_u32(&st[64*QST + (ks*16 + lrow)*QST + dg*16 + lko]));
                mma2(Of[2*dg],   aH, vh_[0], vh_[1]);
                mma2(Of[2*dg+1], aH, vh_[2], vh_[3]);
            }
        }
    }

    // ---- normalize + store hi-only O to g_aoh [B,N,H*D] ----
    {
        float inv0 = 1.f / l0, inv1 = 1.f / l1;
        size_t base0 = ((size_t)b * NSEQ + r0g) * DIMM + h * HD + c2;
        size_t base1 = base0 + 8 * DIMM;
#pragma unroll
        for (int nt = 0; nt < 8; nt++) {
            *(__half2*)&g_aoh[base0 + nt*8] = __halves2half2(
                __float2half_rn(Of[nt][0] * inv0), __float2half_rn(Of[nt][1] * inv0));
            *(__half2*)&g_aoh[base1 + nt*8] = __halves2half2(
                __float2half_rn(Of[nt][2] * inv1), __float2half_rn(Of[nt][3] * inv1));
        }
    }
}

// ---------------------------------------------------------------------------
extern "C" void kernel_launch(void* const* d_in, const int* in_sizes, int n_in,
                              void* d_out, int out_size) {
    const float *x = nullptr, *pb = nullptr, *wq = nullptr, *wo = nullptr;
    for (int i = 0; i < n_in; i++) {
        switch (in_sizes[i]) {
            case 4194304: x  = (const float*)d_in[i]; break;  // x [8,1024,512]
            case 8388608: pb = (const float*)d_in[i]; break;  // pos_bias [8,1024,1024]
            case 786432:  wq = (const float*)d_in[i]; break;  // w_qkv [512,1536]
            case 262144:  wo = (const float*)d_in[i]; break;  // w_out [512,512]
        }
    }
    if (!x)  x  = (const float*)d_in[0];
    if (!pb) pb = (const float*)d_in[1];
    if (!wq) wq = (const float*)d_in[2];
    if (!wo) wo = (const float*)d_in[3];

    cudaFuncSetAttribute(k_attn_mma, cudaFuncAttributeMaxDynamicSharedMemorySize,
                         ATTN_SMEM);
    cudaFuncSetAttribute(gemm_mma<COLS3, true>,
                         cudaFuncAttributeMaxDynamicSharedMemorySize, GEMM_SMEM);
    cudaFuncSetAttribute(gemm_mma<DIMM, false>,
                         cudaFuncAttributeMaxDynamicSharedMemorySize, GEMM_SMEM);

    const int n4tot = N4_X + N4_WQ + N4_WO;
    k_split_all<<<(n4tot + 255) / 256, 256>>>(x, wq, wo);

    gemm_mma<COLS3, true><<<dim3(12, 64), 256, GEMM_SMEM>>>(nullptr);
    k_attn_mma<<<dim3(BSZ, NH, 8), 256, ATTN_SMEM>>>(pb);
    gemm_mma<DIMM, false><<<dim3(4, 64), 256, GEMM_SMEM>>>((float*)d_out);
}